// round 9
// baseline (speedup 1.0000x reference)
#include <cuda_runtime.h>
#include <cuda_bf16.h>
#include <math.h>
#include <stdint.h>

// Problem constants
#define DD    400
#define BB    64
#define NC_   10
#define NH_   50
#define NHEAD 20
#define DH    20
#define LL    640      // BB*NC_
#define MM    32000    // BB*NC_*NH_
#define BNH   3200     // BB*NH_

typedef __nv_bfloat16 bf16;

// ---------------- fp32 device scratch ----------------
__device__ float g_Hq3 [BNH * 1200];
__device__ float g_Cq3 [LL * 1200];
__device__ float g_T1  [BNH * 400];
__device__ float g_T2  [LL * 400];
__device__ float g_tc  [400];
__device__ float g_CA  [LL * 400];
__device__ float g_hall[MM * 400];
__device__ float g_a2  [MM * 200];
__device__ float g_s   [MM];

// ---------------- bf16 split scratch (hi/lo pairs) ----------------
__device__ __align__(16) bf16 g_bHcat_h[BNH * 1200], g_bHcat_l[BNH * 1200];
__device__ __align__(16) bf16 g_bh_h  [BNH * 400],  g_bh_l  [BNH * 400];
__device__ __align__(16) bf16 g_bHs_h [BNH * 400],  g_bHs_l [BNH * 400];
__device__ __align__(16) bf16 g_bHp1_h[BNH * 400],  g_bHp1_l[BNH * 400];
__device__ __align__(16) bf16 g_bc_h  [LL * 400],   g_bc_l  [LL * 400];
__device__ __align__(16) bf16 g_bCc_h [LL * 400],   g_bCc_l [LL * 400];
__device__ __align__(16) bf16 g_bCs_h [LL * 400],   g_bCs_l [LL * 400];
__device__ __align__(16) bf16 g_bXo_h [MM * 400],   g_bXo_l [MM * 400];
__device__ __align__(16) bf16 g_bhall_h[MM * 400],  g_bhall_l[MM * 400];
__device__ __align__(16) bf16 g_ba1_h [MM * 400],   g_ba1_l [MM * 400];
__device__ __align__(16) bf16 g_bW1_h [400 * 1600], g_bW1_l [400 * 1600];
__device__ __align__(16) bf16 g_bW2_h [400 * 800],  g_bW2_l [400 * 800];
__device__ __align__(16) bf16 g_bWqkv_h[1200 * 400],g_bWqkv_l[1200 * 400];
__device__ __align__(16) bf16 g_bW3_h [400 * 800],  g_bW3_l [400 * 800];
__device__ __align__(16) bf16 g_bWa1_h[400 * 800],  g_bWa1_l[400 * 800];
__device__ __align__(16) bf16 g_bWa2_h[200 * 400],  g_bWa2_l[200 * 400];
__device__ __align__(16) bf16 g_bWoT_h[400 * 400],  g_bWoT_l[400 * 400];
__device__ __align__(16) bf16 g_bWm_h [400 * 400],  g_bWm_l [400 * 400];

// attention pre-split K/V
// K: [n][h][m(640)][32 padded]   V: [n][h][d(20)][m(640)]
__device__ __align__(16) bf16 g_KHg[50 * 20 * 640 * 32], g_KLg[50 * 20 * 640 * 32];
__device__ __align__(16) bf16 g_VHg[50 * 20 * 20 * 640], g_VLg[50 * 20 * 20 * 640];

// ---------------- helpers ----------------
__device__ __forceinline__ uint32_t s2u(const void* p) {
    return (uint32_t)__cvta_generic_to_shared(p);
}
__device__ __forceinline__ void ldm4(uint32_t& r0, uint32_t& r1, uint32_t& r2, uint32_t& r3,
                                     uint32_t addr) {
    asm volatile("ldmatrix.sync.aligned.m8n8.x4.shared.b16 {%0,%1,%2,%3}, [%4];"
                 : "=r"(r0), "=r"(r1), "=r"(r2), "=r"(r3) : "r"(addr));
}
__device__ __forceinline__ void ldm2(uint32_t& r0, uint32_t& r1, uint32_t addr) {
    asm volatile("ldmatrix.sync.aligned.m8n8.x2.shared.b16 {%0,%1}, [%2];"
                 : "=r"(r0), "=r"(r1) : "r"(addr));
}
__device__ __forceinline__ void mma16816(float* d, const uint32_t* a, uint32_t b0, uint32_t b1) {
    asm volatile("mma.sync.aligned.m16n8k16.row.col.f32.bf16.bf16.f32 "
                 "{%0,%1,%2,%3}, {%4,%5,%6,%7}, {%8,%9}, {%0,%1,%2,%3};"
                 : "+f"(d[0]), "+f"(d[1]), "+f"(d[2]), "+f"(d[3])
                 : "r"(a[0]), "r"(a[1]), "r"(a[2]), "r"(a[3]), "r"(b0), "r"(b1));
}
__device__ __forceinline__ uint32_t pkbf(float a, float b) {
    __nv_bfloat162 t = __floats2bfloat162_rn(a, b);
    return *reinterpret_cast<uint32_t*>(&t);
}
__device__ __forceinline__ uint32_t pk2h(bf16 a, bf16 b) {
    __nv_bfloat162 t; t.x = a; t.y = b;
    return *reinterpret_cast<uint32_t*>(&t);
}
// cp.async 16B with src-size (0 => zero-fill)
__device__ __forceinline__ void cpa16(uint32_t saddr, const void* gptr, uint32_t bytes) {
    asm volatile("cp.async.cg.shared.global [%0], [%1], 16, %2;"
                 :: "r"(saddr), "l"(gptr), "r"(bytes));
}
#define CPA_COMMIT() asm volatile("cp.async.commit_group;" ::: "memory")
#define CPA_WAIT0()  asm volatile("cp.async.wait_group 0;" ::: "memory")

// ---------------- merged convert: 8 segments in one launch ----------------
struct ConvParams {
    const float* src[8];
    bf16* hi[8];
    bf16* lo[8];
    int cum[9];
};
__global__ void conv_all_kernel(ConvParams P) {
    int i = blockIdx.x * blockDim.x + threadIdx.x;
    if (i >= P.cum[8]) return;
    int g = 0;
    #pragma unroll
    for (int s = 1; s < 8; s++) if (i >= P.cum[s]) g = s;
    int local = i - P.cum[g];
    float v = P.src[g][local];
    bf16 hh = __float2bfloat16_rn(v);
    P.hi[g][local] = hh;
    P.lo[g][local] = __float2bfloat16_rn(v - __bfloat162float(hh));
}

// ---------------- prep2: Hcat gather (bf16 pairs) + Wo transpose-split, one launch ----------------
#define HC_PAIRS (BNH * 600)
#define HC_BLOCKS ((HC_PAIRS + 255) / 256)
#define TR_BLOCKS ((400 * 400 + 255) / 256)
__global__ void prep2_kernel(const bf16* __restrict__ hh, const bf16* __restrict__ hl,
                             bf16* __restrict__ oh, bf16* __restrict__ ol,
                             const float* __restrict__ Wo,
                             bf16* __restrict__ th, bf16* __restrict__ tl) {
    if ((int)blockIdx.x < HC_BLOCKS) {
        int idx = blockIdx.x * blockDim.x + threadIdx.x;   // pairs
        if (idx >= HC_PAIRS) return;
        int row = idx / 600, pr = idx % 600;
        int col = pr * 2;
        int b = row / NH_, j = row % NH_;
        int part = col / 400, d = col % 400;
        int jj = (part == 0) ? (j + NH_ - 1) % NH_ : ((part == 1) ? j : (j + 1) % NH_);
        int s = (b * NH_ + jj) * 400 + d;
        reinterpret_cast<uint32_t*>(oh)[idx] = *reinterpret_cast<const uint32_t*>(&hh[s]);
        reinterpret_cast<uint32_t*>(ol)[idx] = *reinterpret_cast<const uint32_t*>(&hl[s]);
    } else {
        int idx = (blockIdx.x - HC_BLOCKS) * blockDim.x + threadIdx.x;
        if (idx >= 400 * 400) return;
        int n = idx / 400, k = idx % 400;
        float v = Wo[k * 400 + n];
        bf16 hv = __float2bfloat16_rn(v);
        th[idx] = hv;
        tl[idx] = __float2bfloat16_rn(v - __bfloat162float(hv));
    }
}

// ---------------- tc: warp-per-row reduction ----------------
__global__ void tc_kernel(const float* __restrict__ b1, const float* __restrict__ bo,
                          const float* __restrict__ b3, const float* __restrict__ W3,
                          float* __restrict__ tc) {
    int w = threadIdx.x >> 5, lane = threadIdx.x & 31;
    int r = blockIdx.x * 8 + w;
    if (r >= 400) return;
    const float* row = W3 + (size_t)r * 800;
    float acc = 0.f;
    for (int d = lane; d < 400; d += 32)
        acc += b1[d] * row[d] + bo[d] * row[400 + d];
    #pragma unroll
    for (int o = 16; o > 0; o >>= 1) acc += __shfl_xor_sync(0xffffffffu, acc, o);
    if (lane == 0) tc[r] = acc + b3[r];
}

// ---------------- shared tensor-core GEMM core (bf16 2-way split, 3 MMAs, cp.async) ----------------
#define TBM 128
#define TBN 128
#define TBK 16
#define SSTR 24

__device__ __forceinline__ void gemm_core(
    const bf16* __restrict__ Ah, const bf16* __restrict__ Al, int lda,
    const bf16* __restrict__ Bh, const bf16* __restrict__ Bl, int ldb,
    float* __restrict__ C, bf16* __restrict__ Ch, bf16* __restrict__ Cl,
    int ldc, int M, int N, int K,
    const float* __restrict__ aux0, const float* __restrict__ aux1,
    const float* __restrict__ aux2,
    int row0, int col0, int mode, int out)
{
    __shared__ __align__(16) bf16 sAh[2][TBM * SSTR];
    __shared__ __align__(16) bf16 sAl[2][TBM * SSTR];
    __shared__ __align__(16) bf16 sBh[2][TBM * SSTR];
    __shared__ __align__(16) bf16 sBl[2][TBM * SSTR];

    const int tid = threadIdx.x;
    const int lrow = tid >> 1, lhalf = tid & 1;

    const bool aok = (row0 + lrow) < M;
    const bool bok = (col0 + lrow) < N;
    const uint32_t abytes = aok ? 16u : 0u;
    const uint32_t bbytes = bok ? 16u : 0u;
    const int arow = aok ? (row0 + lrow) : 0;
    const int brow = bok ? (col0 + lrow) : 0;
    const bf16* Aph = Ah + (size_t)arow * lda + lhalf * 8;
    const bf16* Apl = Al + (size_t)arow * lda + lhalf * 8;
    const bf16* Bph = Bh + (size_t)brow * ldb + lhalf * 8;
    const bf16* Bpl = Bl + (size_t)brow * ldb + lhalf * 8;
    const uint32_t sboff = (uint32_t)((lrow * SSTR + lhalf * 8) * 2);

    const int w = tid >> 5, lane = tid & 31;
    const int wm = w >> 2, wn = w & 3;
    const int mrow = ((lane >> 3) & 1) * 8 + (lane & 7);
    const int koff = (lane >> 4) * 8;

    uint32_t aoff[4], boff[2];
    #pragma unroll
    for (int fm = 0; fm < 4; fm++)
        aoff[fm] = (uint32_t)(((wm * 64 + fm * 16 + mrow) * SSTR + koff) * 2);
    #pragma unroll
    for (int f = 0; f < 2; f++)
        boff[f] = (uint32_t)(((wn * 32 + f * 16 + mrow) * SSTR + koff) * 2);

    const uint32_t bAh = s2u(sAh), bAl = s2u(sAl), bBh = s2u(sBh), bBl = s2u(sBl);
    const uint32_t STB = TBM * SSTR * 2;

    float acc[4][4][4];
    #pragma unroll
    for (int i = 0; i < 4; i++)
        #pragma unroll
        for (int j = 0; j < 4; j++)
            #pragma unroll
            for (int e = 0; e < 4; e++) acc[i][j][e] = 0.f;

    // stage-0 async copy
    {
        cpa16(bAh + sboff, Aph, abytes);
        cpa16(bAl + sboff, Apl, abytes);
        cpa16(bBh + sboff, Bph, bbytes);
        cpa16(bBl + sboff, Bpl, bbytes);
        CPA_COMMIT();
    }
    CPA_WAIT0();
    __syncthreads();

    const int nk = K / TBK;
    for (int t = 0; t < nk; t++) {
        const int st = t & 1;
        if (t + 1 < nk) {
            const int k = (t + 1) * TBK;
            const uint32_t nso = (uint32_t)(st ^ 1) * STB + sboff;
            cpa16(bAh + nso, Aph + k, abytes);
            cpa16(bAl + nso, Apl + k, abytes);
            cpa16(bBh + nso, Bph + k, bbytes);
            cpa16(bBl + nso, Bpl + k, bbytes);
            CPA_COMMIT();
        }

        uint32_t ah[4][4], al[4][4], bh[2][4], bl[2][4];
        #pragma unroll
        for (int fm = 0; fm < 4; fm++) {
            ldm4(ah[fm][0], ah[fm][1], ah[fm][2], ah[fm][3], bAh + st * STB + aoff[fm]);
            ldm4(al[fm][0], al[fm][1], al[fm][2], al[fm][3], bAl + st * STB + aoff[fm]);
        }
        #pragma unroll
        for (int f = 0; f < 2; f++) {
            ldm4(bh[f][0], bh[f][1], bh[f][2], bh[f][3], bBh + st * STB + boff[f]);
            ldm4(bl[f][0], bl[f][1], bl[f][2], bl[f][3], bBl + st * STB + boff[f]);
        }

        #pragma unroll
        for (int fm = 0; fm < 4; fm++) {
            #pragma unroll
            for (int f = 0; f < 2; f++) {
                mma16816(acc[fm][f * 2 + 0], ah[fm], bh[f][0], bh[f][2]);
                mma16816(acc[fm][f * 2 + 0], ah[fm], bl[f][0], bl[f][2]);
                mma16816(acc[fm][f * 2 + 0], al[fm], bh[f][0], bh[f][2]);
                mma16816(acc[fm][f * 2 + 1], ah[fm], bh[f][1], bh[f][3]);
                mma16816(acc[fm][f * 2 + 1], ah[fm], bl[f][1], bl[f][3]);
                mma16816(acc[fm][f * 2 + 1], al[fm], bh[f][1], bh[f][3]);
            }
        }

        if (t + 1 < nk) {
            CPA_WAIT0();
            __syncthreads();
        }
    }

    // epilogue (pairwise: cols cc, cc+1)
    #pragma unroll
    for (int fm = 0; fm < 4; fm++) {
        #pragma unroll
        for (int half = 0; half < 2; half++) {
            const int r = row0 + wm * 64 + fm * 16 + (lane >> 2) + half * 8;
            if (r >= M) continue;
            int bb = 0, ii = 0, jj = 0;
            if (mode == 3 || mode == 4) { bb = r / 500; ii = (r / 50) % 10; jj = r % 50; }
            #pragma unroll
            for (int fn = 0; fn < 4; fn++) {
                const int cc = col0 + wn * 32 + fn * 8 + (lane & 3) * 2;
                if (cc >= N) continue;
                float v0 = acc[fm][fn][half * 2], v1 = acc[fm][fn][half * 2 + 1];
                if (mode == 1) { v0 += aux0[cc]; v1 += aux0[cc + 1]; }
                if (mode == 2) { v0 = tanhf(v0 + aux0[cc]); v1 = tanhf(v1 + aux0[cc + 1]); }
                if (mode == 3) {
                    const float* p0 = aux0 + (size_t)(bb * 50 + jj) * N;
                    const float* p1 = aux1 + (size_t)(bb * 10 + ii) * N;
                    v0 += p0[cc] + p1[cc] + aux2[cc];
                    v1 += p0[cc + 1] + p1[cc + 1] + aux2[cc + 1];
                }
                if (mode == 4) {
                    const float* p0 = aux0 + (size_t)(bb * 10 + ii) * N;
                    v0 = tanhf(v0 + p0[cc]); v1 = tanhf(v1 + p0[cc + 1]);
                }
                if (out & 1)
                    *reinterpret_cast<float2*>(&C[(size_t)r * ldc + cc]) = make_float2(v0, v1);
                if (out & 2) {
                    bf16 h0 = __float2bfloat16_rn(v0), h1 = __float2bfloat16_rn(v1);
                    *reinterpret_cast<uint32_t*>(&Ch[(size_t)r * ldc + cc]) = pk2h(h0, h1);
                    *reinterpret_cast<uint32_t*>(&Cl[(size_t)r * ldc + cc]) =
                        pkbf(v0 - __bfloat162float(h0), v1 - __bfloat162float(h1));
                }
            }
        }
    }
}

// template wrapper (big GEMMs, modes 2/3/4)
template <int MODE, int OUT>
__global__ __launch_bounds__(256, 2) void gemm_mma(
    const bf16* __restrict__ Ah, const bf16* __restrict__ Al, int lda,
    const bf16* __restrict__ Bh, const bf16* __restrict__ Bl, int ldb,
    float* __restrict__ C, bf16* __restrict__ Ch, bf16* __restrict__ Cl,
    int ldc, int M, int N, int K,
    const float* __restrict__ aux0, const float* __restrict__ aux1,
    const float* __restrict__ aux2)
{
    gemm_core(Ah, Al, lda, Bh, Bl, ldb, C, Ch, Cl, ldc, M, N, K,
              aux0, aux1, aux2, blockIdx.y * TBM, blockIdx.x * TBN, MODE, OUT);
}

// grouped wrapper (small GEMMs, modes 0/1)
struct GDesc {
    const bf16 *Ah, *Al, *Bh, *Bl;
    float* C; bf16 *Ch; bf16 *Cl;
    const float* aux0;
    int lda, ldb, ldc, M, N, K, mode, out, bx;
};
struct GParams { GDesc d[6]; int cum[7]; int nd; };

__global__ __launch_bounds__(256, 2) void gemm_group(GParams P) {
    int g = 0;
    while (g + 1 < P.nd && (int)blockIdx.x >= P.cum[g + 1]) g++;
    const GDesc& D = P.d[g];
    int local = blockIdx.x - P.cum[g];
    int bxi = local % D.bx, byi = local / D.bx;
    gemm_core(D.Ah, D.Al, D.lda, D.Bh, D.Bl, D.ldb, D.C, D.Ch, D.Cl, D.ldc,
              D.M, D.N, D.K, D.aux0, nullptr, nullptr,
              byi * TBM, bxi * TBN, D.mode, D.out);
}

// ---------------- attention K/V pre-split ----------------
__global__ void attn_prep(const float* __restrict__ Cq3, const float* __restrict__ Hq3,
                          bf16* __restrict__ KHg, bf16* __restrict__ KLg,
                          bf16* __restrict__ VHg, bf16* __restrict__ VLg)
{
    const int n = blockIdx.x, b = blockIdx.y;
    const float* Hrow = Hq3 + (size_t)(b * NH_ + n) * 1200;
    const bf16 zb = __float2bfloat16_rn(0.f);

    for (int idx = threadIdx.x; idx < 4000; idx += 256) {
        int h = idx / 200, mm = (idx / 20) % 10, d = idx % 20;
        int m = b * 10 + mm;
        float kv = Cq3[m * 1200 + 400 + h * 20 + d] + Hrow[400 + h * 20 + d];
        bf16 hh = __float2bfloat16_rn(kv);
        size_t o = ((size_t)(n * 20 + h) * 640 + m) * 32 + d;
        KHg[o] = hh;
        KLg[o] = __float2bfloat16_rn(kv - __bfloat162float(hh));
    }
    for (int idx = threadIdx.x; idx < 2400; idx += 256) {
        int h = idx / 120, mm = (idx / 12) % 10, d = 20 + idx % 12;
        size_t o = ((size_t)(n * 20 + h) * 640 + b * 10 + mm) * 32 + d;
        KHg[o] = zb; KLg[o] = zb;
    }
    for (int idx = threadIdx.x; idx < 4000; idx += 256) {
        int h = idx / 200, d = (idx / 10) % 20, mm = idx % 10;
        int m = b * 10 + mm;
        float vv = Cq3[m * 1200 + 800 + h * 20 + d] + Hrow[800 + h * 20 + d];
        bf16 hh = __float2bfloat16_rn(vv);
        size_t o = ((size_t)(n * 20 + h) * 20 + d) * 640 + m;
        VHg[o] = hh;
        VLg[o] = __float2bfloat16_rn(vv - __bfloat162float(hh));
    }
}

// ---------------- tensor-core flash attention ----------------
__global__ __launch_bounds__(256) void attn_mma(
    const float* __restrict__ Cq3, const float* __restrict__ Hq3,
    const bf16* __restrict__ KHg, const bf16* __restrict__ KLg,
    const bf16* __restrict__ VHg, const bf16* __restrict__ VLg,
    bf16* __restrict__ Xoh, bf16* __restrict__ Xol)
{
    __shared__ __align__(16) bf16 sm[18944];
    bf16* QH = sm;               // [128][40]
    bf16* QL = sm + 5120;
    bf16* KH = sm;               // reuse after Q frags loaded
    bf16* KL = sm + 5120;
    bf16* VTH = sm + 10240;      // [32][136]
    bf16* VTL = sm + 14592;

    const int qt = blockIdx.x, n = blockIdx.y, h = blockIdx.z;
    const int tid = threadIdx.x, w = tid >> 5, lane = tid & 31;
    const float scale = 0.22360679774997896f;  // 1/sqrt(20)
    const bf16 zb = __float2bfloat16_rn(0.f);

    const bf16* Kbh = KHg + (size_t)(n * 20 + h) * 640 * 32;
    const bf16* Kbl = KLg + (size_t)(n * 20 + h) * 640 * 32;
    const bf16* Vbh = VHg + (size_t)(n * 20 + h) * 20 * 640;
    const bf16* Vbl = VLg + (size_t)(n * 20 + h) * 20 * 640;

    for (int idx = tid; idx < 128 * 32; idx += 256) {
        int r = idx >> 5, d = idx & 31;
        float v = 0.f;
        if (d < 20) {
            int l = qt * 128 + r;
            int qr = (l / NC_) * NH_ + n;
            v = (Cq3[l * 1200 + h * 20 + d] + Hq3[qr * 1200 + h * 20 + d]) * scale;
        }
        bf16 hh = __float2bfloat16_rn(v);
        QH[r * 40 + d] = hh;
        QL[r * 40 + d] = __float2bfloat16_rn(v - __bfloat162float(hh));
    }
    __syncthreads();

    const int mrow = ((lane >> 3) & 1) * 8 + (lane & 7);
    const int koff = (lane >> 4) * 8;

    uint32_t qh[2][4], ql[2][4];
    #pragma unroll
    for (int kc = 0; kc < 2; kc++) {
        uint32_t a = (uint32_t)(((w * 16 + mrow) * 40 + kc * 16 + koff) * 2);
        ldm4(qh[kc][0], qh[kc][1], qh[kc][2], qh[kc][3], s2u(QH) + a);
        ldm4(ql[kc][0], ql[kc][1], ql[kc][2], ql[kc][3], s2u(QL) + a);
    }
    __syncthreads();

    for (int idx = tid; idx < 12 * 136; idx += 256) {
        int d = 20 + idx / 136, k = idx % 136;
        VTH[d * 136 + k] = zb; VTL[d * 136 + k] = zb;
    }

    float O0[3][4];
    #pragma unroll
    for (int f = 0; f < 3; f++)
        #pragma unroll
        for (int e = 0; e < 4; e++) O0[f][e] = 0.f;
    float zl = 0.f, zh2 = 0.f;

    for (int kt = 0; kt < 5; kt++) {
        __syncthreads();
        for (int i = tid; i < 512; i += 256) {
            int kk = i >> 2, q = (i & 3) * 8;
            size_t src = (size_t)(kt * 128 + kk) * 32 + q;
            *reinterpret_cast<uint4*>(&KH[kk * 40 + q]) =
                *reinterpret_cast<const uint4*>(&Kbh[src]);
            *reinterpret_cast<uint4*>(&KL[kk * 40 + q]) =
                *reinterpret_cast<const uint4*>(&Kbl[src]);
        }
        for (int i = tid; i < 320; i += 256) {
            int d = i >> 4, cc = (i & 15) * 8;
            size_t src = (size_t)d * 640 + kt * 128 + cc;
            *reinterpret_cast<uint4*>(&VTH[d * 136 + cc]) =
                *reinterpret_cast<const uint4*>(&Vbh[src]);
            *reinterpret_cast<uint4*>(&VTL[d * 136 + cc]) =
                *reinterpret_cast<const uint4*>(&Vbl[src]);
        }
        __syncthreads();

        union { float f[16][4]; uint32_t u[16][4]; } SP;
        #pragma unroll
        for (int f = 0; f < 16; f++)
            #pragma unroll
            for (int e = 0; e < 4; e++) SP.f[f][e] = 0.f;

        #pragma unroll
        for (int g = 0; g < 8; g++) {
            uint32_t kh[2][4], kl[2][4];
            #pragma unroll
            for (int kc = 0; kc < 2; kc++) {
                uint32_t a = (uint32_t)(((g * 16 + mrow) * 40 + kc * 16 + koff) * 2);
                ldm4(kh[kc][0], kh[kc][1], kh[kc][2], kh[kc][3], s2u(KH) + a);
                ldm4(kl[kc][0], kl[kc][1], kl[kc][2], kl[kc][3], s2u(KL) + a);
            }
            #pragma unroll
            for (int kc = 0; kc < 2; kc++) {
                mma16816(SP.f[2 * g + 0], qh[kc], kh[kc][0], kh[kc][2]);
                mma16816(SP.f[2 * g + 0], qh[kc], kl[kc][0], kl[kc][2]);
                mma16816(SP.f[2 * g + 0], ql[kc], kh[kc][0], kh[kc][2]);
                mma16816(SP.f[2 * g + 1], qh[kc], kh[kc][1], kh[kc][3]);
                mma16816(SP.f[2 * g + 1], qh[kc], kl[kc][1], kl[kc][3]);
                mma16816(SP.f[2 * g + 1], ql[kc], kh[kc][1], kh[kc][3]);
            }
        }

        #pragma unroll
        for (int f = 0; f < 16; f++) {
            float e0 = __expf(SP.f[f][0]), e1 = __expf(SP.f[f][1]);
            float e2 = __expf(SP.f[f][2]), e3 = __expf(SP.f[f][3]);
            zl += e0 + e1; zh2 += e2 + e3;
            bf16 h0 = __float2bfloat16_rn(e0), h1 = __float2bfloat16_rn(e1);
            bf16 h2 = __float2bfloat16_rn(e2), h3 = __float2bfloat16_rn(e3);
            uint32_t ph01 = pk2h(h0, h1), ph23 = pk2h(h2, h3);
            uint32_t pl01 = pkbf(e0 - __bfloat162float(h0), e1 - __bfloat162float(h1));
            uint32_t pl23 = pkbf(e2 - __bfloat162float(h2), e3 - __bfloat162float(h3));
            SP.u[f][0] = ph01; SP.u[f][1] = ph23; SP.u[f][2] = pl01; SP.u[f][3] = pl23;
        }

        #pragma unroll
        for (int kc2 = 0; kc2 < 8; kc2++) {
            uint32_t ah[4] = { SP.u[2 * kc2][0], SP.u[2 * kc2][1],
                               SP.u[2 * kc2 + 1][0], SP.u[2 * kc2 + 1][1] };
            uint32_t al[4] = { SP.u[2 * kc2][2], SP.u[2 * kc2][3],
                               SP.u[2 * kc2 + 1][2], SP.u[2 * kc2 + 1][3] };
            uint32_t vh4[4], vl4[4], vh2[2], vl2[2];
            uint32_t a4 = (uint32_t)((mrow * 136 + kc2 * 16 + koff) * 2);
            uint32_t a2 = (uint32_t)(((16 + (lane & 7)) * 136 + kc2 * 16 + ((lane >> 3) & 1) * 8) * 2);
            ldm4(vh4[0], vh4[1], vh4[2], vh4[3], s2u(VTH) + a4);
            ldm4(vl4[0], vl4[1], vl4[2], vl4[3], s2u(VTL) + a4);
            ldm2(vh2[0], vh2[1], s2u(VTH) + a2);
            ldm2(vl2[0], vl2[1], s2u(VTL) + a2);
            mma16816(O0[0], ah, vh4[0], vh4[2]);
            mma16816(O0[0], ah, vl4[0], vl4[2]);
            mma16816(O0[0], al, vh4[0], vh4[2]);
            mma16816(O0[1], ah, vh4[1], vh4[3]);
            mma16816(O0[1], ah, vl4[1], vl4[3]);
            mma16816(O0[1], al, vh4[1], vh4[3]);
            mma16816(O0[2], ah, vh2[0], vh2[1]);
            mma16816(O0[2], ah, vl2[0], vl2[1]);
            mma16816(O0[2], al, vh2[0], vh2[1]);
        }
    }

    zl  += __shfl_xor_sync(0xffffffffu, zl, 1);
    zl  += __shfl_xor_sync(0xffffffffu, zl, 2);
    zh2 += __shfl_xor_sync(0xffffffffu, zh2, 1);
    zh2 += __shfl_xor_sync(0xffffffffu, zh2, 2);
    float izl = 1.f / zl, izh = 1.f / zh2;

    const int rowq = lane >> 2;
    #pragma unroll
    for (int f = 0; f < 3; f++) {
        int d0 = f * 8 + (lane & 3) * 2;
        if (d0 >= 20) continue;
        #pragma unroll
        for (int half = 0; half < 2; half++) {
            int lq = qt * 128 + w * 16 + rowq + half * 8;
            float v0 = O0[f][half * 2]     * (half ? izh : izl);
            float v1 = O0[f][half * 2 + 1] * (half ? izh : izl);
            size_t o = (size_t)(lq * NH_ + n) * 400 + h * 20 + d0;
            bf16 h0 = __float2bfloat16_rn(v0), h1 = __float2bfloat16_rn(v1);
            *reinterpret_cast<uint32_t*>(&Xoh[o]) = pk2h(h0, h1);
            *reinterpret_cast<uint32_t*>(&Xol[o]) =
                pkbf(v0 - __bfloat162float(h0), v1 - __bfloat162float(h1));
        }
    }
}

// ---------------- score + softmax ----------------
__global__ void score_kernel(const float* __restrict__ a2, const float* __restrict__ Wa3,
                             const float* __restrict__ ba3, float* __restrict__ s)
{
    int row = blockIdx.x * 8 + threadIdx.y;
    if (row >= MM) return;
    int lane = threadIdx.x;
    float acc = 0.f;
    for (int d = lane; d < 200; d += 32) acc += a2[(size_t)row * 200 + d] * Wa3[d];
    #pragma unroll
    for (int o = 16; o > 0; o >>= 1) acc += __shfl_xor_sync(0xffffffffu, acc, o);
    if (lane == 0) s[row] = acc + ba3[0];
}

__global__ void softmax_u_kernel(const float* __restrict__ s, const float* __restrict__ hall,
                                 float* __restrict__ u)
{
    __shared__ float a[NH_];
    int bi = blockIdx.x;
    if (threadIdx.x == 0) {
        float mx = -1e30f;
        for (int j = 0; j < NH_; j++) mx = fmaxf(mx, s[bi * NH_ + j]);
        float Z = 0.f;
        for (int j = 0; j < NH_; j++) { float e = __expf(s[bi * NH_ + j] - mx); a[j] = e; Z += e; }
        float iz = 1.f / Z;
        for (int j = 0; j < NH_; j++) a[j] *= iz;
    }
    __syncthreads();
    for (int d = threadIdx.x; d < 400; d += blockDim.x) {
        float acc = 0.f;
        for (int j = 0; j < NH_; j++)
            acc += a[j] * hall[((size_t)bi * NH_ + j) * 400 + d];
        u[(size_t)bi * 400 + d] = acc;
    }
}

// ---------------- launch ----------------
static inline dim3 mgrid(int M, int N) { return dim3((N + TBN - 1) / TBN, (M + TBM - 1) / TBM); }

extern "C" void kernel_launch(void* const* d_in, const int* in_sizes, int n_in,
                              void* d_out, int out_size)
{
    const float* h    = (const float*)d_in[0];
    const float* c    = (const float*)d_in[2];
    const float* W1   = (const float*)d_in[4];
    const float* b1   = (const float*)d_in[5];
    const float* W2   = (const float*)d_in[6];
    const float* b2   = (const float*)d_in[7];
    const float* W3   = (const float*)d_in[8];
    const float* b3   = (const float*)d_in[9];
    const float* Wa1  = (const float*)d_in[10];
    const float* ba1  = (const float*)d_in[11];
    const float* Wa2  = (const float*)d_in[12];
    const float* ba2  = (const float*)d_in[13];
    const float* Wa3  = (const float*)d_in[14];
    const float* ba3  = (const float*)d_in[15];
    const float* Wqkv = (const float*)d_in[16];
    const float* bqkv = (const float*)d_in[17];
    const float* Wo   = (const float*)d_in[18];
    const float* bo   = (const float*)d_in[19];
    float* u = (float*)d_out;

    float *Hq3, *Cq3, *T1, *T2, *tc, *CA, *hall, *a2, *sc;
    cudaGetSymbolAddress((void**)&Hq3,  g_Hq3);
    cudaGetSymbolAddress((void**)&Cq3,  g_Cq3);
    cudaGetSymbolAddress((void**)&T1,   g_T1);
    cudaGetSymbolAddress((void**)&T2,   g_T2);
    cudaGetSymbolAddress((void**)&tc,   g_tc);
    cudaGetSymbolAddress((void**)&CA,   g_CA);
    cudaGetSymbolAddress((void**)&hall, g_hall);
    cudaGetSymbolAddress((void**)&a2,   g_a2);
    cudaGetSymbolAddress((void**)&sc,   g_s);

    bf16 *bHcat_h, *bHcat_l, *bh_h, *bh_l, *bHs_h, *bHs_l, *bHp1_h, *bHp1_l;
    bf16 *bc_h, *bc_l, *bCc_h, *bCc_l, *bCs_h, *bCs_l;
    bf16 *bXo_h, *bXo_l, *bhall_h, *bhall_l, *ba1_h, *ba1_l;
    bf16 *bW1_h, *bW1_l, *bW2_h, *bW2_l, *bWqkv_h, *bWqkv_l, *bW3_h, *bW3_l;
    bf16 *bWa1_h, *bWa1_l, *bWa2_h, *bWa2_l, *bWoT_h, *bWoT_l, *bWm_h, *bWm_l;
    bf16 *KHg, *KLg, *VHg, *VLg;
    cudaGetSymbolAddress((void**)&bHcat_h, g_bHcat_h);  cudaGetSymbolAddress((void**)&bHcat_l, g_bHcat_l);
    cudaGetSymbolAddress((void**)&bh_h,    g_bh_h);     cudaGetSymbolAddress((void**)&bh_l,    g_bh_l);
    cudaGetSymbolAddress((void**)&bHs_h,   g_bHs_h);    cudaGetSymbolAddress((void**)&bHs_l,   g_bHs_l);
    cudaGetSymbolAddress((void**)&bHp1_h,  g_bHp1_h);   cudaGetSymbolAddress((void**)&bHp1_l,  g_bHp1_l);
    cudaGetSymbolAddress((void**)&bc_h,    g_bc_h);     cudaGetSymbolAddress((void**)&bc_l,    g_bc_l);
    cudaGetSymbolAddress((void**)&bCc_h,   g_bCc_h);    cudaGetSymbolAddress((void**)&bCc_l,   g_bCc_l);
    cudaGetSymbolAddress((void**)&bCs_h,   g_bCs_h);    cudaGetSymbolAddress((void**)&bCs_l,   g_bCs_l);
    cudaGetSymbolAddress((void**)&bXo_h,   g_bXo_h);    cudaGetSymbolAddress((void**)&bXo_l,   g_bXo_l);
    cudaGetSymbolAddress((void**)&bhall_h, g_bhall_h);  cudaGetSymbolAddress((void**)&bhall_l, g_bhall_l);
    cudaGetSymbolAddress((void**)&ba1_h,   g_ba1_h);    cudaGetSymbolAddress((void**)&ba1_l,   g_ba1_l);
    cudaGetSymbolAddress((void**)&bW1_h,   g_bW1_h);    cudaGetSymbolAddress((void**)&bW1_l,   g_bW1_l);
    cudaGetSymbolAddress((void**)&bW2_h,   g_bW2_h);    cudaGetSymbolAddress((void**)&bW2_l,   g_bW2_l);
    cudaGetSymbolAddress((void**)&bWqkv_h, g_bWqkv_h);  cudaGetSymbolAddress((void**)&bWqkv_l, g_bWqkv_l);
    cudaGetSymbolAddress((void**)&bW3_h,   g_bW3_h);    cudaGetSymbolAddress((void**)&bW3_l,   g_bW3_l);
    cudaGetSymbolAddress((void**)&bWa1_h,  g_bWa1_h);   cudaGetSymbolAddress((void**)&bWa1_l,  g_bWa1_l);
    cudaGetSymbolAddress((void**)&bWa2_h,  g_bWa2_h);   cudaGetSymbolAddress((void**)&bWa2_l,  g_bWa2_l);
    cudaGetSymbolAddress((void**)&bWoT_h,  g_bWoT_h);   cudaGetSymbolAddress((void**)&bWoT_l,  g_bWoT_l);
    cudaGetSymbolAddress((void**)&bWm_h,   g_bWm_h);    cudaGetSymbolAddress((void**)&bWm_l,   g_bWm_l);
    cudaGetSymbolAddress((void**)&KHg, g_KHg);  cudaGetSymbolAddress((void**)&KLg, g_KLg);
    cudaGetSymbolAddress((void**)&VHg, g_VHg);  cudaGetSymbolAddress((void**)&VLg, g_VLg);

    // (1) merged conversions
    ConvParams CP;
    const float* srcs[8] = { h, c, W1, W2, Wqkv, W3, Wa1, Wa2 };
    bf16* his[8] = { bh_h, bc_h, bW1_h, bW2_h, bWqkv_h, bW3_h, bWa1_h, bWa2_h };
    bf16* los[8] = { bh_l, bc_l, bW1_l, bW2_l, bWqkv_l, bW3_l, bWa1_l, bWa2_l };
    int ns[8] = { BNH * 400, LL * 400, 400 * 1600, 400 * 800, 1200 * 400,
                  400 * 800, 400 * 800, 200 * 400 };
    int cum = 0;
    for (int i = 0; i < 8; i++) { CP.src[i] = srcs[i]; CP.hi[i] = his[i]; CP.lo[i] = los[i];
                                  CP.cum[i] = cum; cum += ns[i]; }
    CP.cum[8] = cum;
    conv_all_kernel<<<(cum + 255) / 256, 256>>>(CP);

    // (2) Hcat gather + Wo transpose-split, one launch
    prep2_kernel<<<HC_BLOCKS + TR_BLOCKS, 256>>>(bh_h, bh_l, bHcat_h, bHcat_l,
                                                 Wo, bWoT_h, bWoT_l);

    // (3) grouped GEMM launch 1: independent small GEMMs
    {
        GParams G; int cumb = 0; int gi = 0;
        auto add = [&](const bf16* Ah, const bf16* Al, int lda,
                       const bf16* Bh, const bf16* Bl, int ldb,
                       float* C, bf16* Ch, bf16* Cl, int ldc,
                       int M, int N, int K, int mode, int out, const float* aux0) {
            GDesc& D = G.d[gi];
            D.Ah = Ah; D.Al = Al; D.Bh = Bh; D.Bl = Bl;
            D.C = C; D.Ch = Ch; D.Cl = Cl; D.aux0 = aux0;
            D.lda = lda; D.ldb = ldb; D.ldc = ldc; D.M = M; D.N = N; D.K = K;
            D.mode = mode; D.out = out;
            D.bx = (N + TBN - 1) / TBN;
            int by = (M + TBM - 1) / TBM;
            G.cum[gi] = cumb; cumb += D.bx * by; gi++;
        };
        add(bHcat_h, bHcat_l, 1200, bW1_h, bW1_l, 1600, nullptr, bHp1_h, bHp1_l, 400,
            BNH, 400, 1200, 0, 2, nullptr);                                   // Hp1
        add(bh_h, bh_l, 400, bW2_h + 400, bW2_l + 400, 800, nullptr, bHs_h, bHs_l, 400,
            BNH, 400, 400, 0, 2, nullptr);                                    // Hs
        add(bc_h, bc_l, 400, bW1_h + 1200, bW1_l + 1200, 1600, nullptr, bCc_h, bCc_l, 400,
            LL, 400, 400, 0, 2, nullptr);                                     // Cc
        add(bc_h, bc_l, 400, bW2_h, bW2_l, 800, nullptr, bCs_h, bCs_l, 400,
            LL, 400, 400, 1, 2, b2);                                          // Cs
        add(bc_h, bc_l, 400, bWa1_h + 400, bWa1_l + 400, 800, CA, nullptr, nullptr, 400,
            LL, 400, 400, 1, 1, ba1);                                         // CA
        add(bW3_h + 400, bW3_l + 400, 800, bWoT_h, bWoT_l, 400, nullptr, bWm_h, bWm_l, 400,
            400, 400, 400, 0, 2, nullptr);                                    // Wm
        G.cum[gi] = cumb; G.nd = gi;
        gemm_group<<<cumb, 256>>>(G);
    }

    // (4) grouped GEMM launch 2: dependent small GEMMs
    {
        GParams G; int cumb = 0; int gi = 0;
        auto add = [&](const bf16* Ah, const bf16* Al, int lda,
                       const bf16* Bh, const bf16* Bl, int ldb,
                       float* C, int ldc, int M, int N, int K, int mode, const float* aux0) {
            GDesc& D = G.d[gi];
            D.Ah = Ah; D.Al = Al; D.Bh = Bh; D.Bl = Bl;
            D.C = C; D.Ch = nullptr; D.Cl = nullptr; D.aux0 = aux0;
            D.lda = lda; D.ldb = ldb; D.ldc = ldc; D.M = M; D.N = N; D.K = K;
            D.mode = mode; D.out = 1;
            D.bx = (N + TBN - 1) / TBN;
            int by = (M + TBM - 1) / TBM;
            G.cum[gi] = cumb; cumb += D.bx * by; gi++;
        };
        add(bHp1_h, bHp1_l, 400, bW3_h, bW3_l, 800, T1, 400, BNH, 400, 400, 0, nullptr);      // T1
        add(bHs_h, bHs_l, 400, bWqkv_h, bWqkv_l, 400, Hq3, 1200, BNH, 1200, 400, 0, nullptr); // Hq3
        add(bCs_h, bCs_l, 400, bWqkv_h, bWqkv_l, 400, Cq3, 1200, LL, 1200, 400, 1, bqkv);     // Cq3
        add(bCc_h, bCc_l, 400, bW3_h, bW3_l, 800, T2, 400, LL, 400, 400, 0, nullptr);         // T2
        G.cum[gi] = cumb; G.nd = gi;
        gemm_group<<<cumb, 256>>>(G);
    }

    // (5) attention K/V pre-split
    attn_prep<<<dim3(NH_, BB), 256>>>(Cq3, Hq3, KHg, KLg, VHg, VLg);

    // (6) tensor-core flash attention
    attn_mma<<<dim3(5, NH_, NHEAD), 256>>>(Cq3, Hq3, KHg, KLg, VHg, VLg, bXo_h, bXo_l);

    // (7) tc
    tc_kernel<<<50, 256>>>(b1, bo, b3, W3, tc);

    // (8-10) big GEMMs
    gemm_mma<3, 3><<<mgrid(MM, 400), 256>>>(bXo_h, bXo_l, 400, bWm_h, bWm_l, 400,
        hall, bhall_h, bhall_l, 400, MM, 400, 400, T1, T2, tc);
    gemm_mma<4, 2><<<mgrid(MM, 400), 256>>>(bhall_h, bhall_l, 400, bWa1_h, bWa1_l, 800,
        nullptr, ba1_h, ba1_l, 400, MM, 400, 400, CA, nullptr, nullptr);
    gemm_mma<2, 1><<<mgrid(MM, 200), 256>>>(ba1_h, ba1_l, 400, bWa2_h, bWa2_l, 400,
        a2, nullptr, nullptr, 200, MM, 200, 400, ba2, nullptr, nullptr);

    // (11-12) scoring + softmax + weighted sum
    score_kernel<<<MM / 8, dim3(32, 8)>>>(a2, Wa3, ba3, sc);
    softmax_u_kernel<<<LL, 128>>>(sc, hall, u);
}

// round 10
// speedup vs baseline: 1.2554x; 1.2554x over previous
#include <cuda_runtime.h>
#include <cuda_bf16.h>
#include <math.h>
#include <stdint.h>

// Problem constants
#define DD    400
#define BB    64
#define NC_   10
#define NH_   50
#define NHEAD 20
#define DH    20
#define LL    640      // BB*NC_
#define MM    32000    // BB*NC_*NH_
#define BNH   3200     // BB*NH_

typedef __nv_bfloat16 bf16;

// ---------------- fp32 device scratch ----------------
__device__ float g_Hq3 [BNH * 1200];
__device__ float g_Cq3 [LL * 1200];
__device__ float g_T1  [BNH * 400];
__device__ float g_T2  [LL * 400];
__device__ float g_tc  [400];
__device__ float g_CA  [LL * 400];
__device__ float g_hall[MM * 400];
__device__ float g_a2  [MM * 200];
__device__ float g_s   [MM];

// ---------------- bf16 split scratch (hi/lo pairs) ----------------
__device__ __align__(16) bf16 g_bHcat_h[BNH * 1200], g_bHcat_l[BNH * 1200];
__device__ __align__(16) bf16 g_bh_h  [BNH * 400],  g_bh_l  [BNH * 400];
__device__ __align__(16) bf16 g_bHs_h [BNH * 400],  g_bHs_l [BNH * 400];
__device__ __align__(16) bf16 g_bHp1_h[BNH * 400],  g_bHp1_l[BNH * 400];
__device__ __align__(16) bf16 g_bc_h  [LL * 400],   g_bc_l  [LL * 400];
__device__ __align__(16) bf16 g_bCc_h [LL * 400],   g_bCc_l [LL * 400];
__device__ __align__(16) bf16 g_bCs_h [LL * 400],   g_bCs_l [LL * 400];
__device__ __align__(16) bf16 g_bXo_h [MM * 400],   g_bXo_l [MM * 400];
__device__ __align__(16) bf16 g_bhall_h[MM * 400],  g_bhall_l[MM * 400];
__device__ __align__(16) bf16 g_ba1_h [MM * 400],   g_ba1_l [MM * 400];
__device__ __align__(16) bf16 g_bW1_h [400 * 1600], g_bW1_l [400 * 1600];
__device__ __align__(16) bf16 g_bW2_h [400 * 800],  g_bW2_l [400 * 800];
__device__ __align__(16) bf16 g_bWqkv_h[1200 * 400],g_bWqkv_l[1200 * 400];
__device__ __align__(16) bf16 g_bW3_h [400 * 800],  g_bW3_l [400 * 800];
__device__ __align__(16) bf16 g_bWa1_h[400 * 800],  g_bWa1_l[400 * 800];
__device__ __align__(16) bf16 g_bWa2_h[200 * 400],  g_bWa2_l[200 * 400];
__device__ __align__(16) bf16 g_bWoT_h[400 * 400],  g_bWoT_l[400 * 400];
__device__ __align__(16) bf16 g_bWm_h [400 * 400],  g_bWm_l [400 * 400];

// attention pre-split K/V
// K concat-split: [n][h][m(640)][64] = [Kh(20) | Kl(20) | Kh(20) | 0(4)]
// V: [n][h][d(20)][m(640)] hi/lo
__device__ __align__(16) bf16 g_Kg [50 * 20 * 640 * 64];
__device__ __align__(16) bf16 g_VHg[50 * 20 * 20 * 640], g_VLg[50 * 20 * 20 * 640];

// ---------------- helpers ----------------
__device__ __forceinline__ uint32_t s2u(const void* p) {
    return (uint32_t)__cvta_generic_to_shared(p);
}
__device__ __forceinline__ void ldm4(uint32_t& r0, uint32_t& r1, uint32_t& r2, uint32_t& r3,
                                     uint32_t addr) {
    asm volatile("ldmatrix.sync.aligned.m8n8.x4.shared.b16 {%0,%1,%2,%3}, [%4];"
                 : "=r"(r0), "=r"(r1), "=r"(r2), "=r"(r3) : "r"(addr));
}
__device__ __forceinline__ void ldm2(uint32_t& r0, uint32_t& r1, uint32_t addr) {
    asm volatile("ldmatrix.sync.aligned.m8n8.x2.shared.b16 {%0,%1}, [%2];"
                 : "=r"(r0), "=r"(r1) : "r"(addr));
}
__device__ __forceinline__ void mma16816(float* d, const uint32_t* a, uint32_t b0, uint32_t b1) {
    asm volatile("mma.sync.aligned.m16n8k16.row.col.f32.bf16.bf16.f32 "
                 "{%0,%1,%2,%3}, {%4,%5,%6,%7}, {%8,%9}, {%0,%1,%2,%3};"
                 : "+f"(d[0]), "+f"(d[1]), "+f"(d[2]), "+f"(d[3])
                 : "r"(a[0]), "r"(a[1]), "r"(a[2]), "r"(a[3]), "r"(b0), "r"(b1));
}
__device__ __forceinline__ uint32_t pkbf(float a, float b) {
    __nv_bfloat162 t = __floats2bfloat162_rn(a, b);
    return *reinterpret_cast<uint32_t*>(&t);
}
__device__ __forceinline__ uint32_t pk2h(bf16 a, bf16 b) {
    __nv_bfloat162 t; t.x = a; t.y = b;
    return *reinterpret_cast<uint32_t*>(&t);
}
// cp.async 16B with src-size (0 => zero-fill)
__device__ __forceinline__ void cpa16(uint32_t saddr, const void* gptr, uint32_t bytes) {
    asm volatile("cp.async.cg.shared.global [%0], [%1], 16, %2;"
                 :: "r"(saddr), "l"(gptr), "r"(bytes));
}
#define CPA_COMMIT() asm volatile("cp.async.commit_group;" ::: "memory")
#define CPA_WAIT0()  asm volatile("cp.async.wait_group 0;" ::: "memory")

// ---------------- merged convert: 8 segments in one launch ----------------
struct ConvParams {
    const float* src[8];
    bf16* hi[8];
    bf16* lo[8];
    int cum[9];
};
__global__ void conv_all_kernel(ConvParams P) {
    int i = blockIdx.x * blockDim.x + threadIdx.x;
    if (i >= P.cum[8]) return;
    int g = 0;
    #pragma unroll
    for (int s = 1; s < 8; s++) if (i >= P.cum[s]) g = s;
    int local = i - P.cum[g];
    float v = P.src[g][local];
    bf16 hh = __float2bfloat16_rn(v);
    P.hi[g][local] = hh;
    P.lo[g][local] = __float2bfloat16_rn(v - __bfloat162float(hh));
}

// ---------------- prep2: Hcat gather (bf16 pairs) + Wo transpose-split, one launch ----------------
#define HC_PAIRS (BNH * 600)
#define HC_BLOCKS ((HC_PAIRS + 255) / 256)
#define TR_BLOCKS ((400 * 400 + 255) / 256)
__global__ void prep2_kernel(const bf16* __restrict__ hh, const bf16* __restrict__ hl,
                             bf16* __restrict__ oh, bf16* __restrict__ ol,
                             const float* __restrict__ Wo,
                             bf16* __restrict__ th, bf16* __restrict__ tl) {
    if ((int)blockIdx.x < HC_BLOCKS) {
        int idx = blockIdx.x * blockDim.x + threadIdx.x;   // pairs
        if (idx >= HC_PAIRS) return;
        int row = idx / 600, pr = idx % 600;
        int col = pr * 2;
        int b = row / NH_, j = row % NH_;
        int part = col / 400, d = col % 400;
        int jj = (part == 0) ? (j + NH_ - 1) % NH_ : ((part == 1) ? j : (j + 1) % NH_);
        int s = (b * NH_ + jj) * 400 + d;
        reinterpret_cast<uint32_t*>(oh)[idx] = *reinterpret_cast<const uint32_t*>(&hh[s]);
        reinterpret_cast<uint32_t*>(ol)[idx] = *reinterpret_cast<const uint32_t*>(&hl[s]);
    } else {
        int idx = (blockIdx.x - HC_BLOCKS) * blockDim.x + threadIdx.x;
        if (idx >= 400 * 400) return;
        int n = idx / 400, k = idx % 400;
        float v = Wo[k * 400 + n];
        bf16 hv = __float2bfloat16_rn(v);
        th[idx] = hv;
        tl[idx] = __float2bfloat16_rn(v - __bfloat162float(hv));
    }
}

// ---------------- tc: warp-per-row reduction ----------------
__global__ void tc_kernel(const float* __restrict__ b1, const float* __restrict__ bo,
                          const float* __restrict__ b3, const float* __restrict__ W3,
                          float* __restrict__ tc) {
    int w = threadIdx.x >> 5, lane = threadIdx.x & 31;
    int r = blockIdx.x * 8 + w;
    if (r >= 400) return;
    const float* row = W3 + (size_t)r * 800;
    float acc = 0.f;
    for (int d = lane; d < 400; d += 32)
        acc += b1[d] * row[d] + bo[d] * row[400 + d];
    #pragma unroll
    for (int o = 16; o > 0; o >>= 1) acc += __shfl_xor_sync(0xffffffffu, acc, o);
    if (lane == 0) tc[r] = acc + b3[r];
}

// ---------------- shared tensor-core GEMM core (bf16 2-way split, 3 MMAs, cp.async) ----------------
#define TBM 128
#define TBN 128
#define TBK 16
#define SSTR 24

__device__ __forceinline__ void gemm_core(
    const bf16* __restrict__ Ah, const bf16* __restrict__ Al, int lda,
    const bf16* __restrict__ Bh, const bf16* __restrict__ Bl, int ldb,
    float* __restrict__ C, bf16* __restrict__ Ch, bf16* __restrict__ Cl,
    int ldc, int M, int N, int K,
    const float* __restrict__ aux0, const float* __restrict__ aux1,
    const float* __restrict__ aux2,
    int row0, int col0, int mode, int out)
{
    __shared__ __align__(16) bf16 sAh[2][TBM * SSTR];
    __shared__ __align__(16) bf16 sAl[2][TBM * SSTR];
    __shared__ __align__(16) bf16 sBh[2][TBM * SSTR];
    __shared__ __align__(16) bf16 sBl[2][TBM * SSTR];

    const int tid = threadIdx.x;
    const int lrow = tid >> 1, lhalf = tid & 1;

    const bool aok = (row0 + lrow) < M;
    const bool bok = (col0 + lrow) < N;
    const uint32_t abytes = aok ? 16u : 0u;
    const uint32_t bbytes = bok ? 16u : 0u;
    const int arow = aok ? (row0 + lrow) : 0;
    const int brow = bok ? (col0 + lrow) : 0;
    const bf16* Aph = Ah + (size_t)arow * lda + lhalf * 8;
    const bf16* Apl = Al + (size_t)arow * lda + lhalf * 8;
    const bf16* Bph = Bh + (size_t)brow * ldb + lhalf * 8;
    const bf16* Bpl = Bl + (size_t)brow * ldb + lhalf * 8;
    const uint32_t sboff = (uint32_t)((lrow * SSTR + lhalf * 8) * 2);

    const int w = tid >> 5, lane = tid & 31;
    const int wm = w >> 2, wn = w & 3;
    const int mrow = ((lane >> 3) & 1) * 8 + (lane & 7);
    const int koff = (lane >> 4) * 8;

    uint32_t aoff[4], boff[2];
    #pragma unroll
    for (int fm = 0; fm < 4; fm++)
        aoff[fm] = (uint32_t)(((wm * 64 + fm * 16 + mrow) * SSTR + koff) * 2);
    #pragma unroll
    for (int f = 0; f < 2; f++)
        boff[f] = (uint32_t)(((wn * 32 + f * 16 + mrow) * SSTR + koff) * 2);

    const uint32_t bAh = s2u(sAh), bAl = s2u(sAl), bBh = s2u(sBh), bBl = s2u(sBl);
    const uint32_t STB = TBM * SSTR * 2;

    float acc[4][4][4];
    #pragma unroll
    for (int i = 0; i < 4; i++)
        #pragma unroll
        for (int j = 0; j < 4; j++)
            #pragma unroll
            for (int e = 0; e < 4; e++) acc[i][j][e] = 0.f;

    // stage-0 async copy
    {
        cpa16(bAh + sboff, Aph, abytes);
        cpa16(bAl + sboff, Apl, abytes);
        cpa16(bBh + sboff, Bph, bbytes);
        cpa16(bBl + sboff, Bpl, bbytes);
        CPA_COMMIT();
    }
    CPA_WAIT0();
    __syncthreads();

    const int nk = K / TBK;
    for (int t = 0; t < nk; t++) {
        const int st = t & 1;
        if (t + 1 < nk) {
            const int k = (t + 1) * TBK;
            const uint32_t nso = (uint32_t)(st ^ 1) * STB + sboff;
            cpa16(bAh + nso, Aph + k, abytes);
            cpa16(bAl + nso, Apl + k, abytes);
            cpa16(bBh + nso, Bph + k, bbytes);
            cpa16(bBl + nso, Bpl + k, bbytes);
            CPA_COMMIT();
        }

        uint32_t ah[4][4], al[4][4], bh[2][4], bl[2][4];
        #pragma unroll
        for (int fm = 0; fm < 4; fm++) {
            ldm4(ah[fm][0], ah[fm][1], ah[fm][2], ah[fm][3], bAh + st * STB + aoff[fm]);
            ldm4(al[fm][0], al[fm][1], al[fm][2], al[fm][3], bAl + st * STB + aoff[fm]);
        }
        #pragma unroll
        for (int f = 0; f < 2; f++) {
            ldm4(bh[f][0], bh[f][1], bh[f][2], bh[f][3], bBh + st * STB + boff[f]);
            ldm4(bl[f][0], bl[f][1], bl[f][2], bl[f][3], bBl + st * STB + boff[f]);
        }

        #pragma unroll
        for (int fm = 0; fm < 4; fm++) {
            #pragma unroll
            for (int f = 0; f < 2; f++) {
                mma16816(acc[fm][f * 2 + 0], ah[fm], bh[f][0], bh[f][2]);
                mma16816(acc[fm][f * 2 + 0], ah[fm], bl[f][0], bl[f][2]);
                mma16816(acc[fm][f * 2 + 0], al[fm], bh[f][0], bh[f][2]);
                mma16816(acc[fm][f * 2 + 1], ah[fm], bh[f][1], bh[f][3]);
                mma16816(acc[fm][f * 2 + 1], ah[fm], bl[f][1], bl[f][3]);
                mma16816(acc[fm][f * 2 + 1], al[fm], bh[f][1], bh[f][3]);
            }
        }

        if (t + 1 < nk) {
            CPA_WAIT0();
            __syncthreads();
        }
    }

    // epilogue (pairwise: cols cc, cc+1)
    #pragma unroll
    for (int fm = 0; fm < 4; fm++) {
        #pragma unroll
        for (int half = 0; half < 2; half++) {
            const int r = row0 + wm * 64 + fm * 16 + (lane >> 2) + half * 8;
            if (r >= M) continue;
            int bb = 0, ii = 0, jj = 0;
            if (mode == 3 || mode == 4) { bb = r / 500; ii = (r / 50) % 10; jj = r % 50; }
            #pragma unroll
            for (int fn = 0; fn < 4; fn++) {
                const int cc = col0 + wn * 32 + fn * 8 + (lane & 3) * 2;
                if (cc >= N) continue;
                float v0 = acc[fm][fn][half * 2], v1 = acc[fm][fn][half * 2 + 1];
                if (mode == 1) { v0 += aux0[cc]; v1 += aux0[cc + 1]; }
                if (mode == 2) { v0 = tanhf(v0 + aux0[cc]); v1 = tanhf(v1 + aux0[cc + 1]); }
                if (mode == 3) {
                    const float* p0 = aux0 + (size_t)(bb * 50 + jj) * N;
                    const float* p1 = aux1 + (size_t)(bb * 10 + ii) * N;
                    v0 += p0[cc] + p1[cc] + aux2[cc];
                    v1 += p0[cc + 1] + p1[cc + 1] + aux2[cc + 1];
                }
                if (mode == 4) {
                    const float* p0 = aux0 + (size_t)(bb * 10 + ii) * N;
                    v0 = tanhf(v0 + p0[cc]); v1 = tanhf(v1 + p0[cc + 1]);
                }
                if (out & 1)
                    *reinterpret_cast<float2*>(&C[(size_t)r * ldc + cc]) = make_float2(v0, v1);
                if (out & 2) {
                    bf16 h0 = __float2bfloat16_rn(v0), h1 = __float2bfloat16_rn(v1);
                    *reinterpret_cast<uint32_t*>(&Ch[(size_t)r * ldc + cc]) = pk2h(h0, h1);
                    *reinterpret_cast<uint32_t*>(&Cl[(size_t)r * ldc + cc]) =
                        pkbf(v0 - __bfloat162float(h0), v1 - __bfloat162float(h1));
                }
            }
        }
    }
}

// template wrapper (big GEMMs, modes 2/3/4)
template <int MODE, int OUT>
__global__ __launch_bounds__(256, 2) void gemm_mma(
    const bf16* __restrict__ Ah, const bf16* __restrict__ Al, int lda,
    const bf16* __restrict__ Bh, const bf16* __restrict__ Bl, int ldb,
    float* __restrict__ C, bf16* __restrict__ Ch, bf16* __restrict__ Cl,
    int ldc, int M, int N, int K,
    const float* __restrict__ aux0, const float* __restrict__ aux1,
    const float* __restrict__ aux2)
{
    gemm_core(Ah, Al, lda, Bh, Bl, ldb, C, Ch, Cl, ldc, M, N, K,
              aux0, aux1, aux2, blockIdx.y * TBM, blockIdx.x * TBN, MODE, OUT);
}

// grouped wrapper (small GEMMs, modes 0/1)
struct GDesc {
    const bf16 *Ah, *Al, *Bh, *Bl;
    float* C; bf16 *Ch; bf16 *Cl;
    const float* aux0;
    int lda, ldb, ldc, M, N, K, mode, out, bx;
};
struct GParams { GDesc d[6]; int cum[7]; int nd; };

__global__ __launch_bounds__(256, 2) void gemm_group(GParams P) {
    int g = 0;
    while (g + 1 < P.nd && (int)blockIdx.x >= P.cum[g + 1]) g++;
    const GDesc& D = P.d[g];
    int local = blockIdx.x - P.cum[g];
    int bxi = local % D.bx, byi = local / D.bx;
    gemm_core(D.Ah, D.Al, D.lda, D.Bh, D.Bl, D.ldb, D.C, D.Ch, D.Cl, D.ldc,
              D.M, D.N, D.K, D.aux0, nullptr, nullptr,
              byi * TBM, bxi * TBN, D.mode, D.out);
}

// ---------------- attention K/V prep ----------------
// K concat layout per row (64): [Kh(0:20) | Kl(20:40) | Kh(40:60) | 0]
__global__ void attn_prep(const float* __restrict__ Cq3, const float* __restrict__ Hq3,
                          bf16* __restrict__ Kg,
                          bf16* __restrict__ VHg, bf16* __restrict__ VLg)
{
    const int n = blockIdx.x, b = blockIdx.y;
    const float* Hrow = Hq3 + (size_t)(b * NH_ + n) * 1200;
    const bf16 zb = __float2bfloat16_rn(0.f);

    // K: 20 heads x 10 rows x 64 dims
    for (int idx = threadIdx.x; idx < 20 * 10 * 64; idx += 256) {
        int h = idx / 640, rem = idx % 640, mm = rem >> 6, d = rem & 63;
        int m = b * 10 + mm;
        bf16 outv = zb;
        if (d < 60) {
            int dd = (d < 20) ? d : ((d < 40) ? d - 20 : d - 40);
            float kv = Cq3[m * 1200 + 400 + h * 20 + dd] + Hrow[400 + h * 20 + dd];
            bf16 hh = __float2bfloat16_rn(kv);
            outv = (d >= 20 && d < 40)
                 ? __float2bfloat16_rn(kv - __bfloat162float(hh)) : hh;
        }
        Kg[((size_t)(n * 20 + h) * 640 + m) * 64 + d] = outv;
    }
    // V: split hi/lo, [n][h][d][m]
    for (int idx = threadIdx.x; idx < 4000; idx += 256) {
        int h = idx / 200, d = (idx / 10) % 20, mm = idx % 10;
        int m = b * 10 + mm;
        float vv = Cq3[m * 1200 + 800 + h * 20 + d] + Hrow[800 + h * 20 + d];
        bf16 hh = __float2bfloat16_rn(vv);
        size_t o = ((size_t)(n * 20 + h) * 20 + d) * 640 + m;
        VHg[o] = hh;
        VLg[o] = __float2bfloat16_rn(vv - __bfloat162float(hh));
    }
}

// ---------------- tensor-core flash attention (concat-split S) ----------------
__global__ __launch_bounds__(256, 2) void attn_mma(
    const float* __restrict__ Cq3, const float* __restrict__ Hq3,
    const bf16* __restrict__ Kg,
    const bf16* __restrict__ VHg, const bf16* __restrict__ VLg,
    bf16* __restrict__ Xoh, bf16* __restrict__ Xol)
{
    __shared__ __align__(16) bf16 sm[15744];
    bf16* QK  = sm;              // [128][72]: Q concat first, K tiles after frags loaded
    bf16* VTH = sm + 9216;       // [24][136]
    bf16* VTL = sm + 12480;

    const int qt = blockIdx.x, n = blockIdx.y, h = blockIdx.z;
    const int tid = threadIdx.x, w = tid >> 5, lane = tid & 31;
    const float scale = 0.22360679774997896f;  // 1/sqrt(20)
    const bf16 zb = __float2bfloat16_rn(0.f);

    const bf16* Kb  = Kg  + (size_t)(n * 20 + h) * 640 * 64;
    const bf16* Vbh = VHg + (size_t)(n * 20 + h) * 20 * 640;
    const bf16* Vbl = VLg + (size_t)(n * 20 + h) * 20 * 640;

    // build Q concat [128][64]: [Qh | Qh | Ql | 0]
    for (int idx = tid; idx < 128 * 64; idx += 256) {
        int r = idx >> 6, d = idx & 63;
        bf16 outv = zb;
        if (d < 60) {
            int dd = (d < 20) ? d : ((d < 40) ? d - 20 : d - 40);
            int l = qt * 128 + r;
            int qr = (l / NC_) * NH_ + n;
            float qv = (Cq3[l * 1200 + h * 20 + dd] + Hq3[qr * 1200 + h * 20 + dd]) * scale;
            bf16 hh = __float2bfloat16_rn(qv);
            outv = (d < 40) ? hh : __float2bfloat16_rn(qv - __bfloat162float(hh));
        }
        QK[r * 72 + d] = outv;
    }
    __syncthreads();

    const int mrow = ((lane >> 3) & 1) * 8 + (lane & 7);
    const int koff = (lane >> 4) * 8;

    uint32_t qf[4][4];
    #pragma unroll
    for (int kc = 0; kc < 4; kc++) {
        uint32_t a = (uint32_t)(((w * 16 + mrow) * 72 + kc * 16 + koff) * 2);
        ldm4(qf[kc][0], qf[kc][1], qf[kc][2], qf[kc][3], s2u(QK) + a);
    }
    __syncthreads();

    // zero VT pad rows 20-23
    for (int idx = tid; idx < 4 * 136; idx += 256) {
        int d = 20 + idx / 136, k = idx % 136;
        VTH[d * 136 + k] = zb; VTL[d * 136 + k] = zb;
    }

    float O0[3][4];
    #pragma unroll
    for (int f = 0; f < 3; f++)
        #pragma unroll
        for (int e = 0; e < 4; e++) O0[f][e] = 0.f;
    float zl = 0.f, zh2 = 0.f;

    for (int kt = 0; kt < 5; kt++) {
        __syncthreads();
        // copy K tile: 128 rows x 64 = 1024 uint4
        for (int i = tid; i < 1024; i += 256) {
            int kk = i >> 3, q8 = (i & 7) * 8;
            *reinterpret_cast<uint4*>(&QK[kk * 72 + q8]) =
                *reinterpret_cast<const uint4*>(&Kb[(size_t)(kt * 128 + kk) * 64 + q8]);
        }
        // copy V tile: 20 d-rows x 128 keys (split)
        for (int i = tid; i < 320; i += 256) {
            int d = i >> 4, cc = (i & 15) * 8;
            size_t src = (size_t)d * 640 + kt * 128 + cc;
            *reinterpret_cast<uint4*>(&VTH[d * 136 + cc]) =
                *reinterpret_cast<const uint4*>(&Vbh[src]);
            *reinterpret_cast<uint4*>(&VTL[d * 136 + cc]) =
                *reinterpret_cast<const uint4*>(&Vbl[src]);
        }
        __syncthreads();

        // S = Q K^T over concat k=64 (exact 3-term split in one pass)
        union { float f[16][4]; uint32_t u[16][4]; } SP;
        #pragma unroll
        for (int f = 0; f < 16; f++)
            #pragma unroll
            for (int e = 0; e < 4; e++) SP.f[f][e] = 0.f;

        #pragma unroll
        for (int g = 0; g < 8; g++) {
            uint32_t kf[4][4];
            #pragma unroll
            for (int kc = 0; kc < 4; kc++) {
                uint32_t a = (uint32_t)(((g * 16 + mrow) * 72 + kc * 16 + koff) * 2);
                ldm4(kf[kc][0], kf[kc][1], kf[kc][2], kf[kc][3], s2u(QK) + a);
            }
            #pragma unroll
            for (int kc = 0; kc < 4; kc++) {
                mma16816(SP.f[2 * g + 0], qf[kc], kf[kc][0], kf[kc][2]);
                mma16816(SP.f[2 * g + 1], qf[kc], kf[kc][1], kf[kc][3]);
            }
        }

        // exp + split P (in place)
        #pragma unroll
        for (int f = 0; f < 16; f++) {
            float e0 = __expf(SP.f[f][0]), e1 = __expf(SP.f[f][1]);
            float e2 = __expf(SP.f[f][2]), e3 = __expf(SP.f[f][3]);
            zl += e0 + e1; zh2 += e2 + e3;
            bf16 h0 = __float2bfloat16_rn(e0), h1 = __float2bfloat16_rn(e1);
            bf16 h2 = __float2bfloat16_rn(e2), h3 = __float2bfloat16_rn(e3);
            uint32_t ph01 = pk2h(h0, h1), ph23 = pk2h(h2, h3);
            uint32_t pl01 = pkbf(e0 - __bfloat162float(h0), e1 - __bfloat162float(h1));
            uint32_t pl23 = pkbf(e2 - __bfloat162float(h2), e3 - __bfloat162float(h3));
            SP.u[f][0] = ph01; SP.u[f][1] = ph23; SP.u[f][2] = pl01; SP.u[f][3] = pl23;
        }

        // O += P V
        #pragma unroll
        for (int kc2 = 0; kc2 < 8; kc2++) {
            uint32_t ah[4] = { SP.u[2 * kc2][0], SP.u[2 * kc2][1],
                               SP.u[2 * kc2 + 1][0], SP.u[2 * kc2 + 1][1] };
            uint32_t al[4] = { SP.u[2 * kc2][2], SP.u[2 * kc2][3],
                               SP.u[2 * kc2 + 1][2], SP.u[2 * kc2 + 1][3] };
            uint32_t vh4[4], vl4[4], vh2[2], vl2[2];
            uint32_t a4 = (uint32_t)((mrow * 136 + kc2 * 16 + koff) * 2);
            uint32_t a2 = (uint32_t)(((16 + (lane & 7)) * 136 + kc2 * 16 + ((lane >> 3) & 1) * 8) * 2);
            ldm4(vh4[0], vh4[1], vh4[2], vh4[3], s2u(VTH) + a4);
            ldm4(vl4[0], vl4[1], vl4[2], vl4[3], s2u(VTL) + a4);
            ldm2(vh2[0], vh2[1], s2u(VTH) + a2);
            ldm2(vl2[0], vl2[1], s2u(VTL) + a2);
            mma16816(O0[0], ah, vh4[0], vh4[2]);
            mma16816(O0[0], ah, vl4[0], vl4[2]);
            mma16816(O0[0], al, vh4[0], vh4[2]);
            mma16816(O0[1], ah, vh4[1], vh4[3]);
            mma16816(O0[1], ah, vl4[1], vl4[3]);
            mma16816(O0[1], al, vh4[1], vh4[3]);
            mma16816(O0[2], ah, vh2[0], vh2[1]);
            mma16816(O0[2], ah, vl2[0], vl2[1]);
            mma16816(O0[2], al, vh2[0], vh2[1]);
        }
    }

    zl  += __shfl_xor_sync(0xffffffffu, zl, 1);
    zl  += __shfl_xor_sync(0xffffffffu, zl, 2);
    zh2 += __shfl_xor_sync(0xffffffffu, zh2, 1);
    zh2 += __shfl_xor_sync(0xffffffffu, zh2, 2);
    float izl = 1.f / zl, izh = 1.f / zh2;

    const int rowq = lane >> 2;
    #pragma unroll
    for (int f = 0; f < 3; f++) {
        int d0 = f * 8 + (lane & 3) * 2;
        if (d0 >= 20) continue;
        #pragma unroll
        for (int half = 0; half < 2; half++) {
            int lq = qt * 128 + w * 16 + rowq + half * 8;
            float v0 = O0[f][half * 2]     * (half ? izh : izl);
            float v1 = O0[f][half * 2 + 1] * (half ? izh : izl);
            size_t o = (size_t)(lq * NH_ + n) * 400 + h * 20 + d0;
            bf16 h0 = __float2bfloat16_rn(v0), h1 = __float2bfloat16_rn(v1);
            *reinterpret_cast<uint32_t*>(&Xoh[o]) = pk2h(h0, h1);
            *reinterpret_cast<uint32_t*>(&Xol[o]) =
                pkbf(v0 - __bfloat162float(h0), v1 - __bfloat162float(h1));
        }
    }
}

// ---------------- score + softmax ----------------
__global__ void score_kernel(const float* __restrict__ a2, const float* __restrict__ Wa3,
                             const float* __restrict__ ba3, float* __restrict__ s)
{
    int row = blockIdx.x * 8 + threadIdx.y;
    if (row >= MM) return;
    int lane = threadIdx.x;
    float acc = 0.f;
    for (int d = lane; d < 200; d += 32) acc += a2[(size_t)row * 200 + d] * Wa3[d];
    #pragma unroll
    for (int o = 16; o > 0; o >>= 1) acc += __shfl_xor_sync(0xffffffffu, acc, o);
    if (lane == 0) s[row] = acc + ba3[0];
}

__global__ void softmax_u_kernel(const float* __restrict__ s, const float* __restrict__ hall,
                                 float* __restrict__ u)
{
    __shared__ float a[NH_];
    int bi = blockIdx.x;
    if (threadIdx.x == 0) {
        float mx = -1e30f;
        for (int j = 0; j < NH_; j++) mx = fmaxf(mx, s[bi * NH_ + j]);
        float Z = 0.f;
        for (int j = 0; j < NH_; j++) { float e = __expf(s[bi * NH_ + j] - mx); a[j] = e; Z += e; }
        float iz = 1.f / Z;
        for (int j = 0; j < NH_; j++) a[j] *= iz;
    }
    __syncthreads();
    for (int d = threadIdx.x; d < 400; d += blockDim.x) {
        float acc = 0.f;
        for (int j = 0; j < NH_; j++)
            acc += a[j] * hall[((size_t)bi * NH_ + j) * 400 + d];
        u[(size_t)bi * 400 + d] = acc;
    }
}

// ---------------- launch ----------------
static inline dim3 mgrid(int M, int N) { return dim3((N + TBN - 1) / TBN, (M + TBM - 1) / TBM); }

extern "C" void kernel_launch(void* const* d_in, const int* in_sizes, int n_in,
                              void* d_out, int out_size)
{
    const float* h    = (const float*)d_in[0];
    const float* c    = (const float*)d_in[2];
    const float* W1   = (const float*)d_in[4];
    const float* b1   = (const float*)d_in[5];
    const float* W2   = (const float*)d_in[6];
    const float* b2   = (const float*)d_in[7];
    const float* W3   = (const float*)d_in[8];
    const float* b3   = (const float*)d_in[9];
    const float* Wa1  = (const float*)d_in[10];
    const float* ba1  = (const float*)d_in[11];
    const float* Wa2  = (const float*)d_in[12];
    const float* ba2  = (const float*)d_in[13];
    const float* Wa3  = (const float*)d_in[14];
    const float* ba3  = (const float*)d_in[15];
    const float* Wqkv = (const float*)d_in[16];
    const float* bqkv = (const float*)d_in[17];
    const float* Wo   = (const float*)d_in[18];
    const float* bo   = (const float*)d_in[19];
    float* u = (float*)d_out;

    float *Hq3, *Cq3, *T1, *T2, *tc, *CA, *hall, *a2, *sc;
    cudaGetSymbolAddress((void**)&Hq3,  g_Hq3);
    cudaGetSymbolAddress((void**)&Cq3,  g_Cq3);
    cudaGetSymbolAddress((void**)&T1,   g_T1);
    cudaGetSymbolAddress((void**)&T2,   g_T2);
    cudaGetSymbolAddress((void**)&tc,   g_tc);
    cudaGetSymbolAddress((void**)&CA,   g_CA);
    cudaGetSymbolAddress((void**)&hall, g_hall);
    cudaGetSymbolAddress((void**)&a2,   g_a2);
    cudaGetSymbolAddress((void**)&sc,   g_s);

    bf16 *bHcat_h, *bHcat_l, *bh_h, *bh_l, *bHs_h, *bHs_l, *bHp1_h, *bHp1_l;
    bf16 *bc_h, *bc_l, *bCc_h, *bCc_l, *bCs_h, *bCs_l;
    bf16 *bXo_h, *bXo_l, *bhall_h, *bhall_l, *ba1_h, *ba1_l;
    bf16 *bW1_h, *bW1_l, *bW2_h, *bW2_l, *bWqkv_h, *bWqkv_l, *bW3_h, *bW3_l;
    bf16 *bWa1_h, *bWa1_l, *bWa2_h, *bWa2_l, *bWoT_h, *bWoT_l, *bWm_h, *bWm_l;
    bf16 *Kg, *VHg, *VLg;
    cudaGetSymbolAddress((void**)&bHcat_h, g_bHcat_h);  cudaGetSymbolAddress((void**)&bHcat_l, g_bHcat_l);
    cudaGetSymbolAddress((void**)&bh_h,    g_bh_h);     cudaGetSymbolAddress((void**)&bh_l,    g_bh_l);
    cudaGetSymbolAddress((void**)&bHs_h,   g_bHs_h);    cudaGetSymbolAddress((void**)&bHs_l,   g_bHs_l);
    cudaGetSymbolAddress((void**)&bHp1_h,  g_bHp1_h);   cudaGetSymbolAddress((void**)&bHp1_l,  g_bHp1_l);
    cudaGetSymbolAddress((void**)&bc_h,    g_bc_h);     cudaGetSymbolAddress((void**)&bc_l,    g_bc_l);
    cudaGetSymbolAddress((void**)&bCc_h,   g_bCc_h);    cudaGetSymbolAddress((void**)&bCc_l,   g_bCc_l);
    cudaGetSymbolAddress((void**)&bCs_h,   g_bCs_h);    cudaGetSymbolAddress((void**)&bCs_l,   g_bCs_l);
    cudaGetSymbolAddress((void**)&bXo_h,   g_bXo_h);    cudaGetSymbolAddress((void**)&bXo_l,   g_bXo_l);
    cudaGetSymbolAddress((void**)&bhall_h, g_bhall_h);  cudaGetSymbolAddress((void**)&bhall_l, g_bhall_l);
    cudaGetSymbolAddress((void**)&ba1_h,   g_ba1_h);    cudaGetSymbolAddress((void**)&ba1_l,   g_ba1_l);
    cudaGetSymbolAddress((void**)&bW1_h,   g_bW1_h);    cudaGetSymbolAddress((void**)&bW1_l,   g_bW1_l);
    cudaGetSymbolAddress((void**)&bW2_h,   g_bW2_h);    cudaGetSymbolAddress((void**)&bW2_l,   g_bW2_l);
    cudaGetSymbolAddress((void**)&bWqkv_h, g_bWqkv_h);  cudaGetSymbolAddress((void**)&bWqkv_l, g_bWqkv_l);
    cudaGetSymbolAddress((void**)&bW3_h,   g_bW3_h);    cudaGetSymbolAddress((void**)&bW3_l,   g_bW3_l);
    cudaGetSymbolAddress((void**)&bWa1_h,  g_bWa1_h);   cudaGetSymbolAddress((void**)&bWa1_l,  g_bWa1_l);
    cudaGetSymbolAddress((void**)&bWa2_h,  g_bWa2_h);   cudaGetSymbolAddress((void**)&bWa2_l,  g_bWa2_l);
    cudaGetSymbolAddress((void**)&bWoT_h,  g_bWoT_h);   cudaGetSymbolAddress((void**)&bWoT_l,  g_bWoT_l);
    cudaGetSymbolAddress((void**)&bWm_h,   g_bWm_h);    cudaGetSymbolAddress((void**)&bWm_l,   g_bWm_l);
    cudaGetSymbolAddress((void**)&Kg,  g_Kg);
    cudaGetSymbolAddress((void**)&VHg, g_VHg);  cudaGetSymbolAddress((void**)&VLg, g_VLg);

    // (1) merged conversions
    ConvParams CP;
    const float* srcs[8] = { h, c, W1, W2, Wqkv, W3, Wa1, Wa2 };
    bf16* his[8] = { bh_h, bc_h, bW1_h, bW2_h, bWqkv_h, bW3_h, bWa1_h, bWa2_h };
    bf16* los[8] = { bh_l, bc_l, bW1_l, bW2_l, bWqkv_l, bW3_l, bWa1_l, bWa2_l };
    int ns[8] = { BNH * 400, LL * 400, 400 * 1600, 400 * 800, 1200 * 400,
                  400 * 800, 400 * 800, 200 * 400 };
    int cum = 0;
    for (int i = 0; i < 8; i++) { CP.src[i] = srcs[i]; CP.hi[i] = his[i]; CP.lo[i] = los[i];
                                  CP.cum[i] = cum; cum += ns[i]; }
    CP.cum[8] = cum;
    conv_all_kernel<<<(cum + 255) / 256, 256>>>(CP);

    // (2) Hcat gather + Wo transpose-split, one launch
    prep2_kernel<<<HC_BLOCKS + TR_BLOCKS, 256>>>(bh_h, bh_l, bHcat_h, bHcat_l,
                                                 Wo, bWoT_h, bWoT_l);

    // (3) grouped GEMM launch 1: independent small GEMMs
    {
        GParams G; int cumb = 0; int gi = 0;
        auto add = [&](const bf16* Ah, const bf16* Al, int lda,
                       const bf16* Bh, const bf16* Bl, int ldb,
                       float* C, bf16* Ch, bf16* Cl, int ldc,
                       int M, int N, int K, int mode, int out, const float* aux0) {
            GDesc& D = G.d[gi];
            D.Ah = Ah; D.Al = Al; D.Bh = Bh; D.Bl = Bl;
            D.C = C; D.Ch = Ch; D.Cl = Cl; D.aux0 = aux0;
            D.lda = lda; D.ldb = ldb; D.ldc = ldc; D.M = M; D.N = N; D.K = K;
            D.mode = mode; D.out = out;
            D.bx = (N + TBN - 1) / TBN;
            int by = (M + TBM - 1) / TBM;
            G.cum[gi] = cumb; cumb += D.bx * by; gi++;
        };
        add(bHcat_h, bHcat_l, 1200, bW1_h, bW1_l, 1600, nullptr, bHp1_h, bHp1_l, 400,
            BNH, 400, 1200, 0, 2, nullptr);                                   // Hp1
        add(bh_h, bh_l, 400, bW2_h + 400, bW2_l + 400, 800, nullptr, bHs_h, bHs_l, 400,
            BNH, 400, 400, 0, 2, nullptr);                                    // Hs
        add(bc_h, bc_l, 400, bW1_h + 1200, bW1_l + 1200, 1600, nullptr, bCc_h, bCc_l, 400,
            LL, 400, 400, 0, 2, nullptr);                                     // Cc
        add(bc_h, bc_l, 400, bW2_h, bW2_l, 800, nullptr, bCs_h, bCs_l, 400,
            LL, 400, 400, 1, 2, b2);                                          // Cs
        add(bc_h, bc_l, 400, bWa1_h + 400, bWa1_l + 400, 800, CA, nullptr, nullptr, 400,
            LL, 400, 400, 1, 1, ba1);                                         // CA
        add(bW3_h + 400, bW3_l + 400, 800, bWoT_h, bWoT_l, 400, nullptr, bWm_h, bWm_l, 400,
            400, 400, 400, 0, 2, nullptr);                                    // Wm
        G.cum[gi] = cumb; G.nd = gi;
        gemm_group<<<cumb, 256>>>(G);
    }

    // (4) grouped GEMM launch 2: dependent small GEMMs
    {
        GParams G; int cumb = 0; int gi = 0;
        auto add = [&](const bf16* Ah, const bf16* Al, int lda,
                       const bf16* Bh, const bf16* Bl, int ldb,
                       float* C, int ldc, int M, int N, int K, int mode, const float* aux0) {
            GDesc& D = G.d[gi];
            D.Ah = Ah; D.Al = Al; D.Bh = Bh; D.Bl = Bl;
            D.C = C; D.Ch = nullptr; D.Cl = nullptr; D.aux0 = aux0;
            D.lda = lda; D.ldb = ldb; D.ldc = ldc; D.M = M; D.N = N; D.K = K;
            D.mode = mode; D.out = 1;
            D.bx = (N + TBN - 1) / TBN;
            int by = (M + TBM - 1) / TBM;
            G.cum[gi] = cumb; cumb += D.bx * by; gi++;
        };
        add(bHp1_h, bHp1_l, 400, bW3_h, bW3_l, 800, T1, 400, BNH, 400, 400, 0, nullptr);      // T1
        add(bHs_h, bHs_l, 400, bWqkv_h, bWqkv_l, 400, Hq3, 1200, BNH, 1200, 400, 0, nullptr); // Hq3
        add(bCs_h, bCs_l, 400, bWqkv_h, bWqkv_l, 400, Cq3, 1200, LL, 1200, 400, 1, bqkv);     // Cq3
        add(bCc_h, bCc_l, 400, bW3_h, bW3_l, 800, T2, 400, LL, 400, 400, 0, nullptr);         // T2
        G.cum[gi] = cumb; G.nd = gi;
        gemm_group<<<cumb, 256>>>(G);
    }

    // (5) attention K/V prep (concat K + split V)
    attn_prep<<<dim3(NH_, BB), 256>>>(Cq3, Hq3, Kg, VHg, VLg);

    // (6) tensor-core flash attention
    attn_mma<<<dim3(5, NH_, NHEAD), 256>>>(Cq3, Hq3, Kg, VHg, VLg, bXo_h, bXo_l);

    // (7) tc
    tc_kernel<<<50, 256>>>(b1, bo, b3, W3, tc);

    // (8-10) big GEMMs
    gemm_mma<3, 3><<<mgrid(MM, 400), 256>>>(bXo_h, bXo_l, 400, bWm_h, bWm_l, 400,
        hall, bhall_h, bhall_l, 400, MM, 400, 400, T1, T2, tc);
    gemm_mma<4, 2><<<mgrid(MM, 400), 256>>>(bhall_h, bhall_l, 400, bWa1_h, bWa1_l, 800,
        nullptr, ba1_h, ba1_l, 400, MM, 400, 400, CA, nullptr, nullptr);
    gemm_mma<2, 1><<<mgrid(MM, 200), 256>>>(ba1_h, ba1_l, 400, bWa2_h, bWa2_l, 400,
        a2, nullptr, nullptr, 200, MM, 200, 400, ba2, nullptr, nullptr);

    // (11-12) scoring + softmax + weighted sum
    score_kernel<<<MM / 8, dim3(32, 8)>>>(a2, Wa3, ba3, sc);
    softmax_u_kernel<<<LL, 128>>>(sc, hall, u);
}

// round 11
// speedup vs baseline: 1.4526x; 1.1572x over previous
#include <cuda_runtime.h>
#include <cuda_bf16.h>
#include <math.h>
#include <stdint.h>

// Problem constants
#define DD    400
#define BB    64
#define NC_   10
#define NH_   50
#define NHEAD 20
#define DH    20
#define LL    640      // BB*NC_
#define MM    32000    // BB*NC_*NH_
#define BNH   3200     // BB*NH_

typedef __nv_bfloat16 bf16;

// ---------------- fp32 device scratch ----------------
__device__ float g_Hq3 [BNH * 1200];
__device__ float g_Cq3 [LL * 1200];
__device__ float g_T1  [BNH * 400];
__device__ float g_T2  [LL * 400];
__device__ float g_tc  [400];
__device__ float g_CA  [LL * 400];
__device__ float g_hall[MM * 400];
__device__ float g_a2  [MM * 200];
__device__ float g_s   [MM];

// ---------------- bf16 split scratch (hi/lo pairs) ----------------
__device__ __align__(16) bf16 g_bHcat_h[BNH * 1200], g_bHcat_l[BNH * 1200];
__device__ __align__(16) bf16 g_bh_h  [BNH * 400],  g_bh_l  [BNH * 400];
__device__ __align__(16) bf16 g_bHs_h [BNH * 400],  g_bHs_l [BNH * 400];
__device__ __align__(16) bf16 g_bHp1_h[BNH * 400],  g_bHp1_l[BNH * 400];
__device__ __align__(16) bf16 g_bc_h  [LL * 400],   g_bc_l  [LL * 400];
__device__ __align__(16) bf16 g_bCc_h [LL * 400],   g_bCc_l [LL * 400];
__device__ __align__(16) bf16 g_bCs_h [LL * 400],   g_bCs_l [LL * 400];
__device__ __align__(16) bf16 g_bXo_h [MM * 400],   g_bXo_l [MM * 400];
__device__ __align__(16) bf16 g_bhall_h[MM * 400],  g_bhall_l[MM * 400];
__device__ __align__(16) bf16 g_ba1_h [MM * 400],   g_ba1_l [MM * 400];
__device__ __align__(16) bf16 g_bW1_h [400 * 1600], g_bW1_l [400 * 1600];
__device__ __align__(16) bf16 g_bW2_h [400 * 800],  g_bW2_l [400 * 800];
__device__ __align__(16) bf16 g_bWqkv_h[1200 * 400],g_bWqkv_l[1200 * 400];
__device__ __align__(16) bf16 g_bW3_h [400 * 800],  g_bW3_l [400 * 800];
__device__ __align__(16) bf16 g_bWa1_h[400 * 800],  g_bWa1_l[400 * 800];
__device__ __align__(16) bf16 g_bWa2_h[200 * 400],  g_bWa2_l[200 * 400];
__device__ __align__(16) bf16 g_bWoT_h[400 * 400],  g_bWoT_l[400 * 400];
__device__ __align__(16) bf16 g_bWm_h [400 * 400],  g_bWm_l [400 * 400];

// attention pre-split K/V
// K concat-split: [n][h][m(640)][64] = [Kh(20) | Kl(20) | Kh(20) | 0(4)]
// V: [n][h][d(20)][m(640)] hi/lo
__device__ __align__(16) bf16 g_Kg [50 * 20 * 640 * 64];
__device__ __align__(16) bf16 g_VHg[50 * 20 * 20 * 640], g_VLg[50 * 20 * 20 * 640];

// ---------------- helpers ----------------
__device__ __forceinline__ uint32_t s2u(const void* p) {
    return (uint32_t)__cvta_generic_to_shared(p);
}
__device__ __forceinline__ void ldm4(uint32_t& r0, uint32_t& r1, uint32_t& r2, uint32_t& r3,
                                     uint32_t addr) {
    asm volatile("ldmatrix.sync.aligned.m8n8.x4.shared.b16 {%0,%1,%2,%3}, [%4];"
                 : "=r"(r0), "=r"(r1), "=r"(r2), "=r"(r3) : "r"(addr));
}
__device__ __forceinline__ void ldm2(uint32_t& r0, uint32_t& r1, uint32_t addr) {
    asm volatile("ldmatrix.sync.aligned.m8n8.x2.shared.b16 {%0,%1}, [%2];"
                 : "=r"(r0), "=r"(r1) : "r"(addr));
}
__device__ __forceinline__ void mma16816(float* d, const uint32_t* a, uint32_t b0, uint32_t b1) {
    asm volatile("mma.sync.aligned.m16n8k16.row.col.f32.bf16.bf16.f32 "
                 "{%0,%1,%2,%3}, {%4,%5,%6,%7}, {%8,%9}, {%0,%1,%2,%3};"
                 : "+f"(d[0]), "+f"(d[1]), "+f"(d[2]), "+f"(d[3])
                 : "r"(a[0]), "r"(a[1]), "r"(a[2]), "r"(a[3]), "r"(b0), "r"(b1));
}
__device__ __forceinline__ uint32_t pkbf(float a, float b) {
    __nv_bfloat162 t = __floats2bfloat162_rn(a, b);
    return *reinterpret_cast<uint32_t*>(&t);
}
__device__ __forceinline__ uint32_t pk2h(bf16 a, bf16 b) {
    __nv_bfloat162 t; t.x = a; t.y = b;
    return *reinterpret_cast<uint32_t*>(&t);
}
// cp.async 16B with src-size (0 => zero-fill)
__device__ __forceinline__ void cpa16(uint32_t saddr, const void* gptr, uint32_t bytes) {
    asm volatile("cp.async.cg.shared.global [%0], [%1], 16, %2;"
                 :: "r"(saddr), "l"(gptr), "r"(bytes));
}
#define CPA_COMMIT() asm volatile("cp.async.commit_group;" ::: "memory")
#define CPA_WAIT0()  asm volatile("cp.async.wait_group 0;" ::: "memory")

// ---------------- merged convert: 8 segments in one launch ----------------
struct ConvParams {
    const float* src[8];
    bf16* hi[8];
    bf16* lo[8];
    int cum[9];
};
__global__ void conv_all_kernel(ConvParams P) {
    int i = blockIdx.x * blockDim.x + threadIdx.x;
    if (i >= P.cum[8]) return;
    int g = 0;
    #pragma unroll
    for (int s = 1; s < 8; s++) if (i >= P.cum[s]) g = s;
    int local = i - P.cum[g];
    float v = P.src[g][local];
    bf16 hh = __float2bfloat16_rn(v);
    P.hi[g][local] = hh;
    P.lo[g][local] = __float2bfloat16_rn(v - __bfloat162float(hh));
}

// ---------------- prep2: Hcat gather (bf16 pairs) + Wo transpose-split, one launch ----------------
#define HC_PAIRS (BNH * 600)
#define HC_BLOCKS ((HC_PAIRS + 255) / 256)
#define TR_BLOCKS ((400 * 400 + 255) / 256)
__global__ void prep2_kernel(const bf16* __restrict__ hh, const bf16* __restrict__ hl,
                             bf16* __restrict__ oh, bf16* __restrict__ ol,
                             const float* __restrict__ Wo,
                             bf16* __restrict__ th, bf16* __restrict__ tl) {
    if ((int)blockIdx.x < HC_BLOCKS) {
        int idx = blockIdx.x * blockDim.x + threadIdx.x;   // pairs
        if (idx >= HC_PAIRS) return;
        int row = idx / 600, pr = idx % 600;
        int col = pr * 2;
        int b = row / NH_, j = row % NH_;
        int part = col / 400, d = col % 400;
        int jj = (part == 0) ? (j + NH_ - 1) % NH_ : ((part == 1) ? j : (j + 1) % NH_);
        int s = (b * NH_ + jj) * 400 + d;
        reinterpret_cast<uint32_t*>(oh)[idx] = *reinterpret_cast<const uint32_t*>(&hh[s]);
        reinterpret_cast<uint32_t*>(ol)[idx] = *reinterpret_cast<const uint32_t*>(&hl[s]);
    } else {
        int idx = (blockIdx.x - HC_BLOCKS) * blockDim.x + threadIdx.x;
        if (idx >= 400 * 400) return;
        int n = idx / 400, k = idx % 400;
        float v = Wo[k * 400 + n];
        bf16 hv = __float2bfloat16_rn(v);
        th[idx] = hv;
        tl[idx] = __float2bfloat16_rn(v - __bfloat162float(hv));
    }
}

// ---------------- tc: warp-per-row reduction ----------------
__global__ void tc_kernel(const float* __restrict__ b1, const float* __restrict__ bo,
                          const float* __restrict__ b3, const float* __restrict__ W3,
                          float* __restrict__ tc) {
    int w = threadIdx.x >> 5, lane = threadIdx.x & 31;
    int r = blockIdx.x * 8 + w;
    if (r >= 400) return;
    const float* row = W3 + (size_t)r * 800;
    float acc = 0.f;
    for (int d = lane; d < 400; d += 32)
        acc += b1[d] * row[d] + bo[d] * row[400 + d];
    #pragma unroll
    for (int o = 16; o > 0; o >>= 1) acc += __shfl_xor_sync(0xffffffffu, acc, o);
    if (lane == 0) tc[r] = acc + b3[r];
}

// ---------------- shared tensor-core GEMM core (bf16 2-way split, 3 MMAs, cp.async) ----------------
#define TBM 128
#define TBN 128
#define TBK 16
#define SSTR 24

__device__ __forceinline__ void gemm_core(
    const bf16* __restrict__ Ah, const bf16* __restrict__ Al, int lda,
    const bf16* __restrict__ Bh, const bf16* __restrict__ Bl, int ldb,
    float* __restrict__ C, bf16* __restrict__ Ch, bf16* __restrict__ Cl,
    int ldc, int M, int N, int K,
    const float* __restrict__ aux0, const float* __restrict__ aux1,
    const float* __restrict__ aux2,
    int row0, int col0, int mode, int out)
{
    __shared__ __align__(16) bf16 sAh[2][TBM * SSTR];
    __shared__ __align__(16) bf16 sAl[2][TBM * SSTR];
    __shared__ __align__(16) bf16 sBh[2][TBM * SSTR];
    __shared__ __align__(16) bf16 sBl[2][TBM * SSTR];

    const int tid = threadIdx.x;
    const int lrow = tid >> 1, lhalf = tid & 1;

    const bool aok = (row0 + lrow) < M;
    const bool bok = (col0 + lrow) < N;
    const uint32_t abytes = aok ? 16u : 0u;
    const uint32_t bbytes = bok ? 16u : 0u;
    const int arow = aok ? (row0 + lrow) : 0;
    const int brow = bok ? (col0 + lrow) : 0;
    const bf16* Aph = Ah + (size_t)arow * lda + lhalf * 8;
    const bf16* Apl = Al + (size_t)arow * lda + lhalf * 8;
    const bf16* Bph = Bh + (size_t)brow * ldb + lhalf * 8;
    const bf16* Bpl = Bl + (size_t)brow * ldb + lhalf * 8;
    const uint32_t sboff = (uint32_t)((lrow * SSTR + lhalf * 8) * 2);

    const int w = tid >> 5, lane = tid & 31;
    const int wm = w >> 2, wn = w & 3;
    const int mrow = ((lane >> 3) & 1) * 8 + (lane & 7);
    const int koff = (lane >> 4) * 8;

    uint32_t aoff[4], boff[2];
    #pragma unroll
    for (int fm = 0; fm < 4; fm++)
        aoff[fm] = (uint32_t)(((wm * 64 + fm * 16 + mrow) * SSTR + koff) * 2);
    #pragma unroll
    for (int f = 0; f < 2; f++)
        boff[f] = (uint32_t)(((wn * 32 + f * 16 + mrow) * SSTR + koff) * 2);

    const uint32_t bAh = s2u(sAh), bAl = s2u(sAl), bBh = s2u(sBh), bBl = s2u(sBl);
    const uint32_t STB = TBM * SSTR * 2;

    float acc[4][4][4];
    #pragma unroll
    for (int i = 0; i < 4; i++)
        #pragma unroll
        for (int j = 0; j < 4; j++)
            #pragma unroll
            for (int e = 0; e < 4; e++) acc[i][j][e] = 0.f;

    // stage-0 async copy
    {
        cpa16(bAh + sboff, Aph, abytes);
        cpa16(bAl + sboff, Apl, abytes);
        cpa16(bBh + sboff, Bph, bbytes);
        cpa16(bBl + sboff, Bpl, bbytes);
        CPA_COMMIT();
    }
    CPA_WAIT0();
    __syncthreads();

    const int nk = K / TBK;
    for (int t = 0; t < nk; t++) {
        const int st = t & 1;
        if (t + 1 < nk) {
            const int k = (t + 1) * TBK;
            const uint32_t nso = (uint32_t)(st ^ 1) * STB + sboff;
            cpa16(bAh + nso, Aph + k, abytes);
            cpa16(bAl + nso, Apl + k, abytes);
            cpa16(bBh + nso, Bph + k, bbytes);
            cpa16(bBl + nso, Bpl + k, bbytes);
            CPA_COMMIT();
        }

        uint32_t ah[4][4], al[4][4], bh[2][4], bl[2][4];
        #pragma unroll
        for (int fm = 0; fm < 4; fm++) {
            ldm4(ah[fm][0], ah[fm][1], ah[fm][2], ah[fm][3], bAh + st * STB + aoff[fm]);
            ldm4(al[fm][0], al[fm][1], al[fm][2], al[fm][3], bAl + st * STB + aoff[fm]);
        }
        #pragma unroll
        for (int f = 0; f < 2; f++) {
            ldm4(bh[f][0], bh[f][1], bh[f][2], bh[f][3], bBh + st * STB + boff[f]);
            ldm4(bl[f][0], bl[f][1], bl[f][2], bl[f][3], bBl + st * STB + boff[f]);
        }

        #pragma unroll
        for (int fm = 0; fm < 4; fm++) {
            #pragma unroll
            for (int f = 0; f < 2; f++) {
                mma16816(acc[fm][f * 2 + 0], ah[fm], bh[f][0], bh[f][2]);
                mma16816(acc[fm][f * 2 + 0], ah[fm], bl[f][0], bl[f][2]);
                mma16816(acc[fm][f * 2 + 0], al[fm], bh[f][0], bh[f][2]);
                mma16816(acc[fm][f * 2 + 1], ah[fm], bh[f][1], bh[f][3]);
                mma16816(acc[fm][f * 2 + 1], ah[fm], bl[f][1], bl[f][3]);
                mma16816(acc[fm][f * 2 + 1], al[fm], bh[f][1], bh[f][3]);
            }
        }

        if (t + 1 < nk) {
            CPA_WAIT0();
            __syncthreads();
        }
    }

    // epilogue (pairwise: cols cc, cc+1)
    #pragma unroll
    for (int fm = 0; fm < 4; fm++) {
        #pragma unroll
        for (int half = 0; half < 2; half++) {
            const int r = row0 + wm * 64 + fm * 16 + (lane >> 2) + half * 8;
            if (r >= M) continue;
            int bb = 0, ii = 0, jj = 0;
            if (mode == 3 || mode == 4) { bb = r / 500; ii = (r / 50) % 10; jj = r % 50; }
            #pragma unroll
            for (int fn = 0; fn < 4; fn++) {
                const int cc = col0 + wn * 32 + fn * 8 + (lane & 3) * 2;
                if (cc >= N) continue;
                float v0 = acc[fm][fn][half * 2], v1 = acc[fm][fn][half * 2 + 1];
                if (mode == 1) { v0 += aux0[cc]; v1 += aux0[cc + 1]; }
                if (mode == 2) { v0 = tanhf(v0 + aux0[cc]); v1 = tanhf(v1 + aux0[cc + 1]); }
                if (mode == 3) {
                    const float* p0 = aux0 + (size_t)(bb * 50 + jj) * N;
                    const float* p1 = aux1 + (size_t)(bb * 10 + ii) * N;
                    v0 += p0[cc] + p1[cc] + aux2[cc];
                    v1 += p0[cc + 1] + p1[cc + 1] + aux2[cc + 1];
                }
                if (mode == 4) {
                    const float* p0 = aux0 + (size_t)(bb * 10 + ii) * N;
                    v0 = tanhf(v0 + p0[cc]); v1 = tanhf(v1 + p0[cc + 1]);
                }
                if (out & 1)
                    *reinterpret_cast<float2*>(&C[(size_t)r * ldc + cc]) = make_float2(v0, v1);
                if (out & 2) {
                    bf16 h0 = __float2bfloat16_rn(v0), h1 = __float2bfloat16_rn(v1);
                    *reinterpret_cast<uint32_t*>(&Ch[(size_t)r * ldc + cc]) = pk2h(h0, h1);
                    *reinterpret_cast<uint32_t*>(&Cl[(size_t)r * ldc + cc]) =
                        pkbf(v0 - __bfloat162float(h0), v1 - __bfloat162float(h1));
                }
            }
        }
    }
}

// template wrapper (big GEMMs, modes 2/3/4)
template <int MODE, int OUT>
__global__ __launch_bounds__(256, 2) void gemm_mma(
    const bf16* __restrict__ Ah, const bf16* __restrict__ Al, int lda,
    const bf16* __restrict__ Bh, const bf16* __restrict__ Bl, int ldb,
    float* __restrict__ C, bf16* __restrict__ Ch, bf16* __restrict__ Cl,
    int ldc, int M, int N, int K,
    const float* __restrict__ aux0, const float* __restrict__ aux1,
    const float* __restrict__ aux2)
{
    gemm_core(Ah, Al, lda, Bh, Bl, ldb, C, Ch, Cl, ldc, M, N, K,
              aux0, aux1, aux2, blockIdx.y * TBM, blockIdx.x * TBN, MODE, OUT);
}

// grouped wrapper (small GEMMs, modes 0/1)
struct GDesc {
    const bf16 *Ah, *Al, *Bh, *Bl;
    float* C; bf16 *Ch; bf16 *Cl;
    const float* aux0;
    int lda, ldb, ldc, M, N, K, mode, out, bx;
};
struct GParams { GDesc d[6]; int cum[7]; int nd; };

__global__ __launch_bounds__(256, 2) void gemm_group(GParams P) {
    int g = 0;
    while (g + 1 < P.nd && (int)blockIdx.x >= P.cum[g + 1]) g++;
    const GDesc& D = P.d[g];
    int local = blockIdx.x - P.cum[g];
    int bxi = local % D.bx, byi = local / D.bx;
    gemm_core(D.Ah, D.Al, D.lda, D.Bh, D.Bl, D.ldb, D.C, D.Ch, D.Cl, D.ldc,
              D.M, D.N, D.K, D.aux0, nullptr, nullptr,
              byi * TBM, bxi * TBN, D.mode, D.out);
}

// ---------------- attention K/V prep ----------------
// K concat layout per row (64): [Kh(0:20) | Kl(20:40) | Kh(40:60) | 0]
__global__ void attn_prep(const float* __restrict__ Cq3, const float* __restrict__ Hq3,
                          bf16* __restrict__ Kg,
                          bf16* __restrict__ VHg, bf16* __restrict__ VLg)
{
    const int n = blockIdx.x, b = blockIdx.y;
    const float* Hrow = Hq3 + (size_t)(b * NH_ + n) * 1200;
    const bf16 zb = __float2bfloat16_rn(0.f);

    // K: 20 heads x 10 rows x 64 dims
    for (int idx = threadIdx.x; idx < 20 * 10 * 64; idx += 256) {
        int h = idx / 640, rem = idx % 640, mm = rem >> 6, d = rem & 63;
        int m = b * 10 + mm;
        bf16 outv = zb;
        if (d < 60) {
            int dd = (d < 20) ? d : ((d < 40) ? d - 20 : d - 40);
            float kv = Cq3[m * 1200 + 400 + h * 20 + dd] + Hrow[400 + h * 20 + dd];
            bf16 hh = __float2bfloat16_rn(kv);
            outv = (d >= 20 && d < 40)
                 ? __float2bfloat16_rn(kv - __bfloat162float(hh)) : hh;
        }
        Kg[((size_t)(n * 20 + h) * 640 + m) * 64 + d] = outv;
    }
    // V: split hi/lo, [n][h][d][m]
    for (int idx = threadIdx.x; idx < 4000; idx += 256) {
        int h = idx / 200, d = (idx / 10) % 20, mm = idx % 10;
        int m = b * 10 + mm;
        float vv = Cq3[m * 1200 + 800 + h * 20 + d] + Hrow[800 + h * 20 + d];
        bf16 hh = __float2bfloat16_rn(vv);
        size_t o = ((size_t)(n * 20 + h) * 20 + d) * 640 + m;
        VHg[o] = hh;
        VLg[o] = __float2bfloat16_rn(vv - __bfloat162float(hh));
    }
}

// ---------------- tensor-core flash attention (concat-split S, cp.async pipelined) ----------------
// smem: K double buffer [2][64][64] (Q staging overlays both), V double buffer [2][24][64] hi/lo
// swizzled layout: elem' within row = (seg ^ (row&7))*8 + off, seg = elem>>3
__global__ __launch_bounds__(256, 2) void attn_mma(
    const float* __restrict__ Cq3, const float* __restrict__ Hq3,
    const bf16* __restrict__ Kg,
    const bf16* __restrict__ VHg, const bf16* __restrict__ VLg,
    bf16* __restrict__ Xoh, bf16* __restrict__ Xol)
{
    __shared__ __align__(16) bf16 sm[14336];   // 28KB: KB 2x4096, VTH 2x1536, VTL 2x1536

    const int qt = blockIdx.x, n = blockIdx.y, h = blockIdx.z;
    const int tid = threadIdx.x, w = tid >> 5, lane = tid & 31;
    const float scale = 0.22360679774997896f;  // 1/sqrt(20)
    const bf16 zb = __float2bfloat16_rn(0.f);

    const bf16* Kb  = Kg  + (size_t)(n * 20 + h) * 640 * 64;
    const bf16* Vbh = VHg + (size_t)(n * 20 + h) * 20 * 640;
    const bf16* Vbl = VLg + (size_t)(n * 20 + h) * 20 * 640;

    const uint32_t smb = s2u(sm);

    // build Q concat [128][64] swizzled into KB region (both buffers)
    for (int idx = tid; idx < 128 * 64; idx += 256) {
        int r = idx >> 6, d = idx & 63;
        bf16 outv = zb;
        if (d < 60) {
            int dd = (d < 20) ? d : ((d < 40) ? d - 20 : d - 40);
            int l = qt * 128 + r;
            int qr = (l / NC_) * NH_ + n;
            float qv = (Cq3[l * 1200 + h * 20 + dd] + Hq3[qr * 1200 + h * 20 + dd]) * scale;
            bf16 hh = __float2bfloat16_rn(qv);
            outv = (d < 40) ? hh : __float2bfloat16_rn(qv - __bfloat162float(hh));
        }
        int e = ((d >> 3) ^ (r & 7)) * 8 + (d & 7);
        sm[r * 64 + e] = outv;
    }
    __syncthreads();

    const int mrow = ((lane >> 3) & 1) * 8 + (lane & 7);
    const uint32_t lk16 = (uint32_t)((lane >> 4) << 4);     // 0 or 16 bytes

    uint32_t qf[4][4];
    #pragma unroll
    for (int kc = 0; kc < 4; kc++) {
        int row = w * 16 + mrow;
        uint32_t cb = (uint32_t)(kc * 32) + lk16;
        ldm4(qf[kc][0], qf[kc][1], qf[kc][2], qf[kc][3],
             smb + row * 128 + (cb ^ (uint32_t)((row & 7) << 4)));
    }
    __syncthreads();

    // tile copy: K 512 chunks, V 160 chunks x2
    auto copy_tile = [&](int kt2, int bufi) {
        const uint32_t kdst = smb + bufi * 8192;
        #pragma unroll
        for (int ii = 0; ii < 2; ii++) {
            int i = tid + ii * 256;
            int kk = i >> 3, seg = i & 7;
            cpa16(kdst + kk * 128 + (uint32_t)((seg * 16) ^ ((kk & 7) << 4)),
                  Kb + (size_t)(kt2 * 64 + kk) * 64 + seg * 8, 16);
        }
        if (tid < 160) {
            int d = tid >> 3, seg = tid & 7;
            uint32_t so = (uint32_t)((seg * 16) ^ ((d & 7) << 4));
            size_t gsrc = (size_t)d * 640 + kt2 * 64 + seg * 8;
            cpa16(smb + 16384 + bufi * 3072 + d * 128 + so, Vbh + gsrc, 16);
            cpa16(smb + 22528 + bufi * 3072 + d * 128 + so, Vbl + gsrc, 16);
        }
    };

    copy_tile(0, 0);
    CPA_COMMIT();

    float O0[3][4];
    #pragma unroll
    for (int f = 0; f < 3; f++)
        #pragma unroll
        for (int e = 0; e < 4; e++) O0[f][e] = 0.f;
    float zl = 0.f, zh2 = 0.f;

    for (int kt = 0; kt < 10; kt++) {
        const int bufi = kt & 1;
        CPA_WAIT0();
        __syncthreads();
        if (kt + 1 < 10) { copy_tile(kt + 1, bufi ^ 1); CPA_COMMIT(); }

        const uint32_t kbase = smb + bufi * 8192;
        // S = Q K^T over concat k=64
        union { float f[8][4]; uint32_t u[8][4]; } SP;
        #pragma unroll
        for (int f = 0; f < 8; f++)
            #pragma unroll
            for (int e = 0; e < 4; e++) SP.f[f][e] = 0.f;

        #pragma unroll
        for (int g = 0; g < 4; g++) {
            uint32_t kf[4][4];
            int row = g * 16 + mrow;
            #pragma unroll
            for (int kc = 0; kc < 4; kc++) {
                uint32_t cb = (uint32_t)(kc * 32) + lk16;
                ldm4(kf[kc][0], kf[kc][1], kf[kc][2], kf[kc][3],
                     kbase + row * 128 + (cb ^ (uint32_t)((row & 7) << 4)));
            }
            #pragma unroll
            for (int kc = 0; kc < 4; kc++) {
                mma16816(SP.f[2 * g + 0], qf[kc], kf[kc][0], kf[kc][2]);
                mma16816(SP.f[2 * g + 1], qf[kc], kf[kc][1], kf[kc][3]);
            }
        }

        // exp + split P (in place)
        #pragma unroll
        for (int f = 0; f < 8; f++) {
            float e0 = __expf(SP.f[f][0]), e1 = __expf(SP.f[f][1]);
            float e2 = __expf(SP.f[f][2]), e3 = __expf(SP.f[f][3]);
            zl += e0 + e1; zh2 += e2 + e3;
            bf16 h0 = __float2bfloat16_rn(e0), h1 = __float2bfloat16_rn(e1);
            bf16 h2 = __float2bfloat16_rn(e2), h3 = __float2bfloat16_rn(e3);
            uint32_t ph01 = pk2h(h0, h1), ph23 = pk2h(h2, h3);
            uint32_t pl01 = pkbf(e0 - __bfloat162float(h0), e1 - __bfloat162float(h1));
            uint32_t pl23 = pkbf(e2 - __bfloat162float(h2), e3 - __bfloat162float(h3));
            SP.u[f][0] = ph01; SP.u[f][1] = ph23; SP.u[f][2] = pl01; SP.u[f][3] = pl23;
        }

        // O += P V
        const uint32_t vhbase = smb + 16384 + bufi * 3072;
        const uint32_t vlbase = smb + 22528 + bufi * 3072;
        #pragma unroll
        for (int kc2 = 0; kc2 < 4; kc2++) {
            uint32_t ah[4] = { SP.u[2 * kc2][0], SP.u[2 * kc2][1],
                               SP.u[2 * kc2 + 1][0], SP.u[2 * kc2 + 1][1] };
            uint32_t al[4] = { SP.u[2 * kc2][2], SP.u[2 * kc2][3],
                               SP.u[2 * kc2 + 1][2], SP.u[2 * kc2 + 1][3] };
            uint32_t vh4[4], vl4[4], vh2[2], vl2[2];
            uint32_t cb4 = (uint32_t)(kc2 * 32) + lk16;
            uint32_t a4 = mrow * 128 + (cb4 ^ (uint32_t)((mrow & 7) << 4));
            int d2 = 16 + (lane & 7);
            uint32_t cb2 = (uint32_t)(kc2 * 32) + (uint32_t)(((lane >> 3) & 1) << 4);
            uint32_t a2 = d2 * 128 + (cb2 ^ (uint32_t)((d2 & 7) << 4));
            ldm4(vh4[0], vh4[1], vh4[2], vh4[3], vhbase + a4);
            ldm4(vl4[0], vl4[1], vl4[2], vl4[3], vlbase + a4);
            ldm2(vh2[0], vh2[1], vhbase + a2);
            ldm2(vl2[0], vl2[1], vlbase + a2);
            mma16816(O0[0], ah, vh4[0], vh4[2]);
            mma16816(O0[0], ah, vl4[0], vl4[2]);
            mma16816(O0[0], al, vh4[0], vh4[2]);
            mma16816(O0[1], ah, vh4[1], vh4[3]);
            mma16816(O0[1], ah, vl4[1], vl4[3]);
            mma16816(O0[1], al, vh4[1], vh4[3]);
            mma16816(O0[2], ah, vh2[0], vh2[1]);
            mma16816(O0[2], ah, vl2[0], vl2[1]);
            mma16816(O0[2], al, vh2[0], vh2[1]);
        }
    }

    zl  += __shfl_xor_sync(0xffffffffu, zl, 1);
    zl  += __shfl_xor_sync(0xffffffffu, zl, 2);
    zh2 += __shfl_xor_sync(0xffffffffu, zh2, 1);
    zh2 += __shfl_xor_sync(0xffffffffu, zh2, 2);
    float izl = 1.f / zl, izh = 1.f / zh2;

    const int rowq = lane >> 2;
    #pragma unroll
    for (int f = 0; f < 3; f++) {
        int d0 = f * 8 + (lane & 3) * 2;
        if (d0 >= 20) continue;
        #pragma unroll
        for (int half = 0; half < 2; half++) {
            int lq = qt * 128 + w * 16 + rowq + half * 8;
            float v0 = O0[f][half * 2]     * (half ? izh : izl);
            float v1 = O0[f][half * 2 + 1] * (half ? izh : izl);
            size_t o = (size_t)(lq * NH_ + n) * 400 + h * 20 + d0;
            bf16 h0 = __float2bfloat16_rn(v0), h1 = __float2bfloat16_rn(v1);
            *reinterpret_cast<uint32_t*>(&Xoh[o]) = pk2h(h0, h1);
            *reinterpret_cast<uint32_t*>(&Xol[o]) =
                pkbf(v0 - __bfloat162float(h0), v1 - __bfloat162float(h1));
        }
    }
}

// ---------------- score + softmax ----------------
__global__ void score_kernel(const float* __restrict__ a2, const float* __restrict__ Wa3,
                             const float* __restrict__ ba3, float* __restrict__ s)
{
    int row = blockIdx.x * 8 + threadIdx.y;
    if (row >= MM) return;
    int lane = threadIdx.x;
    float acc = 0.f;
    for (int d = lane; d < 200; d += 32) acc += a2[(size_t)row * 200 + d] * Wa3[d];
    #pragma unroll
    for (int o = 16; o > 0; o >>= 1) acc += __shfl_xor_sync(0xffffffffu, acc, o);
    if (lane == 0) s[row] = acc + ba3[0];
}

__global__ void softmax_u_kernel(const float* __restrict__ s, const float* __restrict__ hall,
                                 float* __restrict__ u)
{
    __shared__ float a[NH_];
    int bi = blockIdx.x;
    if (threadIdx.x == 0) {
        float mx = -1e30f;
        for (int j = 0; j < NH_; j++) mx = fmaxf(mx, s[bi * NH_ + j]);
        float Z = 0.f;
        for (int j = 0; j < NH_; j++) { float e = __expf(s[bi * NH_ + j] - mx); a[j] = e; Z += e; }
        float iz = 1.f / Z;
        for (int j = 0; j < NH_; j++) a[j] *= iz;
    }
    __syncthreads();
    for (int d = threadIdx.x; d < 400; d += blockDim.x) {
        float acc = 0.f;
        for (int j = 0; j < NH_; j++)
            acc += a[j] * hall[((size_t)bi * NH_ + j) * 400 + d];
        u[(size_t)bi * 400 + d] = acc;
    }
}

// ---------------- launch ----------------
static inline dim3 mgrid(int M, int N) { return dim3((N + TBN - 1) / TBN, (M + TBM - 1) / TBM); }

extern "C" void kernel_launch(void* const* d_in, const int* in_sizes, int n_in,
                              void* d_out, int out_size)
{
    const float* h    = (const float*)d_in[0];
    const float* c    = (const float*)d_in[2];
    const float* W1   = (const float*)d_in[4];
    const float* b1   = (const float*)d_in[5];
    const float* W2   = (const float*)d_in[6];
    const float* b2   = (const float*)d_in[7];
    const float* W3   = (const float*)d_in[8];
    const float* b3   = (const float*)d_in[9];
    const float* Wa1  = (const float*)d_in[10];
    const float* ba1  = (const float*)d_in[11];
    const float* Wa2  = (const float*)d_in[12];
    const float* ba2  = (const float*)d_in[13];
    const float* Wa3  = (const float*)d_in[14];
    const float* ba3  = (const float*)d_in[15];
    const float* Wqkv = (const float*)d_in[16];
    const float* bqkv = (const float*)d_in[17];
    const float* Wo   = (const float*)d_in[18];
    const float* bo   = (const float*)d_in[19];
    float* u = (float*)d_out;

    float *Hq3, *Cq3, *T1, *T2, *tc, *CA, *hall, *a2, *sc;
    cudaGetSymbolAddress((void**)&Hq3,  g_Hq3);
    cudaGetSymbolAddress((void**)&Cq3,  g_Cq3);
    cudaGetSymbolAddress((void**)&T1,   g_T1);
    cudaGetSymbolAddress((void**)&T2,   g_T2);
    cudaGetSymbolAddress((void**)&tc,   g_tc);
    cudaGetSymbolAddress((void**)&CA,   g_CA);
    cudaGetSymbolAddress((void**)&hall, g_hall);
    cudaGetSymbolAddress((void**)&a2,   g_a2);
    cudaGetSymbolAddress((void**)&sc,   g_s);

    bf16 *bHcat_h, *bHcat_l, *bh_h, *bh_l, *bHs_h, *bHs_l, *bHp1_h, *bHp1_l;
    bf16 *bc_h, *bc_l, *bCc_h, *bCc_l, *bCs_h, *bCs_l;
    bf16 *bXo_h, *bXo_l, *bhall_h, *bhall_l, *ba1_h, *ba1_l;
    bf16 *bW1_h, *bW1_l, *bW2_h, *bW2_l, *bWqkv_h, *bWqkv_l, *bW3_h, *bW3_l;
    bf16 *bWa1_h, *bWa1_l, *bWa2_h, *bWa2_l, *bWoT_h, *bWoT_l, *bWm_h, *bWm_l;
    bf16 *Kg, *VHg, *VLg;
    cudaGetSymbolAddress((void**)&bHcat_h, g_bHcat_h);  cudaGetSymbolAddress((void**)&bHcat_l, g_bHcat_l);
    cudaGetSymbolAddress((void**)&bh_h,    g_bh_h);     cudaGetSymbolAddress((void**)&bh_l,    g_bh_l);
    cudaGetSymbolAddress((void**)&bHs_h,   g_bHs_h);    cudaGetSymbolAddress((void**)&bHs_l,   g_bHs_l);
    cudaGetSymbolAddress((void**)&bHp1_h,  g_bHp1_h);   cudaGetSymbolAddress((void**)&bHp1_l,  g_bHp1_l);
    cudaGetSymbolAddress((void**)&bc_h,    g_bc_h);     cudaGetSymbolAddress((void**)&bc_l,    g_bc_l);
    cudaGetSymbolAddress((void**)&bCc_h,   g_bCc_h);    cudaGetSymbolAddress((void**)&bCc_l,   g_bCc_l);
    cudaGetSymbolAddress((void**)&bCs_h,   g_bCs_h);    cudaGetSymbolAddress((void**)&bCs_l,   g_bCs_l);
    cudaGetSymbolAddress((void**)&bXo_h,   g_bXo_h);    cudaGetSymbolAddress((void**)&bXo_l,   g_bXo_l);
    cudaGetSymbolAddress((void**)&bhall_h, g_bhall_h);  cudaGetSymbolAddress((void**)&bhall_l, g_bhall_l);
    cudaGetSymbolAddress((void**)&ba1_h,   g_ba1_h);    cudaGetSymbolAddress((void**)&ba1_l,   g_ba1_l);
    cudaGetSymbolAddress((void**)&bW1_h,   g_bW1_h);    cudaGetSymbolAddress((void**)&bW1_l,   g_bW1_l);
    cudaGetSymbolAddress((void**)&bW2_h,   g_bW2_h);    cudaGetSymbolAddress((void**)&bW2_l,   g_bW2_l);
    cudaGetSymbolAddress((void**)&bWqkv_h, g_bWqkv_h);  cudaGetSymbolAddress((void**)&bWqkv_l, g_bWqkv_l);
    cudaGetSymbolAddress((void**)&bW3_h,   g_bW3_h);    cudaGetSymbolAddress((void**)&bW3_l,   g_bW3_l);
    cudaGetSymbolAddress((void**)&bWa1_h,  g_bWa1_h);   cudaGetSymbolAddress((void**)&bWa1_l,  g_bWa1_l);
    cudaGetSymbolAddress((void**)&bWa2_h,  g_bWa2_h);   cudaGetSymbolAddress((void**)&bWa2_l,  g_bWa2_l);
    cudaGetSymbolAddress((void**)&bWoT_h,  g_bWoT_h);   cudaGetSymbolAddress((void**)&bWoT_l,  g_bWoT_l);
    cudaGetSymbolAddress((void**)&bWm_h,   g_bWm_h);    cudaGetSymbolAddress((void**)&bWm_l,   g_bWm_l);
    cudaGetSymbolAddress((void**)&Kg,  g_Kg);
    cudaGetSymbolAddress((void**)&VHg, g_VHg);  cudaGetSymbolAddress((void**)&VLg, g_VLg);

    // (1) merged conversions
    ConvParams CP;
    const float* srcs[8] = { h, c, W1, W2, Wqkv, W3, Wa1, Wa2 };
    bf16* his[8] = { bh_h, bc_h, bW1_h, bW2_h, bWqkv_h, bW3_h, bWa1_h, bWa2_h };
    bf16* los[8] = { bh_l, bc_l, bW1_l, bW2_l, bWqkv_l, bW3_l, bWa1_l, bWa2_l };
    int ns[8] = { BNH * 400, LL * 400, 400 * 1600, 400 * 800, 1200 * 400,
                  400 * 800, 400 * 800, 200 * 400 };
    int cum = 0;
    for (int i = 0; i < 8; i++) { CP.src[i] = srcs[i]; CP.hi[i] = his[i]; CP.lo[i] = los[i];
                                  CP.cum[i] = cum; cum += ns[i]; }
    CP.cum[8] = cum;
    conv_all_kernel<<<(cum + 255) / 256, 256>>>(CP);

    // (2) Hcat gather + Wo transpose-split, one launch
    prep2_kernel<<<HC_BLOCKS + TR_BLOCKS, 256>>>(bh_h, bh_l, bHcat_h, bHcat_l,
                                                 Wo, bWoT_h, bWoT_l);

    // (3) grouped GEMM launch 1: independent small GEMMs
    {
        GParams G; int cumb = 0; int gi = 0;
        auto add = [&](const bf16* Ah, const bf16* Al, int lda,
                       const bf16* Bh, const bf16* Bl, int ldb,
                       float* C, bf16* Ch, bf16* Cl, int ldc,
                       int M, int N, int K, int mode, int out, const float* aux0) {
            GDesc& D = G.d[gi];
            D.Ah = Ah; D.Al = Al; D.Bh = Bh; D.Bl = Bl;
            D.C = C; D.Ch = Ch; D.Cl = Cl; D.aux0 = aux0;
            D.lda = lda; D.ldb = ldb; D.ldc = ldc; D.M = M; D.N = N; D.K = K;
            D.mode = mode; D.out = out;
            D.bx = (N + TBN - 1) / TBN;
            int by = (M + TBM - 1) / TBM;
            G.cum[gi] = cumb; cumb += D.bx * by; gi++;
        };
        add(bHcat_h, bHcat_l, 1200, bW1_h, bW1_l, 1600, nullptr, bHp1_h, bHp1_l, 400,
            BNH, 400, 1200, 0, 2, nullptr);                                   // Hp1
        add(bh_h, bh_l, 400, bW2_h + 400, bW2_l + 400, 800, nullptr, bHs_h, bHs_l, 400,
            BNH, 400, 400, 0, 2, nullptr);                                    // Hs
        add(bc_h, bc_l, 400, bW1_h + 1200, bW1_l + 1200, 1600, nullptr, bCc_h, bCc_l, 400,
            LL, 400, 400, 0, 2, nullptr);                                     // Cc
        add(bc_h, bc_l, 400, bW2_h, bW2_l, 800, nullptr, bCs_h, bCs_l, 400,
            LL, 400, 400, 1, 2, b2);                                          // Cs
        add(bc_h, bc_l, 400, bWa1_h + 400, bWa1_l + 400, 800, CA, nullptr, nullptr, 400,
            LL, 400, 400, 1, 1, ba1);                                         // CA
        add(bW3_h + 400, bW3_l + 400, 800, bWoT_h, bWoT_l, 400, nullptr, bWm_h, bWm_l, 400,
            400, 400, 400, 0, 2, nullptr);                                    // Wm
        G.cum[gi] = cumb; G.nd = gi;
        gemm_group<<<cumb, 256>>>(G);
    }

    // (4) grouped GEMM launch 2: dependent small GEMMs
    {
        GParams G; int cumb = 0; int gi = 0;
        auto add = [&](const bf16* Ah, const bf16* Al, int lda,
                       const bf16* Bh, const bf16* Bl, int ldb,
                       float* C, int ldc, int M, int N, int K, int mode, const float* aux0) {
            GDesc& D = G.d[gi];
            D.Ah = Ah; D.Al = Al; D.Bh = Bh; D.Bl = Bl;
            D.C = C; D.Ch = nullptr; D.Cl = nullptr; D.aux0 = aux0;
            D.lda = lda; D.ldb = ldb; D.ldc = ldc; D.M = M; D.N = N; D.K = K;
            D.mode = mode; D.out = 1;
            D.bx = (N + TBN - 1) / TBN;
            int by = (M + TBM - 1) / TBM;
            G.cum[gi] = cumb; cumb += D.bx * by; gi++;
        };
        add(bHp1_h, bHp1_l, 400, bW3_h, bW3_l, 800, T1, 400, BNH, 400, 400, 0, nullptr);      // T1
        add(bHs_h, bHs_l, 400, bWqkv_h, bWqkv_l, 400, Hq3, 1200, BNH, 1200, 400, 0, nullptr); // Hq3
        add(bCs_h, bCs_l, 400, bWqkv_h, bWqkv_l, 400, Cq3, 1200, LL, 1200, 400, 1, bqkv);     // Cq3
        add(bCc_h, bCc_l, 400, bW3_h, bW3_l, 800, T2, 400, LL, 400, 400, 0, nullptr);         // T2
        G.cum[gi] = cumb; G.nd = gi;
        gemm_group<<<cumb, 256>>>(G);
    }

    // (5) attention K/V prep (concat K + split V)
    attn_prep<<<dim3(NH_, BB), 256>>>(Cq3, Hq3, Kg, VHg, VLg);

    // (6) tensor-core flash attention (pipelined)
    attn_mma<<<dim3(5, NH_, NHEAD), 256>>>(Cq3, Hq3, Kg, VHg, VLg, bXo_h, bXo_l);

    // (7) tc
    tc_kernel<<<50, 256>>>(b1, bo, b3, W3, tc);

    // (8-10) big GEMMs
    gemm_mma<3, 3><<<mgrid(MM, 400), 256>>>(bXo_h, bXo_l, 400, bWm_h, bWm_l, 400,
        hall, bhall_h, bhall_l, 400, MM, 400, 400, T1, T2, tc);
    gemm_mma<4, 2><<<mgrid(MM, 400), 256>>>(bhall_h, bhall_l, 400, bWa1_h, bWa1_l, 800,
        nullptr, ba1_h, ba1_l, 400, MM, 400, 400, CA, nullptr, nullptr);
    gemm_mma<2, 1><<<mgrid(MM, 200), 256>>>(ba1_h, ba1_l, 400, bWa2_h, bWa2_l, 400,
        a2, nullptr, nullptr, 200, MM, 200, 400, ba2, nullptr, nullptr);

    // (11-12) scoring + softmax + weighted sum
    score_kernel<<<MM / 8, dim3(32, 8)>>>(a2, Wa3, ba3, sc);
    softmax_u_kernel<<<LL, 128>>>(sc, hall, u);
}

// round 12
// speedup vs baseline: 1.5315x; 1.0543x over previous
#include <cuda_runtime.h>
#include <cuda_bf16.h>
#include <math.h>
#include <stdint.h>

// Problem constants
#define DD    400
#define BB    64
#define NC_   10
#define NH_   50
#define NHEAD 20
#define DH    20
#define LL    640      // BB*NC_
#define MM    32000    // BB*NC_*NH_
#define BNH   3200     // BB*NH_

typedef __nv_bfloat16 bf16;

// ---------------- fp32 device scratch ----------------
__device__ float g_Hq3 [BNH * 1200];
__device__ float g_Cq3 [LL * 1200];
__device__ float g_T1  [BNH * 400];
__device__ float g_T2  [LL * 400];
__device__ float g_tc  [400];
__device__ float g_CA  [LL * 400];
__device__ float g_a2  [MM * 200];
__device__ float g_s   [MM];

// ---------------- bf16 split scratch (hi/lo pairs) ----------------
__device__ __align__(16) bf16 g_bHcat_h[BNH * 1200], g_bHcat_l[BNH * 1200];
__device__ __align__(16) bf16 g_bh_h  [BNH * 400],  g_bh_l  [BNH * 400];
__device__ __align__(16) bf16 g_bHs_h [BNH * 400],  g_bHs_l [BNH * 400];
__device__ __align__(16) bf16 g_bHp1_h[BNH * 400],  g_bHp1_l[BNH * 400];
__device__ __align__(16) bf16 g_bc_h  [LL * 400],   g_bc_l  [LL * 400];
__device__ __align__(16) bf16 g_bCc_h [LL * 400],   g_bCc_l [LL * 400];
__device__ __align__(16) bf16 g_bCs_h [LL * 400],   g_bCs_l [LL * 400];
__device__ __align__(16) bf16 g_bXo_h [MM * 400],   g_bXo_l [MM * 400];
__device__ __align__(16) bf16 g_bhall_h[MM * 400],  g_bhall_l[MM * 400];
__device__ __align__(16) bf16 g_ba1_h [MM * 400],   g_ba1_l [MM * 400];
__device__ __align__(16) bf16 g_bW1_h [400 * 1600], g_bW1_l [400 * 1600];
__device__ __align__(16) bf16 g_bW2_h [400 * 800],  g_bW2_l [400 * 800];
__device__ __align__(16) bf16 g_bWqkv_h[1200 * 400],g_bWqkv_l[1200 * 400];
__device__ __align__(16) bf16 g_bW3_h [400 * 800],  g_bW3_l [400 * 800];
__device__ __align__(16) bf16 g_bWa1_h[400 * 800],  g_bWa1_l[400 * 800];
__device__ __align__(16) bf16 g_bWa2_h[200 * 400],  g_bWa2_l[200 * 400];
__device__ __align__(16) bf16 g_bWoT_h[400 * 400],  g_bWoT_l[400 * 400];
__device__ __align__(16) bf16 g_bWm_h [400 * 400],  g_bWm_l [400 * 400];

// attention pre-split K/V
// K concat-split: [n][h][m(640)][64] = [Kh(20) | Kl(20) | Kh(20) | 0(4)]
// V: [n][h][d(20)][m(640)] hi/lo
__device__ __align__(16) bf16 g_Kg [50 * 20 * 640 * 64];
__device__ __align__(16) bf16 g_VHg[50 * 20 * 20 * 640], g_VLg[50 * 20 * 20 * 640];

// ---------------- helpers ----------------
__device__ __forceinline__ uint32_t s2u(const void* p) {
    return (uint32_t)__cvta_generic_to_shared(p);
}
__device__ __forceinline__ void ldm4(uint32_t& r0, uint32_t& r1, uint32_t& r2, uint32_t& r3,
                                     uint32_t addr) {
    asm volatile("ldmatrix.sync.aligned.m8n8.x4.shared.b16 {%0,%1,%2,%3}, [%4];"
                 : "=r"(r0), "=r"(r1), "=r"(r2), "=r"(r3) : "r"(addr));
}
__device__ __forceinline__ void ldm2(uint32_t& r0, uint32_t& r1, uint32_t addr) {
    asm volatile("ldmatrix.sync.aligned.m8n8.x2.shared.b16 {%0,%1}, [%2];"
                 : "=r"(r0), "=r"(r1) : "r"(addr));
}
__device__ __forceinline__ void mma16816(float* d, const uint32_t* a, uint32_t b0, uint32_t b1) {
    asm volatile("mma.sync.aligned.m16n8k16.row.col.f32.bf16.bf16.f32 "
                 "{%0,%1,%2,%3}, {%4,%5,%6,%7}, {%8,%9}, {%0,%1,%2,%3};"
                 : "+f"(d[0]), "+f"(d[1]), "+f"(d[2]), "+f"(d[3])
                 : "r"(a[0]), "r"(a[1]), "r"(a[2]), "r"(a[3]), "r"(b0), "r"(b1));
}
__device__ __forceinline__ uint32_t pkbf(float a, float b) {
    __nv_bfloat162 t = __floats2bfloat162_rn(a, b);
    return *reinterpret_cast<uint32_t*>(&t);
}
__device__ __forceinline__ uint32_t pk2h(bf16 a, bf16 b) {
    __nv_bfloat162 t; t.x = a; t.y = b;
    return *reinterpret_cast<uint32_t*>(&t);
}
// cp.async 16B with src-size (0 => zero-fill)
__device__ __forceinline__ void cpa16(uint32_t saddr, const void* gptr, uint32_t bytes) {
    asm volatile("cp.async.cg.shared.global [%0], [%1], 16, %2;"
                 :: "r"(saddr), "l"(gptr), "r"(bytes));
}
#define CPA_COMMIT() asm volatile("cp.async.commit_group;" ::: "memory")
#define CPA_WAIT0()  asm volatile("cp.async.wait_group 0;" ::: "memory")

// ---------------- merged convert: 8 segments in one launch ----------------
struct ConvParams {
    const float* src[8];
    bf16* hi[8];
    bf16* lo[8];
    int cum[9];
};
__global__ void conv_all_kernel(ConvParams P) {
    int i = blockIdx.x * blockDim.x + threadIdx.x;
    if (i >= P.cum[8]) return;
    int g = 0;
    #pragma unroll
    for (int s = 1; s < 8; s++) if (i >= P.cum[s]) g = s;
    int local = i - P.cum[g];
    float v = P.src[g][local];
    bf16 hh = __float2bfloat16_rn(v);
    P.hi[g][local] = hh;
    P.lo[g][local] = __float2bfloat16_rn(v - __bfloat162float(hh));
}

// ---------------- prep2: Hcat gather (bf16 pairs) + Wo transpose-split, one launch ----------------
#define HC_PAIRS (BNH * 600)
#define HC_BLOCKS ((HC_PAIRS + 255) / 256)
#define TR_BLOCKS ((400 * 400 + 255) / 256)
__global__ void prep2_kernel(const bf16* __restrict__ hh, const bf16* __restrict__ hl,
                             bf16* __restrict__ oh, bf16* __restrict__ ol,
                             const float* __restrict__ Wo,
                             bf16* __restrict__ th, bf16* __restrict__ tl) {
    if ((int)blockIdx.x < HC_BLOCKS) {
        int idx = blockIdx.x * blockDim.x + threadIdx.x;   // pairs
        if (idx >= HC_PAIRS) return;
        int row = idx / 600, pr = idx % 600;
        int col = pr * 2;
        int b = row / NH_, j = row % NH_;
        int part = col / 400, d = col % 400;
        int jj = (part == 0) ? (j + NH_ - 1) % NH_ : ((part == 1) ? j : (j + 1) % NH_);
        int s = (b * NH_ + jj) * 400 + d;
        reinterpret_cast<uint32_t*>(oh)[idx] = *reinterpret_cast<const uint32_t*>(&hh[s]);
        reinterpret_cast<uint32_t*>(ol)[idx] = *reinterpret_cast<const uint32_t*>(&hl[s]);
    } else {
        int idx = (blockIdx.x - HC_BLOCKS) * blockDim.x + threadIdx.x;
        if (idx >= 400 * 400) return;
        int n = idx / 400, k = idx % 400;
        float v = Wo[k * 400 + n];
        bf16 hv = __float2bfloat16_rn(v);
        th[idx] = hv;
        tl[idx] = __float2bfloat16_rn(v - __bfloat162float(hv));
    }
}

// ---------------- tc: warp-per-row reduction ----------------
__global__ void tc_kernel(const float* __restrict__ b1, const float* __restrict__ bo,
                          const float* __restrict__ b3, const float* __restrict__ W3,
                          float* __restrict__ tc) {
    int w = threadIdx.x >> 5, lane = threadIdx.x & 31;
    int r = blockIdx.x * 8 + w;
    if (r >= 400) return;
    const float* row = W3 + (size_t)r * 800;
    float acc = 0.f;
    for (int d = lane; d < 400; d += 32)
        acc += b1[d] * row[d] + bo[d] * row[400 + d];
    #pragma unroll
    for (int o = 16; o > 0; o >>= 1) acc += __shfl_xor_sync(0xffffffffu, acc, o);
    if (lane == 0) tc[r] = acc + b3[r];
}

// ---------------- shared tensor-core GEMM core (bf16 split, cp.async) ----------------
// nsplit==3: full AhBh + AhBl + AlBh ; nsplit==2: (Ah+Al)·Bh (Bl never touched)
#define TBM 128
#define TBN 128
#define TBK 16
#define SSTR 24

__device__ __forceinline__ void gemm_core(
    const bf16* __restrict__ Ah, const bf16* __restrict__ Al, int lda,
    const bf16* __restrict__ Bh, const bf16* __restrict__ Bl, int ldb,
    float* __restrict__ C, bf16* __restrict__ Ch, bf16* __restrict__ Cl,
    int ldc, int M, int N, int K,
    const float* __restrict__ aux0, const float* __restrict__ aux1,
    const float* __restrict__ aux2,
    int row0, int col0, int mode, int out, int nsplit)
{
    __shared__ __align__(16) bf16 sAh[2][TBM * SSTR];
    __shared__ __align__(16) bf16 sAl[2][TBM * SSTR];
    __shared__ __align__(16) bf16 sBh[2][TBM * SSTR];
    __shared__ __align__(16) bf16 sBl[2][TBM * SSTR];

    const int tid = threadIdx.x;
    const int lrow = tid >> 1, lhalf = tid & 1;

    const bool aok = (row0 + lrow) < M;
    const bool bok = (col0 + lrow) < N;
    const uint32_t abytes = aok ? 16u : 0u;
    const uint32_t bbytes = bok ? 16u : 0u;
    const int arow = aok ? (row0 + lrow) : 0;
    const int brow = bok ? (col0 + lrow) : 0;
    const bf16* Aph = Ah + (size_t)arow * lda + lhalf * 8;
    const bf16* Apl = Al + (size_t)arow * lda + lhalf * 8;
    const bf16* Bph = Bh + (size_t)brow * ldb + lhalf * 8;
    const bf16* Bpl = Bl + (size_t)brow * ldb + lhalf * 8;
    const uint32_t sboff = (uint32_t)((lrow * SSTR + lhalf * 8) * 2);

    const int w = tid >> 5, lane = tid & 31;
    const int wm = w >> 2, wn = w & 3;
    const int mrow = ((lane >> 3) & 1) * 8 + (lane & 7);
    const int koff = (lane >> 4) * 8;

    uint32_t aoff[4], boff[2];
    #pragma unroll
    for (int fm = 0; fm < 4; fm++)
        aoff[fm] = (uint32_t)(((wm * 64 + fm * 16 + mrow) * SSTR + koff) * 2);
    #pragma unroll
    for (int f = 0; f < 2; f++)
        boff[f] = (uint32_t)(((wn * 32 + f * 16 + mrow) * SSTR + koff) * 2);

    const uint32_t bAh = s2u(sAh), bAl = s2u(sAl), bBh = s2u(sBh), bBl = s2u(sBl);
    const uint32_t STB = TBM * SSTR * 2;

    float acc[4][4][4];
    #pragma unroll
    for (int i = 0; i < 4; i++)
        #pragma unroll
        for (int j = 0; j < 4; j++)
            #pragma unroll
            for (int e = 0; e < 4; e++) acc[i][j][e] = 0.f;

    // stage-0 async copy
    {
        cpa16(bAh + sboff, Aph, abytes);
        cpa16(bAl + sboff, Apl, abytes);
        cpa16(bBh + sboff, Bph, bbytes);
        if (nsplit == 3) cpa16(bBl + sboff, Bpl, bbytes);
        CPA_COMMIT();
    }
    CPA_WAIT0();
    __syncthreads();

    const int nk = K / TBK;
    for (int t = 0; t < nk; t++) {
        const int st = t & 1;
        if (t + 1 < nk) {
            const int k = (t + 1) * TBK;
            const uint32_t nso = (uint32_t)(st ^ 1) * STB + sboff;
            cpa16(bAh + nso, Aph + k, abytes);
            cpa16(bAl + nso, Apl + k, abytes);
            cpa16(bBh + nso, Bph + k, bbytes);
            if (nsplit == 3) cpa16(bBl + nso, Bpl + k, bbytes);
            CPA_COMMIT();
        }

        uint32_t ah[4][4], al[4][4], bh[2][4], bl[2][4];
        #pragma unroll
        for (int fm = 0; fm < 4; fm++) {
            ldm4(ah[fm][0], ah[fm][1], ah[fm][2], ah[fm][3], bAh + st * STB + aoff[fm]);
            ldm4(al[fm][0], al[fm][1], al[fm][2], al[fm][3], bAl + st * STB + aoff[fm]);
        }
        #pragma unroll
        for (int f = 0; f < 2; f++) {
            ldm4(bh[f][0], bh[f][1], bh[f][2], bh[f][3], bBh + st * STB + boff[f]);
            if (nsplit == 3)
                ldm4(bl[f][0], bl[f][1], bl[f][2], bl[f][3], bBl + st * STB + boff[f]);
        }

        #pragma unroll
        for (int fm = 0; fm < 4; fm++) {
            #pragma unroll
            for (int f = 0; f < 2; f++) {
                mma16816(acc[fm][f * 2 + 0], ah[fm], bh[f][0], bh[f][2]);
                mma16816(acc[fm][f * 2 + 0], al[fm], bh[f][0], bh[f][2]);
                if (nsplit == 3)
                    mma16816(acc[fm][f * 2 + 0], ah[fm], bl[f][0], bl[f][2]);
                mma16816(acc[fm][f * 2 + 1], ah[fm], bh[f][1], bh[f][3]);
                mma16816(acc[fm][f * 2 + 1], al[fm], bh[f][1], bh[f][3]);
                if (nsplit == 3)
                    mma16816(acc[fm][f * 2 + 1], ah[fm], bl[f][1], bl[f][3]);
            }
        }

        if (t + 1 < nk) {
            CPA_WAIT0();
            __syncthreads();
        }
    }

    // epilogue (pairwise: cols cc, cc+1)
    #pragma unroll
    for (int fm = 0; fm < 4; fm++) {
        #pragma unroll
        for (int half = 0; half < 2; half++) {
            const int r = row0 + wm * 64 + fm * 16 + (lane >> 2) + half * 8;
            if (r >= M) continue;
            int bb = 0, ii = 0, jj = 0;
            if (mode == 3 || mode == 4) { bb = r / 500; ii = (r / 50) % 10; jj = r % 50; }
            #pragma unroll
            for (int fn = 0; fn < 4; fn++) {
                const int cc = col0 + wn * 32 + fn * 8 + (lane & 3) * 2;
                if (cc >= N) continue;
                float v0 = acc[fm][fn][half * 2], v1 = acc[fm][fn][half * 2 + 1];
                if (mode == 1) { v0 += aux0[cc]; v1 += aux0[cc + 1]; }
                if (mode == 2) { v0 = tanhf(v0 + aux0[cc]); v1 = tanhf(v1 + aux0[cc + 1]); }
                if (mode == 3) {
                    const float* p0 = aux0 + (size_t)(bb * 50 + jj) * N;
                    const float* p1 = aux1 + (size_t)(bb * 10 + ii) * N;
                    v0 += p0[cc] + p1[cc] + aux2[cc];
                    v1 += p0[cc + 1] + p1[cc + 1] + aux2[cc + 1];
                }
                if (mode == 4) {
                    const float* p0 = aux0 + (size_t)(bb * 10 + ii) * N;
                    v0 = tanhf(v0 + p0[cc]); v1 = tanhf(v1 + p0[cc + 1]);
                }
                if (out & 1)
                    *reinterpret_cast<float2*>(&C[(size_t)r * ldc + cc]) = make_float2(v0, v1);
                if (out & 2) {
                    bf16 h0 = __float2bfloat16_rn(v0), h1 = __float2bfloat16_rn(v1);
                    *reinterpret_cast<uint32_t*>(&Ch[(size_t)r * ldc + cc]) = pk2h(h0, h1);
                    *reinterpret_cast<uint32_t*>(&Cl[(size_t)r * ldc + cc]) =
                        pkbf(v0 - __bfloat162float(h0), v1 - __bfloat162float(h1));
                }
            }
        }
    }
}

// template wrapper (big GEMMs)
template <int MODE, int OUT, int NSPLIT>
__global__ __launch_bounds__(256, 2) void gemm_mma(
    const bf16* __restrict__ Ah, const bf16* __restrict__ Al, int lda,
    const bf16* __restrict__ Bh, const bf16* __restrict__ Bl, int ldb,
    float* __restrict__ C, bf16* __restrict__ Ch, bf16* __restrict__ Cl,
    int ldc, int M, int N, int K,
    const float* __restrict__ aux0, const float* __restrict__ aux1,
    const float* __restrict__ aux2)
{
    gemm_core(Ah, Al, lda, Bh, Bl, ldb, C, Ch, Cl, ldc, M, N, K,
              aux0, aux1, aux2, blockIdx.y * TBM, blockIdx.x * TBN, MODE, OUT, NSPLIT);
}

// grouped wrapper (small GEMMs, modes 0/1, always nsplit=3)
struct GDesc {
    const bf16 *Ah, *Al, *Bh, *Bl;
    float* C; bf16 *Ch; bf16 *Cl;
    const float* aux0;
    int lda, ldb, ldc, M, N, K, mode, out, bx;
};
struct GParams { GDesc d[6]; int cum[7]; int nd; };

__global__ __launch_bounds__(256, 2) void gemm_group(GParams P) {
    int g = 0;
    while (g + 1 < P.nd && (int)blockIdx.x >= P.cum[g + 1]) g++;
    const GDesc& D = P.d[g];
    int local = blockIdx.x - P.cum[g];
    int bxi = local % D.bx, byi = local / D.bx;
    gemm_core(D.Ah, D.Al, D.lda, D.Bh, D.Bl, D.ldb, D.C, D.Ch, D.Cl, D.ldc,
              D.M, D.N, D.K, D.aux0, nullptr, nullptr,
              byi * TBM, bxi * TBN, D.mode, D.out, 3);
}

// ---------------- attention K/V prep ----------------
// K concat layout per row (64): [Kh(0:20) | Kl(20:40) | Kh(40:60) | 0]
__global__ void attn_prep(const float* __restrict__ Cq3, const float* __restrict__ Hq3,
                          bf16* __restrict__ Kg,
                          bf16* __restrict__ VHg, bf16* __restrict__ VLg)
{
    const int n = blockIdx.x, b = blockIdx.y;
    const float* Hrow = Hq3 + (size_t)(b * NH_ + n) * 1200;
    const bf16 zb = __float2bfloat16_rn(0.f);

    // K: 20 heads x 10 rows x 64 dims
    for (int idx = threadIdx.x; idx < 20 * 10 * 64; idx += 256) {
        int h = idx / 640, rem = idx % 640, mm = rem >> 6, d = rem & 63;
        int m = b * 10 + mm;
        bf16 outv = zb;
        if (d < 60) {
            int dd = (d < 20) ? d : ((d < 40) ? d - 20 : d - 40);
            float kv = Cq3[m * 1200 + 400 + h * 20 + dd] + Hrow[400 + h * 20 + dd];
            bf16 hh = __float2bfloat16_rn(kv);
            outv = (d >= 20 && d < 40)
                 ? __float2bfloat16_rn(kv - __bfloat162float(hh)) : hh;
        }
        Kg[((size_t)(n * 20 + h) * 640 + m) * 64 + d] = outv;
    }
    // V: split hi/lo, [n][h][d][m]
    for (int idx = threadIdx.x; idx < 4000; idx += 256) {
        int h = idx / 200, d = (idx / 10) % 20, mm = idx % 10;
        int m = b * 10 + mm;
        float vv = Cq3[m * 1200 + 800 + h * 20 + d] + Hrow[800 + h * 20 + d];
        bf16 hh = __float2bfloat16_rn(vv);
        size_t o = ((size_t)(n * 20 + h) * 20 + d) * 640 + m;
        VHg[o] = hh;
        VLg[o] = __float2bfloat16_rn(vv - __bfloat162float(hh));
    }
}

// ---------------- tensor-core flash attention (concat-split S, cp.async pipelined) ----------------
__global__ __launch_bounds__(256, 2) void attn_mma(
    const float* __restrict__ Cq3, const float* __restrict__ Hq3,
    const bf16* __restrict__ Kg,
    const bf16* __restrict__ VHg, const bf16* __restrict__ VLg,
    bf16* __restrict__ Xoh, bf16* __restrict__ Xol)
{
    __shared__ __align__(16) bf16 sm[14336];   // 28KB

    const int qt = blockIdx.x, n = blockIdx.y, h = blockIdx.z;
    const int tid = threadIdx.x, w = tid >> 5, lane = tid & 31;
    const float scale = 0.22360679774997896f;  // 1/sqrt(20)
    const bf16 zb = __float2bfloat16_rn(0.f);

    const bf16* Kb  = Kg  + (size_t)(n * 20 + h) * 640 * 64;
    const bf16* Vbh = VHg + (size_t)(n * 20 + h) * 20 * 640;
    const bf16* Vbl = VLg + (size_t)(n * 20 + h) * 20 * 640;

    const uint32_t smb = s2u(sm);

    for (int idx = tid; idx < 128 * 64; idx += 256) {
        int r = idx >> 6, d = idx & 63;
        bf16 outv = zb;
        if (d < 60) {
            int dd = (d < 20) ? d : ((d < 40) ? d - 20 : d - 40);
            int l = qt * 128 + r;
            int qr = (l / NC_) * NH_ + n;
            float qv = (Cq3[l * 1200 + h * 20 + dd] + Hq3[qr * 1200 + h * 20 + dd]) * scale;
            bf16 hh = __float2bfloat16_rn(qv);
            outv = (d < 40) ? hh : __float2bfloat16_rn(qv - __bfloat162float(hh));
        }
        int e = ((d >> 3) ^ (r & 7)) * 8 + (d & 7);
        sm[r * 64 + e] = outv;
    }
    __syncthreads();

    const int mrow = ((lane >> 3) & 1) * 8 + (lane & 7);
    const uint32_t lk16 = (uint32_t)((lane >> 4) << 4);

    uint32_t qf[4][4];
    #pragma unroll
    for (int kc = 0; kc < 4; kc++) {
        int row = w * 16 + mrow;
        uint32_t cb = (uint32_t)(kc * 32) + lk16;
        ldm4(qf[kc][0], qf[kc][1], qf[kc][2], qf[kc][3],
             smb + row * 128 + (cb ^ (uint32_t)((row & 7) << 4)));
    }
    __syncthreads();

    auto copy_tile = [&](int kt2, int bufi) {
        const uint32_t kdst = smb + bufi * 8192;
        #pragma unroll
        for (int ii = 0; ii < 2; ii++) {
            int i = tid + ii * 256;
            int kk = i >> 3, seg = i & 7;
            cpa16(kdst + kk * 128 + (uint32_t)((seg * 16) ^ ((kk & 7) << 4)),
                  Kb + (size_t)(kt2 * 64 + kk) * 64 + seg * 8, 16);
        }
        if (tid < 160) {
            int d = tid >> 3, seg = tid & 7;
            uint32_t so = (uint32_t)((seg * 16) ^ ((d & 7) << 4));
            size_t gsrc = (size_t)d * 640 + kt2 * 64 + seg * 8;
            cpa16(smb + 16384 + bufi * 3072 + d * 128 + so, Vbh + gsrc, 16);
            cpa16(smb + 22528 + bufi * 3072 + d * 128 + so, Vbl + gsrc, 16);
        }
    };

    copy_tile(0, 0);
    CPA_COMMIT();

    float O0[3][4];
    #pragma unroll
    for (int f = 0; f < 3; f++)
        #pragma unroll
        for (int e = 0; e < 4; e++) O0[f][e] = 0.f;
    float zl = 0.f, zh2 = 0.f;

    for (int kt = 0; kt < 10; kt++) {
        const int bufi = kt & 1;
        CPA_WAIT0();
        __syncthreads();
        if (kt + 1 < 10) { copy_tile(kt + 1, bufi ^ 1); CPA_COMMIT(); }

        const uint32_t kbase = smb + bufi * 8192;
        union { float f[8][4]; uint32_t u[8][4]; } SP;
        #pragma unroll
        for (int f = 0; f < 8; f++)
            #pragma unroll
            for (int e = 0; e < 4; e++) SP.f[f][e] = 0.f;

        #pragma unroll
        for (int g = 0; g < 4; g++) {
            uint32_t kf[4][4];
            int row = g * 16 + mrow;
            #pragma unroll
            for (int kc = 0; kc < 4; kc++) {
                uint32_t cb = (uint32_t)(kc * 32) + lk16;
                ldm4(kf[kc][0], kf[kc][1], kf[kc][2], kf[kc][3],
                     kbase + row * 128 + (cb ^ (uint32_t)((row & 7) << 4)));
            }
            #pragma unroll
            for (int kc = 0; kc < 4; kc++) {
                mma16816(SP.f[2 * g + 0], qf[kc], kf[kc][0], kf[kc][2]);
                mma16816(SP.f[2 * g + 1], qf[kc], kf[kc][1], kf[kc][3]);
            }
        }

        #pragma unroll
        for (int f = 0; f < 8; f++) {
            float e0 = __expf(SP.f[f][0]), e1 = __expf(SP.f[f][1]);
            float e2 = __expf(SP.f[f][2]), e3 = __expf(SP.f[f][3]);
            zl += e0 + e1; zh2 += e2 + e3;
            bf16 h0 = __float2bfloat16_rn(e0), h1 = __float2bfloat16_rn(e1);
            bf16 h2 = __float2bfloat16_rn(e2), h3 = __float2bfloat16_rn(e3);
            uint32_t ph01 = pk2h(h0, h1), ph23 = pk2h(h2, h3);
            uint32_t pl01 = pkbf(e0 - __bfloat162float(h0), e1 - __bfloat162float(h1));
            uint32_t pl23 = pkbf(e2 - __bfloat162float(h2), e3 - __bfloat162float(h3));
            SP.u[f][0] = ph01; SP.u[f][1] = ph23; SP.u[f][2] = pl01; SP.u[f][3] = pl23;
        }

        const uint32_t vhbase = smb + 16384 + bufi * 3072;
        const uint32_t vlbase = smb + 22528 + bufi * 3072;
        #pragma unroll
        for (int kc2 = 0; kc2 < 4; kc2++) {
            uint32_t ah[4] = { SP.u[2 * kc2][0], SP.u[2 * kc2][1],
                               SP.u[2 * kc2 + 1][0], SP.u[2 * kc2 + 1][1] };
            uint32_t al[4] = { SP.u[2 * kc2][2], SP.u[2 * kc2][3],
                               SP.u[2 * kc2 + 1][2], SP.u[2 * kc2 + 1][3] };
            uint32_t vh4[4], vl4[4], vh2[2], vl2[2];
            uint32_t cb4 = (uint32_t)(kc2 * 32) + lk16;
            uint32_t a4 = mrow * 128 + (cb4 ^ (uint32_t)((mrow & 7) << 4));
            int d2 = 16 + (lane & 7);
            uint32_t cb2 = (uint32_t)(kc2 * 32) + (uint32_t)(((lane >> 3) & 1) << 4);
            uint32_t a2 = d2 * 128 + (cb2 ^ (uint32_t)((d2 & 7) << 4));
            ldm4(vh4[0], vh4[1], vh4[2], vh4[3], vhbase + a4);
            ldm4(vl4[0], vl4[1], vl4[2], vl4[3], vlbase + a4);
            ldm2(vh2[0], vh2[1], vhbase + a2);
            ldm2(vl2[0], vl2[1], vlbase + a2);
            mma16816(O0[0], ah, vh4[0], vh4[2]);
            mma16816(O0[0], ah, vl4[0], vl4[2]);
            mma16816(O0[0], al, vh4[0], vh4[2]);
            mma16816(O0[1], ah, vh4[1], vh4[3]);
            mma16816(O0[1], ah, vl4[1], vl4[3]);
            mma16816(O0[1], al, vh4[1], vh4[3]);
            mma16816(O0[2], ah, vh2[0], vh2[1]);
            mma16816(O0[2], ah, vl2[0], vl2[1]);
            mma16816(O0[2], al, vh2[0], vh2[1]);
        }
    }

    zl  += __shfl_xor_sync(0xffffffffu, zl, 1);
    zl  += __shfl_xor_sync(0xffffffffu, zl, 2);
    zh2 += __shfl_xor_sync(0xffffffffu, zh2, 1);
    zh2 += __shfl_xor_sync(0xffffffffu, zh2, 2);
    float izl = 1.f / zl, izh = 1.f / zh2;

    const int rowq = lane >> 2;
    #pragma unroll
    for (int f = 0; f < 3; f++) {
        int d0 = f * 8 + (lane & 3) * 2;
        if (d0 >= 20) continue;
        #pragma unroll
        for (int half = 0; half < 2; half++) {
            int lq = qt * 128 + w * 16 + rowq + half * 8;
            float v0 = O0[f][half * 2]     * (half ? izh : izl);
            float v1 = O0[f][half * 2 + 1] * (half ? izh : izl);
            size_t o = (size_t)(lq * NH_ + n) * 400 + h * 20 + d0;
            bf16 h0 = __float2bfloat16_rn(v0), h1 = __float2bfloat16_rn(v1);
            *reinterpret_cast<uint32_t*>(&Xoh[o]) = pk2h(h0, h1);
            *reinterpret_cast<uint32_t*>(&Xol[o]) =
                pkbf(v0 - __bfloat162float(h0), v1 - __bfloat162float(h1));
        }
    }
}

// ---------------- score + softmax ----------------
__global__ void score_kernel(const float* __restrict__ a2, const float* __restrict__ Wa3,
                             const float* __restrict__ ba3, float* __restrict__ s)
{
    int row = blockIdx.x * 8 + threadIdx.y;
    if (row >= MM) return;
    int lane = threadIdx.x;
    float acc = 0.f;
    for (int d = lane; d < 200; d += 32) acc += a2[(size_t)row * 200 + d] * Wa3[d];
    #pragma unroll
    for (int o = 16; o > 0; o >>= 1) acc += __shfl_xor_sync(0xffffffffu, acc, o);
    if (lane == 0) s[row] = acc + ba3[0];
}

// softmax over j + weighted sum; hall reconstructed from bf16 split (hi+lo)
__global__ void softmax_u_kernel(const float* __restrict__ s,
                                 const bf16* __restrict__ hallh,
                                 const bf16* __restrict__ halll,
                                 float* __restrict__ u)
{
    __shared__ float a[NH_];
    int bi = blockIdx.x;
    if (threadIdx.x == 0) {
        float mx = -1e30f;
        for (int j = 0; j < NH_; j++) mx = fmaxf(mx, s[bi * NH_ + j]);
        float Z = 0.f;
        for (int j = 0; j < NH_; j++) { float e = __expf(s[bi * NH_ + j] - mx); a[j] = e; Z += e; }
        float iz = 1.f / Z;
        for (int j = 0; j < NH_; j++) a[j] *= iz;
    }
    __syncthreads();
    for (int d = threadIdx.x; d < 400; d += blockDim.x) {
        float acc = 0.f;
        for (int j = 0; j < NH_; j++) {
            size_t o = ((size_t)bi * NH_ + j) * 400 + d;
            acc += a[j] * (__bfloat162float(hallh[o]) + __bfloat162float(halll[o]));
        }
        u[(size_t)bi * 400 + d] = acc;
    }
}

// ---------------- launch ----------------
static inline dim3 mgrid(int M, int N) { return dim3((N + TBN - 1) / TBN, (M + TBM - 1) / TBM); }

extern "C" void kernel_launch(void* const* d_in, const int* in_sizes, int n_in,
                              void* d_out, int out_size)
{
    const float* h    = (const float*)d_in[0];
    const float* c    = (const float*)d_in[2];
    const float* W1   = (const float*)d_in[4];
    const float* b1   = (const float*)d_in[5];
    const float* W2   = (const float*)d_in[6];
    const float* b2   = (const float*)d_in[7];
    const float* W3   = (const float*)d_in[8];
    const float* b3   = (const float*)d_in[9];
    const float* Wa1  = (const float*)d_in[10];
    const float* ba1  = (const float*)d_in[11];
    const float* Wa2  = (const float*)d_in[12];
    const float* ba2  = (const float*)d_in[13];
    const float* Wa3  = (const float*)d_in[14];
    const float* ba3  = (const float*)d_in[15];
    const float* Wqkv = (const float*)d_in[16];
    const float* bqkv = (const float*)d_in[17];
    const float* Wo   = (const float*)d_in[18];
    const float* bo   = (const float*)d_in[19];
    float* u = (float*)d_out;

    float *Hq3, *Cq3, *T1, *T2, *tc, *CA, *a2, *sc;
    cudaGetSymbolAddress((void**)&Hq3,  g_Hq3);
    cudaGetSymbolAddress((void**)&Cq3,  g_Cq3);
    cudaGetSymbolAddress((void**)&T1,   g_T1);
    cudaGetSymbolAddress((void**)&T2,   g_T2);
    cudaGetSymbolAddress((void**)&tc,   g_tc);
    cudaGetSymbolAddress((void**)&CA,   g_CA);
    cudaGetSymbolAddress((void**)&a2,   g_a2);
    cudaGetSymbolAddress((void**)&sc,   g_s);

    bf16 *bHcat_h, *bHcat_l, *bh_h, *bh_l, *bHs_h, *bHs_l, *bHp1_h, *bHp1_l;
    bf16 *bc_h, *bc_l, *bCc_h, *bCc_l, *bCs_h, *bCs_l;
    bf16 *bXo_h, *bXo_l, *bhall_h, *bhall_l, *ba1_h, *ba1_l;
    bf16 *bW1_h, *bW1_l, *bW2_h, *bW2_l, *bWqkv_h, *bWqkv_l, *bW3_h, *bW3_l;
    bf16 *bWa1_h, *bWa1_l, *bWa2_h, *bWa2_l, *bWoT_h, *bWoT_l, *bWm_h, *bWm_l;
    bf16 *Kg, *VHg, *VLg;
    cudaGetSymbolAddress((void**)&bHcat_h, g_bHcat_h);  cudaGetSymbolAddress((void**)&bHcat_l, g_bHcat_l);
    cudaGetSymbolAddress((void**)&bh_h,    g_bh_h);     cudaGetSymbolAddress((void**)&bh_l,    g_bh_l);
    cudaGetSymbolAddress((void**)&bHs_h,   g_bHs_h);    cudaGetSymbolAddress((void**)&bHs_l,   g_bHs_l);
    cudaGetSymbolAddress((void**)&bHp1_h,  g_bHp1_h);   cudaGetSymbolAddress((void**)&bHp1_l,  g_bHp1_l);
    cudaGetSymbolAddress((void**)&bc_h,    g_bc_h);     cudaGetSymbolAddress((void**)&bc_l,    g_bc_l);
    cudaGetSymbolAddress((void**)&bCc_h,   g_bCc_h);    cudaGetSymbolAddress((void**)&bCc_l,   g_bCc_l);
    cudaGetSymbolAddress((void**)&bCs_h,   g_bCs_h);    cudaGetSymbolAddress((void**)&bCs_l,   g_bCs_l);
    cudaGetSymbolAddress((void**)&bXo_h,   g_bXo_h);    cudaGetSymbolAddress((void**)&bXo_l,   g_bXo_l);
    cudaGetSymbolAddress((void**)&bhall_h, g_bhall_h);  cudaGetSymbolAddress((void**)&bhall_l, g_bhall_l);
    cudaGetSymbolAddress((void**)&ba1_h,   g_ba1_h);    cudaGetSymbolAddress((void**)&ba1_l,   g_ba1_l);
    cudaGetSymbolAddress((void**)&bW1_h,   g_bW1_h);    cudaGetSymbolAddress((void**)&bW1_l,   g_bW1_l);
    cudaGetSymbolAddress((void**)&bW2_h,   g_bW2_h);    cudaGetSymbolAddress((void**)&bW2_l,   g_bW2_l);
    cudaGetSymbolAddress((void**)&bWqkv_h, g_bWqkv_h);  cudaGetSymbolAddress((void**)&bWqkv_l, g_bWqkv_l);
    cudaGetSymbolAddress((void**)&bW3_h,   g_bW3_h);    cudaGetSymbolAddress((void**)&bW3_l,   g_bW3_l);
    cudaGetSymbolAddress((void**)&bWa1_h,  g_bWa1_h);   cudaGetSymbolAddress((void**)&bWa1_l,  g_bWa1_l);
    cudaGetSymbolAddress((void**)&bWa2_h,  g_bWa2_h);   cudaGetSymbolAddress((void**)&bWa2_l,  g_bWa2_l);
    cudaGetSymbolAddress((void**)&bWoT_h,  g_bWoT_h);   cudaGetSymbolAddress((void**)&bWoT_l,  g_bWoT_l);
    cudaGetSymbolAddress((void**)&bWm_h,   g_bWm_h);    cudaGetSymbolAddress((void**)&bWm_l,   g_bWm_l);
    cudaGetSymbolAddress((void**)&Kg,  g_Kg);
    cudaGetSymbolAddress((void**)&VHg, g_VHg);  cudaGetSymbolAddress((void**)&VLg, g_VLg);

    // (1) merged conversions
    ConvParams CP;
    const float* srcs[8] = { h, c, W1, W2, Wqkv, W3, Wa1, Wa2 };
    bf16* his[8] = { bh_h, bc_h, bW1_h, bW2_h, bWqkv_h, bW3_h, bWa1_h, bWa2_h };
    bf16* los[8] = { bh_l, bc_l, bW1_l, bW2_l, bWqkv_l, bW3_l, bWa1_l, bWa2_l };
    int ns[8] = { BNH * 400, LL * 400, 400 * 1600, 400 * 800, 1200 * 400,
                  400 * 800, 400 * 800, 200 * 400 };
    int cum = 0;
    for (int i = 0; i < 8; i++) { CP.src[i] = srcs[i]; CP.hi[i] = his[i]; CP.lo[i] = los[i];
                                  CP.cum[i] = cum; cum += ns[i]; }
    CP.cum[8] = cum;
    conv_all_kernel<<<(cum + 255) / 256, 256>>>(CP);

    // (2) Hcat gather + Wo transpose-split
    prep2_kernel<<<HC_BLOCKS + TR_BLOCKS, 256>>>(bh_h, bh_l, bHcat_h, bHcat_l,
                                                 Wo, bWoT_h, bWoT_l);

    // (3) grouped GEMM launch 1
    {
        GParams G; int cumb = 0; int gi = 0;
        auto add = [&](const bf16* Ah, const bf16* Al, int lda,
                       const bf16* Bh, const bf16* Bl, int ldb,
                       float* C, bf16* Ch, bf16* Cl, int ldc,
                       int M, int N, int K, int mode, int out, const float* aux0) {
            GDesc& D = G.d[gi];
            D.Ah = Ah; D.Al = Al; D.Bh = Bh; D.Bl = Bl;
            D.C = C; D.Ch = Ch; D.Cl = Cl; D.aux0 = aux0;
            D.lda = lda; D.ldb = ldb; D.ldc = ldc; D.M = M; D.N = N; D.K = K;
            D.mode = mode; D.out = out;
            D.bx = (N + TBN - 1) / TBN;
            int by = (M + TBM - 1) / TBM;
            G.cum[gi] = cumb; cumb += D.bx * by; gi++;
        };
        add(bHcat_h, bHcat_l, 1200, bW1_h, bW1_l, 1600, nullptr, bHp1_h, bHp1_l, 400,
            BNH, 400, 1200, 0, 2, nullptr);                                   // Hp1
        add(bh_h, bh_l, 400, bW2_h + 400, bW2_l + 400, 800, nullptr, bHs_h, bHs_l, 400,
            BNH, 400, 400, 0, 2, nullptr);                                    // Hs
        add(bc_h, bc_l, 400, bW1_h + 1200, bW1_l + 1200, 1600, nullptr, bCc_h, bCc_l, 400,
            LL, 400, 400, 0, 2, nullptr);                                     // Cc
        add(bc_h, bc_l, 400, bW2_h, bW2_l, 800, nullptr, bCs_h, bCs_l, 400,
            LL, 400, 400, 1, 2, b2);                                          // Cs
        add(bc_h, bc_l, 400, bWa1_h + 400, bWa1_l + 400, 800, CA, nullptr, nullptr, 400,
            LL, 400, 400, 1, 1, ba1);                                         // CA
        add(bW3_h + 400, bW3_l + 400, 800, bWoT_h, bWoT_l, 400, nullptr, bWm_h, bWm_l, 400,
            400, 400, 400, 0, 2, nullptr);                                    // Wm
        G.cum[gi] = cumb; G.nd = gi;
        gemm_group<<<cumb, 256>>>(G);
    }

    // (4) grouped GEMM launch 2
    {
        GParams G; int cumb = 0; int gi = 0;
        auto add = [&](const bf16* Ah, const bf16* Al, int lda,
                       const bf16* Bh, const bf16* Bl, int ldb,
                       float* C, int ldc, int M, int N, int K, int mode, const float* aux0) {
            GDesc& D = G.d[gi];
            D.Ah = Ah; D.Al = Al; D.Bh = Bh; D.Bl = Bl;
            D.C = C; D.Ch = nullptr; D.Cl = nullptr; D.aux0 = aux0;
            D.lda = lda; D.ldb = ldb; D.ldc = ldc; D.M = M; D.N = N; D.K = K;
            D.mode = mode; D.out = 1;
            D.bx = (N + TBN - 1) / TBN;
            int by = (M + TBM - 1) / TBM;
            G.cum[gi] = cumb; cumb += D.bx * by; gi++;
        };
        add(bHp1_h, bHp1_l, 400, bW3_h, bW3_l, 800, T1, 400, BNH, 400, 400, 0, nullptr);      // T1
        add(bHs_h, bHs_l, 400, bWqkv_h, bWqkv_l, 400, Hq3, 1200, BNH, 1200, 400, 0, nullptr); // Hq3
        add(bCs_h, bCs_l, 400, bWqkv_h, bWqkv_l, 400, Cq3, 1200, LL, 1200, 400, 1, bqkv);     // Cq3
        add(bCc_h, bCc_l, 400, bW3_h, bW3_l, 800, T2, 400, LL, 400, 400, 0, nullptr);         // T2
        G.cum[gi] = cumb; G.nd = gi;
        gemm_group<<<cumb, 256>>>(G);
    }

    // (5) attention K/V prep
    attn_prep<<<dim3(NH_, BB), 256>>>(Cq3, Hq3, Kg, VHg, VLg);

    // (6) tensor-core flash attention
    attn_mma<<<dim3(5, NH_, NHEAD), 256>>>(Cq3, Hq3, Kg, VHg, VLg, bXo_h, bXo_l);

    // (7) tc
    tc_kernel<<<50, 256>>>(b1, bo, b3, W3, tc);

    // (8-10) big GEMMs
    // hall = Xo @ Wm^T + T1 + T2 + tc  (split only; softmax reconstructs)
    gemm_mma<3, 2, 3><<<mgrid(MM, 400), 256>>>(bXo_h, bXo_l, 400, bWm_h, bWm_l, 400,
        nullptr, bhall_h, bhall_l, 400, MM, 400, 400, T1, T2, tc);
    // a1 = tanh(hall @ Wa1a^T + CA)  -- scoring path, nsplit=2
    gemm_mma<4, 2, 2><<<mgrid(MM, 400), 256>>>(bhall_h, bhall_l, 400, bWa1_h, bWa1_l, 800,
        nullptr, ba1_h, ba1_l, 400, MM, 400, 400, CA, nullptr, nullptr);
    // a2 = tanh(a1 @ Wa2^T + ba2)  -- scoring path, nsplit=2
    gemm_mma<2, 1, 2><<<mgrid(MM, 200), 256>>>(ba1_h, ba1_l, 400, bWa2_h, bWa2_l, 400,
        a2, nullptr, nullptr, 200, MM, 200, 400, ba2, nullptr, nullptr);

    // (11-12) scoring + softmax + weighted sum
    score_kernel<<<MM / 8, dim3(32, 8)>>>(a2, Wa3, ba3, sc);
    softmax_u_kernel<<<LL, 128>>>(sc, bhall_h, bhall_l, u);
}

// round 13
// speedup vs baseline: 1.7310x; 1.1303x over previous
#include <cuda_runtime.h>
#include <cuda_bf16.h>
#include <math.h>
#include <stdint.h>

// Problem constants
#define DD    400
#define BB    64
#define NC_   10
#define NH_   50
#define NHEAD 20
#define DH    20
#define LL    640      // BB*NC_
#define MM    32000    // BB*NC_*NH_
#define BNH   3200     // BB*NH_

typedef __nv_bfloat16 bf16;

// ---------------- fp32 device scratch ----------------
__device__ float g_Hq3 [BNH * 1200];
__device__ float g_Cq3 [LL * 1200];
__device__ float g_T1  [BNH * 400];
__device__ float g_T2  [LL * 400];
__device__ float g_tc  [400];
__device__ float g_CA  [LL * 400];
__device__ float g_spart[2 * MM];

// ---------------- bf16 split scratch (hi/lo pairs) ----------------
__device__ __align__(16) bf16 g_bHcat_h[BNH * 1200], g_bHcat_l[BNH * 1200];
__device__ __align__(16) bf16 g_bh_h  [BNH * 400],  g_bh_l  [BNH * 400];
__device__ __align__(16) bf16 g_bHs_h [BNH * 400],  g_bHs_l [BNH * 400];
__device__ __align__(16) bf16 g_bHp1_h[BNH * 400],  g_bHp1_l[BNH * 400];
__device__ __align__(16) bf16 g_bc_h  [LL * 400],   g_bc_l  [LL * 400];
__device__ __align__(16) bf16 g_bCc_h [LL * 400],   g_bCc_l [LL * 400];
__device__ __align__(16) bf16 g_bCs_h [LL * 400],   g_bCs_l [LL * 400];
__device__ __align__(16) bf16 g_bXo_h [MM * 400],   g_bXo_l [MM * 400];
__device__ __align__(16) bf16 g_bhall_h[MM * 400],  g_bhall_l[MM * 400];
__device__ __align__(16) bf16 g_ba1_h [MM * 400],   g_ba1_l [MM * 400];
__device__ __align__(16) bf16 g_bW1_h [400 * 1600], g_bW1_l [400 * 1600];
__device__ __align__(16) bf16 g_bW2_h [400 * 800],  g_bW2_l [400 * 800];
__device__ __align__(16) bf16 g_bWqkv_h[1200 * 400],g_bWqkv_l[1200 * 400];
__device__ __align__(16) bf16 g_bW3_h [400 * 800],  g_bW3_l [400 * 800];
__device__ __align__(16) bf16 g_bWa1_h[400 * 800],  g_bWa1_l[400 * 800];
__device__ __align__(16) bf16 g_bWa2_h[200 * 400],  g_bWa2_l[200 * 400];
__device__ __align__(16) bf16 g_bWoT_h[400 * 400],  g_bWoT_l[400 * 400];
__device__ __align__(16) bf16 g_bWm_h [400 * 400],  g_bWm_l [400 * 400];

// attention pre-split K/V
// K concat-split: [n][h][m(640)][64] = [Kh(20) | Kl(20) | Kh(20) | 0(4)]
// V: [n][h][d(20)][m(640)] hi/lo
__device__ __align__(16) bf16 g_Kg [50 * 20 * 640 * 64];
__device__ __align__(16) bf16 g_VHg[50 * 20 * 20 * 640], g_VLg[50 * 20 * 20 * 640];

// ---------------- helpers ----------------
__device__ __forceinline__ uint32_t s2u(const void* p) {
    return (uint32_t)__cvta_generic_to_shared(p);
}
__device__ __forceinline__ void ldm4(uint32_t& r0, uint32_t& r1, uint32_t& r2, uint32_t& r3,
                                     uint32_t addr) {
    asm volatile("ldmatrix.sync.aligned.m8n8.x4.shared.b16 {%0,%1,%2,%3}, [%4];"
                 : "=r"(r0), "=r"(r1), "=r"(r2), "=r"(r3) : "r"(addr));
}
__device__ __forceinline__ void ldm2(uint32_t& r0, uint32_t& r1, uint32_t addr) {
    asm volatile("ldmatrix.sync.aligned.m8n8.x2.shared.b16 {%0,%1}, [%2];"
                 : "=r"(r0), "=r"(r1) : "r"(addr));
}
__device__ __forceinline__ void mma16816(float* d, const uint32_t* a, uint32_t b0, uint32_t b1) {
    asm volatile("mma.sync.aligned.m16n8k16.row.col.f32.bf16.bf16.f32 "
                 "{%0,%1,%2,%3}, {%4,%5,%6,%7}, {%8,%9}, {%0,%1,%2,%3};"
                 : "+f"(d[0]), "+f"(d[1]), "+f"(d[2]), "+f"(d[3])
                 : "r"(a[0]), "r"(a[1]), "r"(a[2]), "r"(a[3]), "r"(b0), "r"(b1));
}
__device__ __forceinline__ uint32_t pkbf(float a, float b) {
    __nv_bfloat162 t = __floats2bfloat162_rn(a, b);
    return *reinterpret_cast<uint32_t*>(&t);
}
__device__ __forceinline__ uint32_t pk2h(bf16 a, bf16 b) {
    __nv_bfloat162 t; t.x = a; t.y = b;
    return *reinterpret_cast<uint32_t*>(&t);
}
// cp.async 16B with src-size (0 => zero-fill)
__device__ __forceinline__ void cpa16(uint32_t saddr, const void* gptr, uint32_t bytes) {
    asm volatile("cp.async.cg.shared.global [%0], [%1], 16, %2;"
                 :: "r"(saddr), "l"(gptr), "r"(bytes));
}
#define CPA_COMMIT() asm volatile("cp.async.commit_group;" ::: "memory")
#define CPA_WAIT0()  asm volatile("cp.async.wait_group 0;" ::: "memory")

// ---------------- merged convert: 8 segments in one launch ----------------
struct ConvParams {
    const float* src[8];
    bf16* hi[8];
    bf16* lo[8];
    int cum[9];
};
__global__ void conv_all_kernel(ConvParams P) {
    int i = blockIdx.x * blockDim.x + threadIdx.x;
    if (i >= P.cum[8]) return;
    int g = 0;
    #pragma unroll
    for (int s = 1; s < 8; s++) if (i >= P.cum[s]) g = s;
    int local = i - P.cum[g];
    float v = P.src[g][local];
    bf16 hh = __float2bfloat16_rn(v);
    P.hi[g][local] = hh;
    P.lo[g][local] = __float2bfloat16_rn(v - __bfloat162float(hh));
}

// ---------------- prep2: Hcat gather (bf16 pairs) + Wo transpose-split ----------------
#define HC_PAIRS (BNH * 600)
#define HC_BLOCKS ((HC_PAIRS + 255) / 256)
#define TR_BLOCKS ((400 * 400 + 255) / 256)
__global__ void prep2_kernel(const bf16* __restrict__ hh, const bf16* __restrict__ hl,
                             bf16* __restrict__ oh, bf16* __restrict__ ol,
                             const float* __restrict__ Wo,
                             bf16* __restrict__ th, bf16* __restrict__ tl) {
    if ((int)blockIdx.x < HC_BLOCKS) {
        int idx = blockIdx.x * blockDim.x + threadIdx.x;   // pairs
        if (idx >= HC_PAIRS) return;
        int row = idx / 600, pr = idx % 600;
        int col = pr * 2;
        int b = row / NH_, j = row % NH_;
        int part = col / 400, d = col % 400;
        int jj = (part == 0) ? (j + NH_ - 1) % NH_ : ((part == 1) ? j : (j + 1) % NH_);
        int s = (b * NH_ + jj) * 400 + d;
        reinterpret_cast<uint32_t*>(oh)[idx] = *reinterpret_cast<const uint32_t*>(&hh[s]);
        reinterpret_cast<uint32_t*>(ol)[idx] = *reinterpret_cast<const uint32_t*>(&hl[s]);
    } else {
        int idx = (blockIdx.x - HC_BLOCKS) * blockDim.x + threadIdx.x;
        if (idx >= 400 * 400) return;
        int n = idx / 400, k = idx % 400;
        float v = Wo[k * 400 + n];
        bf16 hv = __float2bfloat16_rn(v);
        th[idx] = hv;
        tl[idx] = __float2bfloat16_rn(v - __bfloat162float(hv));
    }
}

// ---------------- tc: warp-per-row reduction ----------------
__global__ void tc_kernel(const float* __restrict__ b1, const float* __restrict__ bo,
                          const float* __restrict__ b3, const float* __restrict__ W3,
                          float* __restrict__ tc) {
    int w = threadIdx.x >> 5, lane = threadIdx.x & 31;
    int r = blockIdx.x * 8 + w;
    if (r >= 400) return;
    const float* row = W3 + (size_t)r * 800;
    float acc = 0.f;
    for (int d = lane; d < 400; d += 32)
        acc += b1[d] * row[d] + bo[d] * row[400 + d];
    #pragma unroll
    for (int o = 16; o > 0; o >>= 1) acc += __shfl_xor_sync(0xffffffffu, acc, o);
    if (lane == 0) tc[r] = acc + b3[r];
}

// ---------------- shared tensor-core GEMM core (bf16 split, cp.async) ----------------
// nsplit==3: AhBh + AhBl + AlBh ; nsplit==2: (Ah+Al)·Bh (Bl never touched)
// mode 0: none | 1: +aux0[col] | 2: tanh(x+aux0[col]) | 3: +aux0/aux1/aux2 biases
// mode 4: tanh(x+aux0[(b,i)*N+col]) | 5: tanh(x+aux0[col]) then fused dot with aux1 -> C=spart
#define TBM 128
#define TBN 128
#define TBK 16
#define SSTR 24

__device__ __forceinline__ void gemm_core(
    const bf16* __restrict__ Ah, const bf16* __restrict__ Al, int lda,
    const bf16* __restrict__ Bh, const bf16* __restrict__ Bl, int ldb,
    float* __restrict__ C, bf16* __restrict__ Ch, bf16* __restrict__ Cl,
    int ldc, int M, int N, int K,
    const float* __restrict__ aux0, const float* __restrict__ aux1,
    const float* __restrict__ aux2,
    int row0, int col0, int mode, int out, int nsplit)
{
    __shared__ __align__(16) bf16 sAh[2][TBM * SSTR];
    __shared__ __align__(16) bf16 sAl[2][TBM * SSTR];
    __shared__ __align__(16) bf16 sBh[2][TBM * SSTR];
    __shared__ __align__(16) bf16 sBl[2][TBM * SSTR];

    const int tid = threadIdx.x;
    const int lrow = tid >> 1, lhalf = tid & 1;

    const bool aok = (row0 + lrow) < M;
    const bool bok = (col0 + lrow) < N;
    const uint32_t abytes = aok ? 16u : 0u;
    const uint32_t bbytes = bok ? 16u : 0u;
    const int arow = aok ? (row0 + lrow) : 0;
    const int brow = bok ? (col0 + lrow) : 0;
    const bf16* Aph = Ah + (size_t)arow * lda + lhalf * 8;
    const bf16* Apl = Al + (size_t)arow * lda + lhalf * 8;
    const bf16* Bph = Bh + (size_t)brow * ldb + lhalf * 8;
    const bf16* Bpl = Bl + (size_t)brow * ldb + lhalf * 8;
    const uint32_t sboff = (uint32_t)((lrow * SSTR + lhalf * 8) * 2);

    const int w = tid >> 5, lane = tid & 31;
    const int wm = w >> 2, wn = w & 3;
    const int mrow = ((lane >> 3) & 1) * 8 + (lane & 7);
    const int koff = (lane >> 4) * 8;

    uint32_t aoff[4], boff[2];
    #pragma unroll
    for (int fm = 0; fm < 4; fm++)
        aoff[fm] = (uint32_t)(((wm * 64 + fm * 16 + mrow) * SSTR + koff) * 2);
    #pragma unroll
    for (int f = 0; f < 2; f++)
        boff[f] = (uint32_t)(((wn * 32 + f * 16 + mrow) * SSTR + koff) * 2);

    const uint32_t bAh = s2u(sAh), bAl = s2u(sAl), bBh = s2u(sBh), bBl = s2u(sBl);
    const uint32_t STB = TBM * SSTR * 2;

    float acc[4][4][4];
    #pragma unroll
    for (int i = 0; i < 4; i++)
        #pragma unroll
        for (int j = 0; j < 4; j++)
            #pragma unroll
            for (int e = 0; e < 4; e++) acc[i][j][e] = 0.f;

    // stage-0 async copy
    {
        cpa16(bAh + sboff, Aph, abytes);
        cpa16(bAl + sboff, Apl, abytes);
        cpa16(bBh + sboff, Bph, bbytes);
        if (nsplit == 3) cpa16(bBl + sboff, Bpl, bbytes);
        CPA_COMMIT();
    }
    CPA_WAIT0();
    __syncthreads();

    const int nk = K / TBK;
    for (int t = 0; t < nk; t++) {
        const int st = t & 1;
        if (t + 1 < nk) {
            const int k = (t + 1) * TBK;
            const uint32_t nso = (uint32_t)(st ^ 1) * STB + sboff;
            cpa16(bAh + nso, Aph + k, abytes);
            cpa16(bAl + nso, Apl + k, abytes);
            cpa16(bBh + nso, Bph + k, bbytes);
            if (nsplit == 3) cpa16(bBl + nso, Bpl + k, bbytes);
            CPA_COMMIT();
        }

        uint32_t ah[4][4], al[4][4], bh[2][4], bl[2][4];
        #pragma unroll
        for (int fm = 0; fm < 4; fm++) {
            ldm4(ah[fm][0], ah[fm][1], ah[fm][2], ah[fm][3], bAh + st * STB + aoff[fm]);
            ldm4(al[fm][0], al[fm][1], al[fm][2], al[fm][3], bAl + st * STB + aoff[fm]);
        }
        #pragma unroll
        for (int f = 0; f < 2; f++) {
            ldm4(bh[f][0], bh[f][1], bh[f][2], bh[f][3], bBh + st * STB + boff[f]);
            if (nsplit == 3)
                ldm4(bl[f][0], bl[f][1], bl[f][2], bl[f][3], bBl + st * STB + boff[f]);
        }

        #pragma unroll
        for (int fm = 0; fm < 4; fm++) {
            #pragma unroll
            for (int f = 0; f < 2; f++) {
                mma16816(acc[fm][f * 2 + 0], ah[fm], bh[f][0], bh[f][2]);
                mma16816(acc[fm][f * 2 + 0], al[fm], bh[f][0], bh[f][2]);
                if (nsplit == 3)
                    mma16816(acc[fm][f * 2 + 0], ah[fm], bl[f][0], bl[f][2]);
                mma16816(acc[fm][f * 2 + 1], ah[fm], bh[f][1], bh[f][3]);
                mma16816(acc[fm][f * 2 + 1], al[fm], bh[f][1], bh[f][3]);
                if (nsplit == 3)
                    mma16816(acc[fm][f * 2 + 1], ah[fm], bl[f][1], bl[f][3]);
            }
        }

        if (t + 1 < nk) {
            CPA_WAIT0();
            __syncthreads();
        }
    }

    float sacc[4][2];
    #pragma unroll
    for (int i = 0; i < 4; i++) { sacc[i][0] = 0.f; sacc[i][1] = 0.f; }

    // epilogue (pairwise: cols cc, cc+1)
    #pragma unroll
    for (int fm = 0; fm < 4; fm++) {
        #pragma unroll
        for (int half = 0; half < 2; half++) {
            const int r = row0 + wm * 64 + fm * 16 + (lane >> 2) + half * 8;
            if (r >= M) continue;
            int bb = 0, ii = 0, jj = 0;
            if (mode == 3 || mode == 4) { bb = r / 500; ii = (r / 50) % 10; jj = r % 50; }
            #pragma unroll
            for (int fn = 0; fn < 4; fn++) {
                const int cc = col0 + wn * 32 + fn * 8 + (lane & 3) * 2;
                if (cc >= N) continue;
                float v0 = acc[fm][fn][half * 2], v1 = acc[fm][fn][half * 2 + 1];
                if (mode == 1) { v0 += aux0[cc]; v1 += aux0[cc + 1]; }
                if (mode == 2 || mode == 5) {
                    v0 = tanhf(v0 + aux0[cc]); v1 = tanhf(v1 + aux0[cc + 1]);
                }
                if (mode == 3) {
                    const float* p0 = aux0 + (size_t)(bb * 50 + jj) * N;
                    const float* p1 = aux1 + (size_t)(bb * 10 + ii) * N;
                    v0 += p0[cc] + p1[cc] + aux2[cc];
                    v1 += p0[cc + 1] + p1[cc + 1] + aux2[cc + 1];
                }
                if (mode == 4) {
                    const float* p0 = aux0 + (size_t)(bb * 10 + ii) * N;
                    v0 = tanhf(v0 + p0[cc]); v1 = tanhf(v1 + p0[cc + 1]);
                }
                if (mode == 5)
                    sacc[fm][half] += v0 * aux1[cc] + v1 * aux1[cc + 1];
                if (out & 1)
                    *reinterpret_cast<float2*>(&C[(size_t)r * ldc + cc]) = make_float2(v0, v1);
                if (out & 2) {
                    bf16 h0 = __float2bfloat16_rn(v0), h1 = __float2bfloat16_rn(v1);
                    *reinterpret_cast<uint32_t*>(&Ch[(size_t)r * ldc + cc]) = pk2h(h0, h1);
                    *reinterpret_cast<uint32_t*>(&Cl[(size_t)r * ldc + cc]) =
                        pkbf(v0 - __bfloat162float(h0), v1 - __bfloat162float(h1));
                }
            }
        }
    }

    // mode 5: deterministic cross-warp score reduction -> C[part*M + r]
    if (mode == 5) {
        __syncthreads();
        float* red = reinterpret_cast<float*>(sAh);
        #pragma unroll
        for (int fm = 0; fm < 4; fm++) {
            #pragma unroll
            for (int half = 0; half < 2; half++) {
                float v = sacc[fm][half];
                v += __shfl_xor_sync(0xffffffffu, v, 1);
                v += __shfl_xor_sync(0xffffffffu, v, 2);
                if ((lane & 3) == 0)
                    red[(wm * 64 + fm * 16 + (lane >> 2) + half * 8) * 4 + wn] = v;
            }
        }
        __syncthreads();
        if (tid < 128) {
            int r = row0 + tid;
            if (r < M)
                C[(size_t)(col0 >> 7) * M + r] =
                    red[tid * 4] + red[tid * 4 + 1] + red[tid * 4 + 2] + red[tid * 4 + 3];
        }
    }
}

// template wrapper (big GEMMs)
template <int MODE, int OUT, int NSPLIT>
__global__ __launch_bounds__(256, 2) void gemm_mma(
    const bf16* __restrict__ Ah, const bf16* __restrict__ Al, int lda,
    const bf16* __restrict__ Bh, const bf16* __restrict__ Bl, int ldb,
    float* __restrict__ C, bf16* __restrict__ Ch, bf16* __restrict__ Cl,
    int ldc, int M, int N, int K,
    const float* __restrict__ aux0, const float* __restrict__ aux1,
    const float* __restrict__ aux2)
{
    gemm_core(Ah, Al, lda, Bh, Bl, ldb, C, Ch, Cl, ldc, M, N, K,
              aux0, aux1, aux2, blockIdx.y * TBM, blockIdx.x * TBN, MODE, OUT, NSPLIT);
}

// grouped wrapper (small GEMMs, modes 0/1, always nsplit=3)
struct GDesc {
    const bf16 *Ah, *Al, *Bh, *Bl;
    float* C; bf16 *Ch; bf16 *Cl;
    const float* aux0;
    int lda, ldb, ldc, M, N, K, mode, out, bx;
};
struct GParams { GDesc d[6]; int cum[7]; int nd; };

__global__ __launch_bounds__(256, 2) void gemm_group(GParams P) {
    int g = 0;
    while (g + 1 < P.nd && (int)blockIdx.x >= P.cum[g + 1]) g++;
    const GDesc& D = P.d[g];
    int local = blockIdx.x - P.cum[g];
    int bxi = local % D.bx, byi = local / D.bx;
    gemm_core(D.Ah, D.Al, D.lda, D.Bh, D.Bl, D.ldb, D.C, D.Ch, D.Cl, D.ldc,
              D.M, D.N, D.K, D.aux0, nullptr, nullptr,
              byi * TBM, bxi * TBN, D.mode, D.out, 3);
}

// ---------------- attention K/V prep ----------------
// K concat layout per row (64): [Kh(0:20) | Kl(20:40) | Kh(40:60) | 0]
__global__ void attn_prep(const float* __restrict__ Cq3, const float* __restrict__ Hq3,
                          bf16* __restrict__ Kg,
                          bf16* __restrict__ VHg, bf16* __restrict__ VLg)
{
    const int n = blockIdx.x, b = blockIdx.y;
    const float* Hrow = Hq3 + (size_t)(b * NH_ + n) * 1200;
    const bf16 zb = __float2bfloat16_rn(0.f);

    for (int idx = threadIdx.x; idx < 20 * 10 * 64; idx += 256) {
        int h = idx / 640, rem = idx % 640, mm = rem >> 6, d = rem & 63;
        int m = b * 10 + mm;
        bf16 outv = zb;
        if (d < 60) {
            int dd = (d < 20) ? d : ((d < 40) ? d - 20 : d - 40);
            float kv = Cq3[m * 1200 + 400 + h * 20 + dd] + Hrow[400 + h * 20 + dd];
            bf16 hh = __float2bfloat16_rn(kv);
            outv = (d >= 20 && d < 40)
                 ? __float2bfloat16_rn(kv - __bfloat162float(hh)) : hh;
        }
        Kg[((size_t)(n * 20 + h) * 640 + m) * 64 + d] = outv;
    }
    for (int idx = threadIdx.x; idx < 4000; idx += 256) {
        int h = idx / 200, d = (idx / 10) % 20, mm = idx % 10;
        int m = b * 10 + mm;
        float vv = Cq3[m * 1200 + 800 + h * 20 + d] + Hrow[800 + h * 20 + d];
        bf16 hh = __float2bfloat16_rn(vv);
        size_t o = ((size_t)(n * 20 + h) * 20 + d) * 640 + m;
        VHg[o] = hh;
        VLg[o] = __float2bfloat16_rn(vv - __bfloat162float(hh));
    }
}

// ---------------- tensor-core flash attention ----------------
// S = Qh·(Kh+Kl) over concat cols 0..47 (Q cols 40-47 = 0); PV exact 3-term split.
__global__ __launch_bounds__(256, 2) void attn_mma(
    const float* __restrict__ Cq3, const float* __restrict__ Hq3,
    const bf16* __restrict__ Kg,
    const bf16* __restrict__ VHg, const bf16* __restrict__ VLg,
    bf16* __restrict__ Xoh, bf16* __restrict__ Xol)
{
    __shared__ __align__(16) bf16 sm[14336];   // 28KB

    const int qt = blockIdx.x, n = blockIdx.y, h = blockIdx.z;
    const int tid = threadIdx.x, w = tid >> 5, lane = tid & 31;
    const float scale = 0.22360679774997896f;  // 1/sqrt(20)
    const bf16 zb = __float2bfloat16_rn(0.f);

    const bf16* Kb  = Kg  + (size_t)(n * 20 + h) * 640 * 64;
    const bf16* Vbh = VHg + (size_t)(n * 20 + h) * 20 * 640;
    const bf16* Vbl = VLg + (size_t)(n * 20 + h) * 20 * 640;

    const uint32_t smb = s2u(sm);

    // build Q concat [128][64]: [Qh | Qh | 0 | 0] (cols 40+ zero)
    for (int idx = tid; idx < 128 * 64; idx += 256) {
        int r = idx >> 6, d = idx & 63;
        bf16 outv = zb;
        if (d < 40) {
            int dd = (d < 20) ? d : d - 20;
            int l = qt * 128 + r;
            int qr = (l / NC_) * NH_ + n;
            float qv = (Cq3[l * 1200 + h * 20 + dd] + Hq3[qr * 1200 + h * 20 + dd]) * scale;
            outv = __float2bfloat16_rn(qv);
        }
        int e = ((d >> 3) ^ (r & 7)) * 8 + (d & 7);
        sm[r * 64 + e] = outv;
    }
    __syncthreads();

    const int mrow = ((lane >> 3) & 1) * 8 + (lane & 7);
    const uint32_t lk16 = (uint32_t)((lane >> 4) << 4);

    uint32_t qf[3][4];
    #pragma unroll
    for (int kc = 0; kc < 3; kc++) {
        int row = w * 16 + mrow;
        uint32_t cb = (uint32_t)(kc * 32) + lk16;
        ldm4(qf[kc][0], qf[kc][1], qf[kc][2], qf[kc][3],
             smb + row * 128 + (cb ^ (uint32_t)((row & 7) << 4)));
    }
    __syncthreads();

    // tile copy: K segs 0-5 only (cols 0-47; chunk 3 never read), V hi/lo
    auto copy_tile = [&](int kt2, int bufi) {
        const uint32_t kdst = smb + bufi * 8192;
        #pragma unroll
        for (int ii = 0; ii < 2; ii++) {
            int i = tid + ii * 256;
            if (i < 384) {
                int kk = i / 6, seg = i % 6;
                cpa16(kdst + kk * 128 + (uint32_t)((seg * 16) ^ ((kk & 7) << 4)),
                      Kb + (size_t)(kt2 * 64 + kk) * 64 + seg * 8, 16);
            }
        }
        if (tid < 160) {
            int d = tid >> 3, seg = tid & 7;
            uint32_t so = (uint32_t)((seg * 16) ^ ((d & 7) << 4));
            size_t gsrc = (size_t)d * 640 + kt2 * 64 + seg * 8;
            cpa16(smb + 16384 + bufi * 3072 + d * 128 + so, Vbh + gsrc, 16);
            cpa16(smb + 22528 + bufi * 3072 + d * 128 + so, Vbl + gsrc, 16);
        }
    };

    copy_tile(0, 0);
    CPA_COMMIT();

    float O0[3][4];
    #pragma unroll
    for (int f = 0; f < 3; f++)
        #pragma unroll
        for (int e = 0; e < 4; e++) O0[f][e] = 0.f;
    float zl = 0.f, zh2 = 0.f;

    for (int kt = 0; kt < 10; kt++) {
        const int bufi = kt & 1;
        CPA_WAIT0();
        __syncthreads();
        if (kt + 1 < 10) { copy_tile(kt + 1, bufi ^ 1); CPA_COMMIT(); }

        const uint32_t kbase = smb + bufi * 8192;
        union { float f[8][4]; uint32_t u[8][4]; } SP;
        #pragma unroll
        for (int f = 0; f < 8; f++)
            #pragma unroll
            for (int e = 0; e < 4; e++) SP.f[f][e] = 0.f;

        #pragma unroll
        for (int g = 0; g < 4; g++) {
            uint32_t kf[3][4];
            int row = g * 16 + mrow;
            #pragma unroll
            for (int kc = 0; kc < 3; kc++) {
                uint32_t cb = (uint32_t)(kc * 32) + lk16;
                ldm4(kf[kc][0], kf[kc][1], kf[kc][2], kf[kc][3],
                     kbase + row * 128 + (cb ^ (uint32_t)((row & 7) << 4)));
            }
            #pragma unroll
            for (int kc = 0; kc < 3; kc++) {
                mma16816(SP.f[2 * g + 0], qf[kc], kf[kc][0], kf[kc][2]);
                mma16816(SP.f[2 * g + 1], qf[kc], kf[kc][1], kf[kc][3]);
            }
        }

        #pragma unroll
        for (int f = 0; f < 8; f++) {
            float e0 = __expf(SP.f[f][0]), e1 = __expf(SP.f[f][1]);
            float e2 = __expf(SP.f[f][2]), e3 = __expf(SP.f[f][3]);
            zl += e0 + e1; zh2 += e2 + e3;
            bf16 h0 = __float2bfloat16_rn(e0), h1 = __float2bfloat16_rn(e1);
            bf16 h2 = __float2bfloat16_rn(e2), h3 = __float2bfloat16_rn(e3);
            uint32_t ph01 = pk2h(h0, h1), ph23 = pk2h(h2, h3);
            uint32_t pl01 = pkbf(e0 - __bfloat162float(h0), e1 - __bfloat162float(h1));
            uint32_t pl23 = pkbf(e2 - __bfloat162float(h2), e3 - __bfloat162float(h3));
            SP.u[f][0] = ph01; SP.u[f][1] = ph23; SP.u[f][2] = pl01; SP.u[f][3] = pl23;
        }

        const uint32_t vhbase = smb + 16384 + bufi * 3072;
        const uint32_t vlbase = smb + 22528 + bufi * 3072;
        #pragma unroll
        for (int kc2 = 0; kc2 < 4; kc2++) {
            uint32_t ah[4] = { SP.u[2 * kc2][0], SP.u[2 * kc2][1],
                               SP.u[2 * kc2 + 1][0], SP.u[2 * kc2 + 1][1] };
            uint32_t al[4] = { SP.u[2 * kc2][2], SP.u[2 * kc2][3],
                               SP.u[2 * kc2 + 1][2], SP.u[2 * kc2 + 1][3] };
            uint32_t vh4[4], vl4[4], vh2[2], vl2[2];
            uint32_t cb4 = (uint32_t)(kc2 * 32) + lk16;
            uint32_t a4 = mrow * 128 + (cb4 ^ (uint32_t)((mrow & 7) << 4));
            int d2 = 16 + (lane & 7);
            uint32_t cb2 = (uint32_t)(kc2 * 32) + (uint32_t)(((lane >> 3) & 1) << 4);
            uint32_t a2 = d2 * 128 + (cb2 ^ (uint32_t)((d2 & 7) << 4));
            ldm4(vh4[0], vh4[1], vh4[2], vh4[3], vhbase + a4);
            ldm4(vl4[0], vl4[1], vl4[2], vl4[3], vlbase + a4);
            ldm2(vh2[0], vh2[1], vhbase + a2);
            ldm2(vl2[0], vl2[1], vlbase + a2);
            mma16816(O0[0], ah, vh4[0], vh4[2]);
            mma16816(O0[0], ah, vl4[0], vl4[2]);
            mma16816(O0[0], al, vh4[0], vh4[2]);
            mma16816(O0[1], ah, vh4[1], vh4[3]);
            mma16816(O0[1], ah, vl4[1], vl4[3]);
            mma16816(O0[1], al, vh4[1], vh4[3]);
            mma16816(O0[2], ah, vh2[0], vh2[1]);
            mma16816(O0[2], ah, vl2[0], vl2[1]);
            mma16816(O0[2], al, vh2[0], vh2[1]);
        }
    }

    zl  += __shfl_xor_sync(0xffffffffu, zl, 1);
    zl  += __shfl_xor_sync(0xffffffffu, zl, 2);
    zh2 += __shfl_xor_sync(0xffffffffu, zh2, 1);
    zh2 += __shfl_xor_sync(0xffffffffu, zh2, 2);
    float izl = 1.f / zl, izh = 1.f / zh2;

    const int rowq = lane >> 2;
    #pragma unroll
    for (int f = 0; f < 3; f++) {
        int d0 = f * 8 + (lane & 3) * 2;
        if (d0 >= 20) continue;
        #pragma unroll
        for (int half = 0; half < 2; half++) {
            int lq = qt * 128 + w * 16 + rowq + half * 8;
            float v0 = O0[f][half * 2]     * (half ? izh : izl);
            float v1 = O0[f][half * 2 + 1] * (half ? izh : izl);
            size_t o = (size_t)(lq * NH_ + n) * 400 + h * 20 + d0;
            bf16 h0 = __float2bfloat16_rn(v0), h1 = __float2bfloat16_rn(v1);
            *reinterpret_cast<uint32_t*>(&Xoh[o]) = pk2h(h0, h1);
            *reinterpret_cast<uint32_t*>(&Xol[o]) =
                pkbf(v0 - __bfloat162float(h0), v1 - __bfloat162float(h1));
        }
    }
}

// ---------------- softmax over j + weighted sum (hall from split; s from 2 parts) ----------------
__global__ void softmax_u_kernel(const float* __restrict__ spart,
                                 const bf16* __restrict__ hallh,
                                 const bf16* __restrict__ halll,
                                 float* __restrict__ u)
{
    __shared__ float a[NH_];
    int bi = blockIdx.x;
    if (threadIdx.x == 0) {
        float sv[NH_];
        float mx = -1e30f;
        for (int j = 0; j < NH_; j++) {
            int r = bi * NH_ + j;
            sv[j] = spart[r] + spart[MM + r];
            mx = fmaxf(mx, sv[j]);
        }
        float Z = 0.f;
        for (int j = 0; j < NH_; j++) { float e = __expf(sv[j] - mx); a[j] = e; Z += e; }
        float iz = 1.f / Z;
        for (int j = 0; j < NH_; j++) a[j] *= iz;
    }
    __syncthreads();
    for (int d = threadIdx.x; d < 400; d += blockDim.x) {
        float acc = 0.f;
        for (int j = 0; j < NH_; j++) {
            size_t o = ((size_t)bi * NH_ + j) * 400 + d;
            acc += a[j] * (__bfloat162float(hallh[o]) + __bfloat162float(halll[o]));
        }
        u[(size_t)bi * 400 + d] = acc;
    }
}

// ---------------- launch ----------------
static inline dim3 mgrid(int M, int N) { return dim3((N + TBN - 1) / TBN, (M + TBM - 1) / TBM); }

extern "C" void kernel_launch(void* const* d_in, const int* in_sizes, int n_in,
                              void* d_out, int out_size)
{
    const float* h    = (const float*)d_in[0];
    const float* c    = (const float*)d_in[2];
    const float* W1   = (const float*)d_in[4];
    const float* b1   = (const float*)d_in[5];
    const float* W2   = (const float*)d_in[6];
    const float* b2   = (const float*)d_in[7];
    const float* W3   = (const float*)d_in[8];
    const float* b3   = (const float*)d_in[9];
    const float* Wa1  = (const float*)d_in[10];
    const float* ba1  = (const float*)d_in[11];
    const float* Wa2  = (const float*)d_in[12];
    const float* ba2  = (const float*)d_in[13];
    const float* Wa3  = (const float*)d_in[14];
    const float* Wqkv = (const float*)d_in[16];
    const float* bqkv = (const float*)d_in[17];
    const float* Wo   = (const float*)d_in[18];
    const float* bo   = (const float*)d_in[19];
    float* u = (float*)d_out;

    float *Hq3, *Cq3, *T1, *T2, *tc, *CA, *spart;
    cudaGetSymbolAddress((void**)&Hq3,  g_Hq3);
    cudaGetSymbolAddress((void**)&Cq3,  g_Cq3);
    cudaGetSymbolAddress((void**)&T1,   g_T1);
    cudaGetSymbolAddress((void**)&T2,   g_T2);
    cudaGetSymbolAddress((void**)&tc,   g_tc);
    cudaGetSymbolAddress((void**)&CA,   g_CA);
    cudaGetSymbolAddress((void**)&spart, g_spart);

    bf16 *bHcat_h, *bHcat_l, *bh_h, *bh_l, *bHs_h, *bHs_l, *bHp1_h, *bHp1_l;
    bf16 *bc_h, *bc_l, *bCc_h, *bCc_l, *bCs_h, *bCs_l;
    bf16 *bXo_h, *bXo_l, *bhall_h, *bhall_l, *ba1_h, *ba1_l;
    bf16 *bW1_h, *bW1_l, *bW2_h, *bW2_l, *bWqkv_h, *bWqkv_l, *bW3_h, *bW3_l;
    bf16 *bWa1_h, *bWa1_l, *bWa2_h, *bWa2_l, *bWoT_h, *bWoT_l, *bWm_h, *bWm_l;
    bf16 *Kg, *VHg, *VLg;
    cudaGetSymbolAddress((void**)&bHcat_h, g_bHcat_h);  cudaGetSymbolAddress((void**)&bHcat_l, g_bHcat_l);
    cudaGetSymbolAddress((void**)&bh_h,    g_bh_h);     cudaGetSymbolAddress((void**)&bh_l,    g_bh_l);
    cudaGetSymbolAddress((void**)&bHs_h,   g_bHs_h);    cudaGetSymbolAddress((void**)&bHs_l,   g_bHs_l);
    cudaGetSymbolAddress((void**)&bHp1_h,  g_bHp1_h);   cudaGetSymbolAddress((void**)&bHp1_l,  g_bHp1_l);
    cudaGetSymbolAddress((void**)&bc_h,    g_bc_h);     cudaGetSymbolAddress((void**)&bc_l,    g_bc_l);
    cudaGetSymbolAddress((void**)&bCc_h,   g_bCc_h);    cudaGetSymbolAddress((void**)&bCc_l,   g_bCc_l);
    cudaGetSymbolAddress((void**)&bCs_h,   g_bCs_h);    cudaGetSymbolAddress((void**)&bCs_l,   g_bCs_l);
    cudaGetSymbolAddress((void**)&bXo_h,   g_bXo_h);    cudaGetSymbolAddress((void**)&bXo_l,   g_bXo_l);
    cudaGetSymbolAddress((void**)&bhall_h, g_bhall_h);  cudaGetSymbolAddress((void**)&bhall_l, g_bhall_l);
    cudaGetSymbolAddress((void**)&ba1_h,   g_ba1_h);    cudaGetSymbolAddress((void**)&ba1_l,   g_ba1_l);
    cudaGetSymbolAddress((void**)&bW1_h,   g_bW1_h);    cudaGetSymbolAddress((void**)&bW1_l,   g_bW1_l);
    cudaGetSymbolAddress((void**)&bW2_h,   g_bW2_h);    cudaGetSymbolAddress((void**)&bW2_l,   g_bW2_l);
    cudaGetSymbolAddress((void**)&bWqkv_h, g_bWqkv_h);  cudaGetSymbolAddress((void**)&bWqkv_l, g_bWqkv_l);
    cudaGetSymbolAddress((void**)&bW3_h,   g_bW3_h);    cudaGetSymbolAddress((void**)&bW3_l,   g_bW3_l);
    cudaGetSymbolAddress((void**)&bWa1_h,  g_bWa1_h);   cudaGetSymbolAddress((void**)&bWa1_l,  g_bWa1_l);
    cudaGetSymbolAddress((void**)&bWa2_h,  g_bWa2_h);   cudaGetSymbolAddress((void**)&bWa2_l,  g_bWa2_l);
    cudaGetSymbolAddress((void**)&bWoT_h,  g_bWoT_h);   cudaGetSymbolAddress((void**)&bWoT_l,  g_bWoT_l);
    cudaGetSymbolAddress((void**)&bWm_h,   g_bWm_h);    cudaGetSymbolAddress((void**)&bWm_l,   g_bWm_l);
    cudaGetSymbolAddress((void**)&Kg,  g_Kg);
    cudaGetSymbolAddress((void**)&VHg, g_VHg);  cudaGetSymbolAddress((void**)&VLg, g_VLg);

    // (1) merged conversions
    ConvParams CP;
    const float* srcs[8] = { h, c, W1, W2, Wqkv, W3, Wa1, Wa2 };
    bf16* his[8] = { bh_h, bc_h, bW1_h, bW2_h, bWqkv_h, bW3_h, bWa1_h, bWa2_h };
    bf16* los[8] = { bh_l, bc_l, bW1_l, bW2_l, bWqkv_l, bW3_l, bWa1_l, bWa2_l };
    int ns[8] = { BNH * 400, LL * 400, 400 * 1600, 400 * 800, 1200 * 400,
                  400 * 800, 400 * 800, 200 * 400 };
    int cum = 0;
    for (int i = 0; i < 8; i++) { CP.src[i] = srcs[i]; CP.hi[i] = his[i]; CP.lo[i] = los[i];
                                  CP.cum[i] = cum; cum += ns[i]; }
    CP.cum[8] = cum;
    conv_all_kernel<<<(cum + 255) / 256, 256>>>(CP);

    // (2) Hcat gather + Wo transpose-split
    prep2_kernel<<<HC_BLOCKS + TR_BLOCKS, 256>>>(bh_h, bh_l, bHcat_h, bHcat_l,
                                                 Wo, bWoT_h, bWoT_l);

    // (3) grouped GEMM launch 1
    {
        GParams G; int cumb = 0; int gi = 0;
        auto add = [&](const bf16* Ah, const bf16* Al, int lda,
                       const bf16* Bh, const bf16* Bl, int ldb,
                       float* C, bf16* Ch, bf16* Cl, int ldc,
                       int M, int N, int K, int mode, int out, const float* aux0) {
            GDesc& D = G.d[gi];
            D.Ah = Ah; D.Al = Al; D.Bh = Bh; D.Bl = Bl;
            D.C = C; D.Ch = Ch; D.Cl = Cl; D.aux0 = aux0;
            D.lda = lda; D.ldb = ldb; D.ldc = ldc; D.M = M; D.N = N; D.K = K;
            D.mode = mode; D.out = out;
            D.bx = (N + TBN - 1) / TBN;
            int by = (M + TBM - 1) / TBM;
            G.cum[gi] = cumb; cumb += D.bx * by; gi++;
        };
        add(bHcat_h, bHcat_l, 1200, bW1_h, bW1_l, 1600, nullptr, bHp1_h, bHp1_l, 400,
            BNH, 400, 1200, 0, 2, nullptr);                                   // Hp1
        add(bh_h, bh_l, 400, bW2_h + 400, bW2_l + 400, 800, nullptr, bHs_h, bHs_l, 400,
            BNH, 400, 400, 0, 2, nullptr);                                    // Hs
        add(bc_h, bc_l, 400, bW1_h + 1200, bW1_l + 1200, 1600, nullptr, bCc_h, bCc_l, 400,
            LL, 400, 400, 0, 2, nullptr);                                     // Cc
        add(bc_h, bc_l, 400, bW2_h, bW2_l, 800, nullptr, bCs_h, bCs_l, 400,
            LL, 400, 400, 1, 2, b2);                                          // Cs
        add(bc_h, bc_l, 400, bWa1_h + 400, bWa1_l + 400, 800, CA, nullptr, nullptr, 400,
            LL, 400, 400, 1, 1, ba1);                                         // CA
        add(bW3_h + 400, bW3_l + 400, 800, bWoT_h, bWoT_l, 400, nullptr, bWm_h, bWm_l, 400,
            400, 400, 400, 0, 2, nullptr);                                    // Wm
        G.cum[gi] = cumb; G.nd = gi;
        gemm_group<<<cumb, 256>>>(G);
    }

    // (4) grouped GEMM launch 2
    {
        GParams G; int cumb = 0; int gi = 0;
        auto add = [&](const bf16* Ah, const bf16* Al, int lda,
                       const bf16* Bh, const bf16* Bl, int ldb,
                       float* C, int ldc, int M, int N, int K, int mode, const float* aux0) {
            GDesc& D = G.d[gi];
            D.Ah = Ah; D.Al = Al; D.Bh = Bh; D.Bl = Bl;
            D.C = C; D.Ch = nullptr; D.Cl = nullptr; D.aux0 = aux0;
            D.lda = lda; D.ldb = ldb; D.ldc = ldc; D.M = M; D.N = N; D.K = K;
            D.mode = mode; D.out = 1;
            D.bx = (N + TBN - 1) / TBN;
            int by = (M + TBM - 1) / TBM;
            G.cum[gi] = cumb; cumb += D.bx * by; gi++;
        };
        add(bHp1_h, bHp1_l, 400, bW3_h, bW3_l, 800, T1, 400, BNH, 400, 400, 0, nullptr);      // T1
        add(bHs_h, bHs_l, 400, bWqkv_h, bWqkv_l, 400, Hq3, 1200, BNH, 1200, 400, 0, nullptr); // Hq3
        add(bCs_h, bCs_l, 400, bWqkv_h, bWqkv_l, 400, Cq3, 1200, LL, 1200, 400, 1, bqkv);     // Cq3
        add(bCc_h, bCc_l, 400, bW3_h, bW3_l, 800, T2, 400, LL, 400, 400, 0, nullptr);         // T2
        G.cum[gi] = cumb; G.nd = gi;
        gemm_group<<<cumb, 256>>>(G);
    }

    // (5) attention K/V prep
    attn_prep<<<dim3(NH_, BB), 256>>>(Cq3, Hq3, Kg, VHg, VLg);

    // (6) tensor-core flash attention
    attn_mma<<<dim3(5, NH_, NHEAD), 256>>>(Cq3, Hq3, Kg, VHg, VLg, bXo_h, bXo_l);

    // (7) tc
    tc_kernel<<<50, 256>>>(b1, bo, b3, W3, tc);

    // (8-10) big GEMMs
    // hall = Xo @ Wm^T + T1 + T2 + tc  (split only; nsplit=2)
    gemm_mma<3, 2, 2><<<mgrid(MM, 400), 256>>>(bXo_h, bXo_l, 400, bWm_h, bWm_l, 400,
        nullptr, bhall_h, bhall_l, 400, MM, 400, 400, T1, T2, tc);
    // a1 = tanh(hall @ Wa1a^T + CA)  (split; nsplit=2)
    gemm_mma<4, 2, 2><<<mgrid(MM, 400), 256>>>(bhall_h, bhall_l, 400, bWa1_h, bWa1_l, 800,
        nullptr, ba1_h, ba1_l, 400, MM, 400, 400, CA, nullptr, nullptr);
    // a2 + score fused: tanh(a1 @ Wa2^T + ba2) · Wa3 -> spart  (nsplit=2)
    gemm_mma<5, 0, 2><<<mgrid(MM, 200), 256>>>(ba1_h, ba1_l, 400, bWa2_h, bWa2_l, 400,
        spart, nullptr, nullptr, 200, MM, 200, 400, ba2, Wa3, nullptr);

    // (11) softmax + weighted sum
    softmax_u_kernel<<<LL, 128>>>(spart, bhall_h, bhall_l, u);
}

// round 14
// speedup vs baseline: 2.2797x; 1.3170x over previous
#include <cuda_runtime.h>
#include <cuda_bf16.h>
#include <math.h>
#include <stdint.h>

// Problem constants
#define DD    400
#define BB    64
#define NC_   10
#define NH_   50
#define NHEAD 20
#define DH    20
#define LL    640      // BB*NC_
#define MM    32000    // BB*NC_*NH_
#define BNH   3200     // BB*NH_

typedef __nv_bfloat16 bf16;

// ---------------- fp32 device scratch ----------------
__device__ float g_Hq3 [BNH * 1200];
__device__ float g_Cq3 [LL * 1200];
__device__ float g_T1  [BNH * 400];
__device__ float g_T2  [LL * 400];
__device__ float g_tc  [400];
__device__ float g_CA  [LL * 400];
__device__ float g_spart[2 * MM];

// ---------------- bf16 split scratch (hi/lo pairs) ----------------
__device__ __align__(16) bf16 g_bHcat_h[BNH * 1200], g_bHcat_l[BNH * 1200];
__device__ __align__(16) bf16 g_bh_h  [BNH * 400],  g_bh_l  [BNH * 400];
__device__ __align__(16) bf16 g_bHs_h [BNH * 400],  g_bHs_l [BNH * 400];
__device__ __align__(16) bf16 g_bHp1_h[BNH * 400],  g_bHp1_l[BNH * 400];
__device__ __align__(16) bf16 g_bc_h  [LL * 400],   g_bc_l  [LL * 400];
__device__ __align__(16) bf16 g_bCc_h [LL * 400],   g_bCc_l [LL * 400];
__device__ __align__(16) bf16 g_bCs_h [LL * 400],   g_bCs_l [LL * 400];
__device__ __align__(16) bf16 g_bXo_h [MM * 400],   g_bXo_l [MM * 400];
__device__ __align__(16) bf16 g_bhall_h[MM * 400],  g_bhall_l[MM * 400];
__device__ __align__(16) bf16 g_ba1_h [MM * 400];
__device__ __align__(16) bf16 g_bW1_h [400 * 1600], g_bW1_l [400 * 1600];
__device__ __align__(16) bf16 g_bW2_h [400 * 800],  g_bW2_l [400 * 800];
__device__ __align__(16) bf16 g_bWqkv_h[1200 * 400],g_bWqkv_l[1200 * 400];
__device__ __align__(16) bf16 g_bW3_h [400 * 800],  g_bW3_l [400 * 800];
__device__ __align__(16) bf16 g_bWa1_h[400 * 800],  g_bWa1_l[400 * 800];
__device__ __align__(16) bf16 g_bWa2_h[200 * 400],  g_bWa2_l[200 * 400];
__device__ __align__(16) bf16 g_bWoT_h[400 * 400],  g_bWoT_l[400 * 400];
__device__ __align__(16) bf16 g_bWm_h [400 * 400],  g_bWm_l [400 * 400];

// attention pre-rounded K/V (pure bf16)
// K: [n][h][m(640)][32] = [Kh(20) | 0(12)]    V: [n][h][d(20)][m(640)]
__device__ __align__(16) bf16 g_Kg [50 * 20 * 640 * 32];
__device__ __align__(16) bf16 g_VHg[50 * 20 * 20 * 640];

// ---------------- helpers ----------------
__device__ __forceinline__ uint32_t s2u(const void* p) {
    return (uint32_t)__cvta_generic_to_shared(p);
}
__device__ __forceinline__ void ldm4(uint32_t& r0, uint32_t& r1, uint32_t& r2, uint32_t& r3,
                                     uint32_t addr) {
    asm volatile("ldmatrix.sync.aligned.m8n8.x4.shared.b16 {%0,%1,%2,%3}, [%4];"
                 : "=r"(r0), "=r"(r1), "=r"(r2), "=r"(r3) : "r"(addr));
}
__device__ __forceinline__ void ldm2(uint32_t& r0, uint32_t& r1, uint32_t addr) {
    asm volatile("ldmatrix.sync.aligned.m8n8.x2.shared.b16 {%0,%1}, [%2];"
                 : "=r"(r0), "=r"(r1) : "r"(addr));
}
__device__ __forceinline__ void mma16816(float* d, const uint32_t* a, uint32_t b0, uint32_t b1) {
    asm volatile("mma.sync.aligned.m16n8k16.row.col.f32.bf16.bf16.f32 "
                 "{%0,%1,%2,%3}, {%4,%5,%6,%7}, {%8,%9}, {%0,%1,%2,%3};"
                 : "+f"(d[0]), "+f"(d[1]), "+f"(d[2]), "+f"(d[3])
                 : "r"(a[0]), "r"(a[1]), "r"(a[2]), "r"(a[3]), "r"(b0), "r"(b1));
}
__device__ __forceinline__ uint32_t pkbf(float a, float b) {
    __nv_bfloat162 t = __floats2bfloat162_rn(a, b);
    return *reinterpret_cast<uint32_t*>(&t);
}
__device__ __forceinline__ uint32_t pk2h(bf16 a, bf16 b) {
    __nv_bfloat162 t; t.x = a; t.y = b;
    return *reinterpret_cast<uint32_t*>(&t);
}
// cp.async 16B with src-size (0 => zero-fill)
__device__ __forceinline__ void cpa16(uint32_t saddr, const void* gptr, uint32_t bytes) {
    asm volatile("cp.async.cg.shared.global [%0], [%1], 16, %2;"
                 :: "r"(saddr), "l"(gptr), "r"(bytes));
}
#define CPA_COMMIT() asm volatile("cp.async.commit_group;" ::: "memory")
#define CPA_WAIT0()  asm volatile("cp.async.wait_group 0;" ::: "memory")

// ---------------- merged convert: 8 segments in one launch ----------------
struct ConvParams {
    const float* src[8];
    bf16* hi[8];
    bf16* lo[8];
    int cum[9];
};
__global__ void conv_all_kernel(ConvParams P) {
    int i = blockIdx.x * blockDim.x + threadIdx.x;
    if (i >= P.cum[8]) return;
    int g = 0;
    #pragma unroll
    for (int s = 1; s < 8; s++) if (i >= P.cum[s]) g = s;
    int local = i - P.cum[g];
    float v = P.src[g][local];
    bf16 hh = __float2bfloat16_rn(v);
    P.hi[g][local] = hh;
    P.lo[g][local] = __float2bfloat16_rn(v - __bfloat162float(hh));
}

// ---------------- prep2: Hcat gather (bf16 pairs) + Wo transpose-split ----------------
#define HC_PAIRS (BNH * 600)
#define HC_BLOCKS ((HC_PAIRS + 255) / 256)
#define TR_BLOCKS ((400 * 400 + 255) / 256)
__global__ void prep2_kernel(const bf16* __restrict__ hh, const bf16* __restrict__ hl,
                             bf16* __restrict__ oh, bf16* __restrict__ ol,
                             const float* __restrict__ Wo,
                             bf16* __restrict__ th, bf16* __restrict__ tl) {
    if ((int)blockIdx.x < HC_BLOCKS) {
        int idx = blockIdx.x * blockDim.x + threadIdx.x;   // pairs
        if (idx >= HC_PAIRS) return;
        int row = idx / 600, pr = idx % 600;
        int col = pr * 2;
        int b = row / NH_, j = row % NH_;
        int part = col / 400, d = col % 400;
        int jj = (part == 0) ? (j + NH_ - 1) % NH_ : ((part == 1) ? j : (j + 1) % NH_);
        int s = (b * NH_ + jj) * 400 + d;
        reinterpret_cast<uint32_t*>(oh)[idx] = *reinterpret_cast<const uint32_t*>(&hh[s]);
        reinterpret_cast<uint32_t*>(ol)[idx] = *reinterpret_cast<const uint32_t*>(&hl[s]);
    } else {
        int idx = (blockIdx.x - HC_BLOCKS) * blockDim.x + threadIdx.x;
        if (idx >= 400 * 400) return;
        int n = idx / 400, k = idx % 400;
        float v = Wo[k * 400 + n];
        bf16 hv = __float2bfloat16_rn(v);
        th[idx] = hv;
        tl[idx] = __float2bfloat16_rn(v - __bfloat162float(hv));
    }
}

// ---------------- tc: warp-per-row reduction ----------------
__global__ void tc_kernel(const float* __restrict__ b1, const float* __restrict__ bo,
                          const float* __restrict__ b3, const float* __restrict__ W3,
                          float* __restrict__ tc) {
    int w = threadIdx.x >> 5, lane = threadIdx.x & 31;
    int r = blockIdx.x * 8 + w;
    if (r >= 400) return;
    const float* row = W3 + (size_t)r * 800;
    float acc = 0.f;
    for (int d = lane; d < 400; d += 32)
        acc += b1[d] * row[d] + bo[d] * row[400 + d];
    #pragma unroll
    for (int o = 16; o > 0; o >>= 1) acc += __shfl_xor_sync(0xffffffffu, acc, o);
    if (lane == 0) tc[r] = acc + b3[r];
}

// ---------------- shared tensor-core GEMM core (bf16 split, cp.async) ----------------
// nsplit==3: AhBh+AhBl+AlBh ; nsplit==2: (Ah+Al)·Bh ; nsplit==1: Ah·Bh only
// mode 0: none | 1: +aux0[col] | 2: tanh(x+aux0[col]) | 3: biases | 4: tanh(x+aux0 row-bias)
// mode 5: tanh(x+aux0[col]) then fused dot with aux1 -> C = spart
// out bit0: fp32 C ; bit1: bf16 split Ch/Cl ; bit2: bf16 hi-only Ch
#define TBM 128
#define TBN 128
#define TBK 16
#define SSTR 24

__device__ __forceinline__ void gemm_core(
    const bf16* __restrict__ Ah, const bf16* __restrict__ Al, int lda,
    const bf16* __restrict__ Bh, const bf16* __restrict__ Bl, int ldb,
    float* __restrict__ C, bf16* __restrict__ Ch, bf16* __restrict__ Cl,
    int ldc, int M, int N, int K,
    const float* __restrict__ aux0, const float* __restrict__ aux1,
    const float* __restrict__ aux2,
    int row0, int col0, int mode, int out, int nsplit)
{
    __shared__ __align__(16) bf16 sAh[2][TBM * SSTR];
    __shared__ __align__(16) bf16 sAl[2][TBM * SSTR];
    __shared__ __align__(16) bf16 sBh[2][TBM * SSTR];
    __shared__ __align__(16) bf16 sBl[2][TBM * SSTR];

    const int tid = threadIdx.x;
    const int lrow = tid >> 1, lhalf = tid & 1;

    const bool aok = (row0 + lrow) < M;
    const bool bok = (col0 + lrow) < N;
    const uint32_t abytes = aok ? 16u : 0u;
    const uint32_t bbytes = bok ? 16u : 0u;
    const int arow = aok ? (row0 + lrow) : 0;
    const int brow = bok ? (col0 + lrow) : 0;
    const bf16* Aph = Ah + (size_t)arow * lda + lhalf * 8;
    const bf16* Apl = Al + (size_t)arow * lda + lhalf * 8;
    const bf16* Bph = Bh + (size_t)brow * ldb + lhalf * 8;
    const bf16* Bpl = Bl + (size_t)brow * ldb + lhalf * 8;
    const uint32_t sboff = (uint32_t)((lrow * SSTR + lhalf * 8) * 2);

    const int w = tid >> 5, lane = tid & 31;
    const int wm = w >> 2, wn = w & 3;
    const int mrow = ((lane >> 3) & 1) * 8 + (lane & 7);
    const int koff = (lane >> 4) * 8;

    uint32_t aoff[4], boff[2];
    #pragma unroll
    for (int fm = 0; fm < 4; fm++)
        aoff[fm] = (uint32_t)(((wm * 64 + fm * 16 + mrow) * SSTR + koff) * 2);
    #pragma unroll
    for (int f = 0; f < 2; f++)
        boff[f] = (uint32_t)(((wn * 32 + f * 16 + mrow) * SSTR + koff) * 2);

    const uint32_t bAh = s2u(sAh), bAl = s2u(sAl), bBh = s2u(sBh), bBl = s2u(sBl);
    const uint32_t STB = TBM * SSTR * 2;

    float acc[4][4][4];
    #pragma unroll
    for (int i = 0; i < 4; i++)
        #pragma unroll
        for (int j = 0; j < 4; j++)
            #pragma unroll
            for (int e = 0; e < 4; e++) acc[i][j][e] = 0.f;

    // stage-0 async copy
    {
        cpa16(bAh + sboff, Aph, abytes);
        if (nsplit >= 2) cpa16(bAl + sboff, Apl, abytes);
        cpa16(bBh + sboff, Bph, bbytes);
        if (nsplit == 3) cpa16(bBl + sboff, Bpl, bbytes);
        CPA_COMMIT();
    }
    CPA_WAIT0();
    __syncthreads();

    const int nk = K / TBK;
    for (int t = 0; t < nk; t++) {
        const int st = t & 1;
        if (t + 1 < nk) {
            const int k = (t + 1) * TBK;
            const uint32_t nso = (uint32_t)(st ^ 1) * STB + sboff;
            cpa16(bAh + nso, Aph + k, abytes);
            if (nsplit >= 2) cpa16(bAl + nso, Apl + k, abytes);
            cpa16(bBh + nso, Bph + k, bbytes);
            if (nsplit == 3) cpa16(bBl + nso, Bpl + k, bbytes);
            CPA_COMMIT();
        }

        uint32_t ah[4][4], al[4][4], bh[2][4], bl[2][4];
        #pragma unroll
        for (int fm = 0; fm < 4; fm++) {
            ldm4(ah[fm][0], ah[fm][1], ah[fm][2], ah[fm][3], bAh + st * STB + aoff[fm]);
            if (nsplit >= 2)
                ldm4(al[fm][0], al[fm][1], al[fm][2], al[fm][3], bAl + st * STB + aoff[fm]);
        }
        #pragma unroll
        for (int f = 0; f < 2; f++) {
            ldm4(bh[f][0], bh[f][1], bh[f][2], bh[f][3], bBh + st * STB + boff[f]);
            if (nsplit == 3)
                ldm4(bl[f][0], bl[f][1], bl[f][2], bl[f][3], bBl + st * STB + boff[f]);
        }

        #pragma unroll
        for (int fm = 0; fm < 4; fm++) {
            #pragma unroll
            for (int f = 0; f < 2; f++) {
                mma16816(acc[fm][f * 2 + 0], ah[fm], bh[f][0], bh[f][2]);
                if (nsplit >= 2)
                    mma16816(acc[fm][f * 2 + 0], al[fm], bh[f][0], bh[f][2]);
                if (nsplit == 3)
                    mma16816(acc[fm][f * 2 + 0], ah[fm], bl[f][0], bl[f][2]);
                mma16816(acc[fm][f * 2 + 1], ah[fm], bh[f][1], bh[f][3]);
                if (nsplit >= 2)
                    mma16816(acc[fm][f * 2 + 1], al[fm], bh[f][1], bh[f][3]);
                if (nsplit == 3)
                    mma16816(acc[fm][f * 2 + 1], ah[fm], bl[f][1], bl[f][3]);
            }
        }

        if (t + 1 < nk) {
            CPA_WAIT0();
            __syncthreads();
        }
    }

    float sacc[4][2];
    #pragma unroll
    for (int i = 0; i < 4; i++) { sacc[i][0] = 0.f; sacc[i][1] = 0.f; }

    // epilogue (pairwise: cols cc, cc+1)
    #pragma unroll
    for (int fm = 0; fm < 4; fm++) {
        #pragma unroll
        for (int half = 0; half < 2; half++) {
            const int r = row0 + wm * 64 + fm * 16 + (lane >> 2) + half * 8;
            if (r >= M) continue;
            int bb = 0, ii = 0, jj = 0;
            if (mode == 3 || mode == 4) { bb = r / 500; ii = (r / 50) % 10; jj = r % 50; }
            #pragma unroll
            for (int fn = 0; fn < 4; fn++) {
                const int cc = col0 + wn * 32 + fn * 8 + (lane & 3) * 2;
                if (cc >= N) continue;
                float v0 = acc[fm][fn][half * 2], v1 = acc[fm][fn][half * 2 + 1];
                if (mode == 1) { v0 += aux0[cc]; v1 += aux0[cc + 1]; }
                if (mode == 2 || mode == 5) {
                    v0 = tanhf(v0 + aux0[cc]); v1 = tanhf(v1 + aux0[cc + 1]);
                }
                if (mode == 3) {
                    const float* p0 = aux0 + (size_t)(bb * 50 + jj) * N;
                    const float* p1 = aux1 + (size_t)(bb * 10 + ii) * N;
                    v0 += p0[cc] + p1[cc] + aux2[cc];
                    v1 += p0[cc + 1] + p1[cc + 1] + aux2[cc + 1];
                }
                if (mode == 4) {
                    const float* p0 = aux0 + (size_t)(bb * 10 + ii) * N;
                    v0 = tanhf(v0 + p0[cc]); v1 = tanhf(v1 + p0[cc + 1]);
                }
                if (mode == 5)
                    sacc[fm][half] += v0 * aux1[cc] + v1 * aux1[cc + 1];
                if (out & 1)
                    *reinterpret_cast<float2*>(&C[(size_t)r * ldc + cc]) = make_float2(v0, v1);
                if (out & 2) {
                    bf16 h0 = __float2bfloat16_rn(v0), h1 = __float2bfloat16_rn(v1);
                    *reinterpret_cast<uint32_t*>(&Ch[(size_t)r * ldc + cc]) = pk2h(h0, h1);
                    *reinterpret_cast<uint32_t*>(&Cl[(size_t)r * ldc + cc]) =
                        pkbf(v0 - __bfloat162float(h0), v1 - __bfloat162float(h1));
                }
                if (out & 4)
                    *reinterpret_cast<uint32_t*>(&Ch[(size_t)r * ldc + cc]) = pkbf(v0, v1);
            }
        }
    }

    // mode 5: deterministic cross-warp score reduction -> C[part*M + r]
    if (mode == 5) {
        __syncthreads();
        float* red = reinterpret_cast<float*>(sAh);
        #pragma unroll
        for (int fm = 0; fm < 4; fm++) {
            #pragma unroll
            for (int half = 0; half < 2; half++) {
                float v = sacc[fm][half];
                v += __shfl_xor_sync(0xffffffffu, v, 1);
                v += __shfl_xor_sync(0xffffffffu, v, 2);
                if ((lane & 3) == 0)
                    red[(wm * 64 + fm * 16 + (lane >> 2) + half * 8) * 4 + wn] = v;
            }
        }
        __syncthreads();
        if (tid < 128) {
            int r = row0 + tid;
            if (r < M)
                C[(size_t)(col0 >> 7) * M + r] =
                    red[tid * 4] + red[tid * 4 + 1] + red[tid * 4 + 2] + red[tid * 4 + 3];
        }
    }
}

// template wrapper (big GEMMs)
template <int MODE, int OUT, int NSPLIT>
__global__ __launch_bounds__(256, 2) void gemm_mma(
    const bf16* __restrict__ Ah, const bf16* __restrict__ Al, int lda,
    const bf16* __restrict__ Bh, const bf16* __restrict__ Bl, int ldb,
    float* __restrict__ C, bf16* __restrict__ Ch, bf16* __restrict__ Cl,
    int ldc, int M, int N, int K,
    const float* __restrict__ aux0, const float* __restrict__ aux1,
    const float* __restrict__ aux2)
{
    gemm_core(Ah, Al, lda, Bh, Bl, ldb, C, Ch, Cl, ldc, M, N, K,
              aux0, aux1, aux2, blockIdx.y * TBM, blockIdx.x * TBN, MODE, OUT, NSPLIT);
}

// grouped wrapper (small GEMMs, modes 0/1, always nsplit=3)
struct GDesc {
    const bf16 *Ah, *Al, *Bh, *Bl;
    float* C; bf16 *Ch; bf16 *Cl;
    const float* aux0;
    int lda, ldb, ldc, M, N, K, mode, out, bx;
};
struct GParams { GDesc d[6]; int cum[7]; int nd; };

__global__ __launch_bounds__(256, 2) void gemm_group(GParams P) {
    int g = 0;
    while (g + 1 < P.nd && (int)blockIdx.x >= P.cum[g + 1]) g++;
    const GDesc& D = P.d[g];
    int local = blockIdx.x - P.cum[g];
    int bxi = local % D.bx, byi = local / D.bx;
    gemm_core(D.Ah, D.Al, D.lda, D.Bh, D.Bl, D.ldb, D.C, D.Ch, D.Cl, D.ldc,
              D.M, D.N, D.K, D.aux0, nullptr, nullptr,
              byi * TBM, bxi * TBN, D.mode, D.out, 3);
}

// ---------------- attention K/V prep (pure bf16) ----------------
// K: [n][h][m][32] = [Kh(20) | 0(12)] ; V: [n][h][d][m] hi only
__global__ void attn_prep(const float* __restrict__ Cq3, const float* __restrict__ Hq3,
                          bf16* __restrict__ Kg, bf16* __restrict__ VHg)
{
    const int n = blockIdx.x, b = blockIdx.y;
    const float* Hrow = Hq3 + (size_t)(b * NH_ + n) * 1200;
    const bf16 zb = __float2bfloat16_rn(0.f);

    for (int idx = threadIdx.x; idx < 20 * 10 * 32; idx += 256) {
        int h = idx / 320, rem = idx % 320, mm = rem >> 5, d = rem & 31;
        int m = b * 10 + mm;
        bf16 outv = zb;
        if (d < 20)
            outv = __float2bfloat16_rn(Cq3[m * 1200 + 400 + h * 20 + d]
                                       + Hrow[400 + h * 20 + d]);
        Kg[((size_t)(n * 20 + h) * 640 + m) * 32 + d] = outv;
    }
    for (int idx = threadIdx.x; idx < 4000; idx += 256) {
        int h = idx / 200, d = (idx / 10) % 20, mm = idx % 10;
        int m = b * 10 + mm;
        VHg[((size_t)(n * 20 + h) * 20 + d) * 640 + m] =
            __float2bfloat16_rn(Cq3[m * 1200 + 800 + h * 20 + d] + Hrow[800 + h * 20 + d]);
    }
}

// ---------------- tensor-core flash attention (pure bf16 S and PV) ----------------
// smem bytes: K double buf 2x8192 (Q staging overlays both), VH 2x3072 at 16384
__global__ __launch_bounds__(256, 2) void attn_mma(
    const float* __restrict__ Cq3, const float* __restrict__ Hq3,
    const bf16* __restrict__ Kg, const bf16* __restrict__ VHg,
    bf16* __restrict__ Xoh, bf16* __restrict__ Xol)
{
    __shared__ __align__(16) bf16 sm[11264];   // 22.5KB

    const int qt = blockIdx.x, n = blockIdx.y, h = blockIdx.z;
    const int tid = threadIdx.x, w = tid >> 5, lane = tid & 31;
    const float scale = 0.22360679774997896f;  // 1/sqrt(20)
    const bf16 zb = __float2bfloat16_rn(0.f);

    const bf16* Kb  = Kg  + (size_t)(n * 20 + h) * 640 * 32;
    const bf16* Vbh = VHg + (size_t)(n * 20 + h) * 20 * 640;

    const uint32_t smb = s2u(sm);

    // build Q [128][32 logical cols] in 128B-stride rows (segs 0-3 swizzled)
    for (int idx = tid; idx < 128 * 32; idx += 256) {
        int r = idx >> 5, d = idx & 31;
        bf16 outv = zb;
        if (d < 20) {
            int l = qt * 128 + r;
            int qr = (l / NC_) * NH_ + n;
            outv = __float2bfloat16_rn(
                (Cq3[l * 1200 + h * 20 + d] + Hq3[qr * 1200 + h * 20 + d]) * scale);
        }
        int e = ((d >> 3) ^ (r & 7)) * 8 + (d & 7);
        sm[r * 64 + e] = outv;
    }
    __syncthreads();

    const int mrow = ((lane >> 3) & 1) * 8 + (lane & 7);
    const uint32_t lk16 = (uint32_t)((lane >> 4) << 4);

    uint32_t qf[2][4];
    #pragma unroll
    for (int kc = 0; kc < 2; kc++) {
        int row = w * 16 + mrow;
        uint32_t cb = (uint32_t)(kc * 32) + lk16;
        ldm4(qf[kc][0], qf[kc][1], qf[kc][2], qf[kc][3],
             smb + row * 128 + (cb ^ (uint32_t)((row & 7) << 4)));
    }
    // zero V pad rows 20-23 of both buffers (never touched by copies)
    for (int idx = tid; idx < 512; idx += 256) {
        int b2 = idx >> 8, e = idx & 255;
        sm[9472 + b2 * 1536 + e] = zb;
    }
    __syncthreads();

    // tile copy: K 256 chunks (cols 0-31), V hi 160 chunks
    auto copy_tile = [&](int kt2, int bufi) {
        const uint32_t kdst = smb + bufi * 8192;
        {
            int kk = tid >> 2, seg = tid & 3;
            cpa16(kdst + kk * 128 + (uint32_t)((seg * 16) ^ ((kk & 7) << 4)),
                  Kb + (size_t)(kt2 * 64 + kk) * 32 + seg * 8, 16);
        }
        if (tid < 160) {
            int d = tid >> 3, seg = tid & 7;
            uint32_t so = (uint32_t)((seg * 16) ^ ((d & 7) << 4));
            cpa16(smb + 16384 + bufi * 3072 + d * 128 + so,
                  Vbh + (size_t)d * 640 + kt2 * 64 + seg * 8, 16);
        }
    };

    copy_tile(0, 0);
    CPA_COMMIT();

    float O0[3][4];
    #pragma unroll
    for (int f = 0; f < 3; f++)
        #pragma unroll
        for (int e = 0; e < 4; e++) O0[f][e] = 0.f;
    float zl = 0.f, zh2 = 0.f;

    for (int kt = 0; kt < 10; kt++) {
        const int bufi = kt & 1;
        CPA_WAIT0();
        __syncthreads();
        if (kt + 1 < 10) { copy_tile(kt + 1, bufi ^ 1); CPA_COMMIT(); }

        const uint32_t kbase = smb + bufi * 8192;
        union { float f[8][4]; uint32_t u[8][4]; } SP;
        #pragma unroll
        for (int f = 0; f < 8; f++)
            #pragma unroll
            for (int e = 0; e < 4; e++) SP.f[f][e] = 0.f;

        #pragma unroll
        for (int g = 0; g < 4; g++) {
            uint32_t kf[2][4];
            int row = g * 16 + mrow;
            #pragma unroll
            for (int kc = 0; kc < 2; kc++) {
                uint32_t cb = (uint32_t)(kc * 32) + lk16;
                ldm4(kf[kc][0], kf[kc][1], kf[kc][2], kf[kc][3],
                     kbase + row * 128 + (cb ^ (uint32_t)((row & 7) << 4)));
            }
            #pragma unroll
            for (int kc = 0; kc < 2; kc++) {
                mma16816(SP.f[2 * g + 0], qf[kc], kf[kc][0], kf[kc][2]);
                mma16816(SP.f[2 * g + 1], qf[kc], kf[kc][1], kf[kc][3]);
            }
        }

        #pragma unroll
        for (int f = 0; f < 8; f++) {
            float e0 = __expf(SP.f[f][0]), e1 = __expf(SP.f[f][1]);
            float e2 = __expf(SP.f[f][2]), e3 = __expf(SP.f[f][3]);
            zl += e0 + e1; zh2 += e2 + e3;
            SP.u[f][0] = pkbf(e0, e1);
            SP.u[f][1] = pkbf(e2, e3);
        }

        const uint32_t vhbase = smb + 16384 + bufi * 3072;
        #pragma unroll
        for (int kc2 = 0; kc2 < 4; kc2++) {
            uint32_t ah[4] = { SP.u[2 * kc2][0], SP.u[2 * kc2][1],
                               SP.u[2 * kc2 + 1][0], SP.u[2 * kc2 + 1][1] };
            uint32_t vh4[4], vh2[2];
            uint32_t cb4 = (uint32_t)(kc2 * 32) + lk16;
            uint32_t a4 = mrow * 128 + (cb4 ^ (uint32_t)((mrow & 7) << 4));
            int d2 = 16 + (lane & 7);
            uint32_t cb2 = (uint32_t)(kc2 * 32) + (uint32_t)(((lane >> 3) & 1) << 4);
            uint32_t a2 = d2 * 128 + (cb2 ^ (uint32_t)((d2 & 7) << 4));
            ldm4(vh4[0], vh4[1], vh4[2], vh4[3], vhbase + a4);
            ldm2(vh2[0], vh2[1], vhbase + a2);
            mma16816(O0[0], ah, vh4[0], vh4[2]);
            mma16816(O0[1], ah, vh4[1], vh4[3]);
            mma16816(O0[2], ah, vh2[0], vh2[1]);
        }
    }

    zl  += __shfl_xor_sync(0xffffffffu, zl, 1);
    zl  += __shfl_xor_sync(0xffffffffu, zl, 2);
    zh2 += __shfl_xor_sync(0xffffffffu, zh2, 1);
    zh2 += __shfl_xor_sync(0xffffffffu, zh2, 2);
    float izl = 1.f / zl, izh = 1.f / zh2;

    const int rowq = lane >> 2;
    #pragma unroll
    for (int f = 0; f < 3; f++) {
        int d0 = f * 8 + (lane & 3) * 2;
        if (d0 >= 20) continue;
        #pragma unroll
        for (int half = 0; half < 2; half++) {
            int lq = qt * 128 + w * 16 + rowq + half * 8;
            float v0 = O0[f][half * 2]     * (half ? izh : izl);
            float v1 = O0[f][half * 2 + 1] * (half ? izh : izl);
            size_t o = (size_t)(lq * NH_ + n) * 400 + h * 20 + d0;
            bf16 h0 = __float2bfloat16_rn(v0), h1 = __float2bfloat16_rn(v1);
            *reinterpret_cast<uint32_t*>(&Xoh[o]) = pk2h(h0, h1);
            *reinterpret_cast<uint32_t*>(&Xol[o]) =
                pkbf(v0 - __bfloat162float(h0), v1 - __bfloat162float(h1));
        }
    }
}

// ---------------- softmax over j + weighted sum ----------------
__global__ void softmax_u_kernel(const float* __restrict__ spart,
                                 const bf16* __restrict__ hallh,
                                 const bf16* __restrict__ halll,
                                 float* __restrict__ u)
{
    __shared__ float a[NH_];
    int bi = blockIdx.x;
    if (threadIdx.x == 0) {
        float sv[NH_];
        float mx = -1e30f;
        for (int j = 0; j < NH_; j++) {
            int r = bi * NH_ + j;
            sv[j] = spart[r] + spart[MM + r];
            mx = fmaxf(mx, sv[j]);
        }
        float Z = 0.f;
        for (int j = 0; j < NH_; j++) { float e = __expf(sv[j] - mx); a[j] = e; Z += e; }
        float iz = 1.f / Z;
        for (int j = 0; j < NH_; j++) a[j] *= iz;
    }
    __syncthreads();
    for (int d = threadIdx.x; d < 400; d += blockDim.x) {
        float acc = 0.f;
        for (int j = 0; j < NH_; j++) {
            size_t o = ((size_t)bi * NH_ + j) * 400 + d;
            acc += a[j] * (__bfloat162float(hallh[o]) + __bfloat162float(halll[o]));
        }
        u[(size_t)bi * 400 + d] = acc;
    }
}

// ---------------- launch ----------------
static inline dim3 mgrid(int M, int N) { return dim3((N + TBN - 1) / TBN, (M + TBM - 1) / TBM); }

extern "C" void kernel_launch(void* const* d_in, const int* in_sizes, int n_in,
                              void* d_out, int out_size)
{
    const float* h    = (const float*)d_in[0];
    const float* c    = (const float*)d_in[2];
    const float* W1   = (const float*)d_in[4];
    const float* b1   = (const float*)d_in[5];
    const float* W2   = (const float*)d_in[6];
    const float* b2   = (const float*)d_in[7];
    const float* W3   = (const float*)d_in[8];
    const float* b3   = (const float*)d_in[9];
    const float* Wa1  = (const float*)d_in[10];
    const float* ba1  = (const float*)d_in[11];
    const float* Wa2  = (const float*)d_in[12];
    const float* ba2  = (const float*)d_in[13];
    const float* Wa3  = (const float*)d_in[14];
    const float* Wqkv = (const float*)d_in[16];
    const float* bqkv = (const float*)d_in[17];
    const float* Wo   = (const float*)d_in[18];
    const float* bo   = (const float*)d_in[19];
    float* u = (float*)d_out;

    float *Hq3, *Cq3, *T1, *T2, *tc, *CA, *spart;
    cudaGetSymbolAddress((void**)&Hq3,  g_Hq3);
    cudaGetSymbolAddress((void**)&Cq3,  g_Cq3);
    cudaGetSymbolAddress((void**)&T1,   g_T1);
    cudaGetSymbolAddress((void**)&T2,   g_T2);
    cudaGetSymbolAddress((void**)&tc,   g_tc);
    cudaGetSymbolAddress((void**)&CA,   g_CA);
    cudaGetSymbolAddress((void**)&spart, g_spart);

    bf16 *bHcat_h, *bHcat_l, *bh_h, *bh_l, *bHs_h, *bHs_l, *bHp1_h, *bHp1_l;
    bf16 *bc_h, *bc_l, *bCc_h, *bCc_l, *bCs_h, *bCs_l;
    bf16 *bXo_h, *bXo_l, *bhall_h, *bhall_l, *ba1_h;
    bf16 *bW1_h, *bW1_l, *bW2_h, *bW2_l, *bWqkv_h, *bWqkv_l, *bW3_h, *bW3_l;
    bf16 *bWa1_h, *bWa1_l, *bWa2_h, *bWa2_l, *bWoT_h, *bWoT_l, *bWm_h, *bWm_l;
    bf16 *Kg, *VHg;
    cudaGetSymbolAddress((void**)&bHcat_h, g_bHcat_h);  cudaGetSymbolAddress((void**)&bHcat_l, g_bHcat_l);
    cudaGetSymbolAddress((void**)&bh_h,    g_bh_h);     cudaGetSymbolAddress((void**)&bh_l,    g_bh_l);
    cudaGetSymbolAddress((void**)&bHs_h,   g_bHs_h);    cudaGetSymbolAddress((void**)&bHs_l,   g_bHs_l);
    cudaGetSymbolAddress((void**)&bHp1_h,  g_bHp1_h);   cudaGetSymbolAddress((void**)&bHp1_l,  g_bHp1_l);
    cudaGetSymbolAddress((void**)&bc_h,    g_bc_h);     cudaGetSymbolAddress((void**)&bc_l,    g_bc_l);
    cudaGetSymbolAddress((void**)&bCc_h,   g_bCc_h);    cudaGetSymbolAddress((void**)&bCc_l,   g_bCc_l);
    cudaGetSymbolAddress((void**)&bCs_h,   g_bCs_h);    cudaGetSymbolAddress((void**)&bCs_l,   g_bCs_l);
    cudaGetSymbolAddress((void**)&bXo_h,   g_bXo_h);    cudaGetSymbolAddress((void**)&bXo_l,   g_bXo_l);
    cudaGetSymbolAddress((void**)&bhall_h, g_bhall_h);  cudaGetSymbolAddress((void**)&bhall_l, g_bhall_l);
    cudaGetSymbolAddress((void**)&ba1_h,   g_ba1_h);
    cudaGetSymbolAddress((void**)&bW1_h,   g_bW1_h);    cudaGetSymbolAddress((void**)&bW1_l,   g_bW1_l);
    cudaGetSymbolAddress((void**)&bW2_h,   g_bW2_h);    cudaGetSymbolAddress((void**)&bW2_l,   g_bW2_l);
    cudaGetSymbolAddress((void**)&bWqkv_h, g_bWqkv_h);  cudaGetSymbolAddress((void**)&bWqkv_l, g_bWqkv_l);
    cudaGetSymbolAddress((void**)&bW3_h,   g_bW3_h);    cudaGetSymbolAddress((void**)&bW3_l,   g_bW3_l);
    cudaGetSymbolAddress((void**)&bWa1_h,  g_bWa1_h);   cudaGetSymbolAddress((void**)&bWa1_l,  g_bWa1_l);
    cudaGetSymbolAddress((void**)&bWa2_h,  g_bWa2_h);   cudaGetSymbolAddress((void**)&bWa2_l,  g_bWa2_l);
    cudaGetSymbolAddress((void**)&bWoT_h,  g_bWoT_h);   cudaGetSymbolAddress((void**)&bWoT_l,  g_bWoT_l);
    cudaGetSymbolAddress((void**)&bWm_h,   g_bWm_h);    cudaGetSymbolAddress((void**)&bWm_l,   g_bWm_l);
    cudaGetSymbolAddress((void**)&Kg,  g_Kg);
    cudaGetSymbolAddress((void**)&VHg, g_VHg);

    // (1) merged conversions
    ConvParams CP;
    const float* srcs[8] = { h, c, W1, W2, Wqkv, W3, Wa1, Wa2 };
    bf16* his[8] = { bh_h, bc_h, bW1_h, bW2_h, bWqkv_h, bW3_h, bWa1_h, bWa2_h };
    bf16* los[8] = { bh_l, bc_l, bW1_l, bW2_l, bWqkv_l, bW3_l, bWa1_l, bWa2_l };
    int ns[8] = { BNH * 400, LL * 400, 400 * 1600, 400 * 800, 1200 * 400,
                  400 * 800, 400 * 800, 200 * 400 };
    int cum = 0;
    for (int i = 0; i < 8; i++) { CP.src[i] = srcs[i]; CP.hi[i] = his[i]; CP.lo[i] = los[i];
                                  CP.cum[i] = cum; cum += ns[i]; }
    CP.cum[8] = cum;
    conv_all_kernel<<<(cum + 255) / 256, 256>>>(CP);

    // (2) Hcat gather + Wo transpose-split
    prep2_kernel<<<HC_BLOCKS + TR_BLOCKS, 256>>>(bh_h, bh_l, bHcat_h, bHcat_l,
                                                 Wo, bWoT_h, bWoT_l);

    // (3) grouped GEMM launch 1
    {
        GParams G; int cumb = 0; int gi = 0;
        auto add = [&](const bf16* Ah, const bf16* Al, int lda,
                       const bf16* Bh, const bf16* Bl, int ldb,
                       float* C, bf16* Ch, bf16* Cl, int ldc,
                       int M, int N, int K, int mode, int out, const float* aux0) {
            GDesc& D = G.d[gi];
            D.Ah = Ah; D.Al = Al; D.Bh = Bh; D.Bl = Bl;
            D.C = C; D.Ch = Ch; D.Cl = Cl; D.aux0 = aux0;
            D.lda = lda; D.ldb = ldb; D.ldc = ldc; D.M = M; D.N = N; D.K = K;
            D.mode = mode; D.out = out;
            D.bx = (N + TBN - 1) / TBN;
            int by = (M + TBM - 1) / TBM;
            G.cum[gi] = cumb; cumb += D.bx * by; gi++;
        };
        add(bHcat_h, bHcat_l, 1200, bW1_h, bW1_l, 1600, nullptr, bHp1_h, bHp1_l, 400,
            BNH, 400, 1200, 0, 2, nullptr);                                   // Hp1
        add(bh_h, bh_l, 400, bW2_h + 400, bW2_l + 400, 800, nullptr, bHs_h, bHs_l, 400,
            BNH, 400, 400, 0, 2, nullptr);                                    // Hs
        add(bc_h, bc_l, 400, bW1_h + 1200, bW1_l + 1200, 1600, nullptr, bCc_h, bCc_l, 400,
            LL, 400, 400, 0, 2, nullptr);                                     // Cc
        add(bc_h, bc_l, 400, bW2_h, bW2_l, 800, nullptr, bCs_h, bCs_l, 400,
            LL, 400, 400, 1, 2, b2);                                          // Cs
        add(bc_h, bc_l, 400, bWa1_h + 400, bWa1_l + 400, 800, CA, nullptr, nullptr, 400,
            LL, 400, 400, 1, 1, ba1);                                         // CA
        add(bW3_h + 400, bW3_l + 400, 800, bWoT_h, bWoT_l, 400, nullptr, bWm_h, bWm_l, 400,
            400, 400, 400, 0, 2, nullptr);                                    // Wm
        G.cum[gi] = cumb; G.nd = gi;
        gemm_group<<<cumb, 256>>>(G);
    }

    // (4) grouped GEMM launch 2
    {
        GParams G; int cumb = 0; int gi = 0;
        auto add = [&](const bf16* Ah, const bf16* Al, int lda,
                       const bf16* Bh, const bf16* Bl, int ldb,
                       float* C, int ldc, int M, int N, int K, int mode, const float* aux0) {
            GDesc& D = G.d[gi];
            D.Ah = Ah; D.Al = Al; D.Bh = Bh; D.Bl = Bl;
            D.C = C; D.Ch = nullptr; D.Cl = nullptr; D.aux0 = aux0;
            D.lda = lda; D.ldb = ldb; D.ldc = ldc; D.M = M; D.N = N; D.K = K;
            D.mode = mode; D.out = 1;
            D.bx = (N + TBN - 1) / TBN;
            int by = (M + TBM - 1) / TBM;
            G.cum[gi] = cumb; cumb += D.bx * by; gi++;
        };
        add(bHp1_h, bHp1_l, 400, bW3_h, bW3_l, 800, T1, 400, BNH, 400, 400, 0, nullptr);      // T1
        add(bHs_h, bHs_l, 400, bWqkv_h, bWqkv_l, 400, Hq3, 1200, BNH, 1200, 400, 0, nullptr); // Hq3
        add(bCs_h, bCs_l, 400, bWqkv_h, bWqkv_l, 400, Cq3, 1200, LL, 1200, 400, 1, bqkv);     // Cq3
        add(bCc_h, bCc_l, 400, bW3_h, bW3_l, 800, T2, 400, LL, 400, 400, 0, nullptr);         // T2
        G.cum[gi] = cumb; G.nd = gi;
        gemm_group<<<cumb, 256>>>(G);
    }

    // (5) attention K/V prep (pure bf16)
    attn_prep<<<dim3(NH_, BB), 256>>>(Cq3, Hq3, Kg, VHg);

    // (6) tensor-core flash attention (pure bf16)
    attn_mma<<<dim3(5, NH_, NHEAD), 256>>>(Cq3, Hq3, Kg, VHg, bXo_h, bXo_l);

    // (7) tc
    tc_kernel<<<50, 256>>>(b1, bo, b3, W3, tc);

    // (8-10) big GEMMs
    // hall = Xo @ Wm^T + T1 + T2 + tc  (split out; nsplit=2)
    gemm_mma<3, 2, 2><<<mgrid(MM, 400), 256>>>(bXo_h, bXo_l, 400, bWm_h, bWm_l, 400,
        nullptr, bhall_h, bhall_l, 400, MM, 400, 400, T1, T2, tc);
    // a1 = tanh(bf16(hall) @ Wa1a^T + CA)  (hi-only out; nsplit=1)
    gemm_mma<4, 4, 1><<<mgrid(MM, 400), 256>>>(bhall_h, bhall_h, 400, bWa1_h, bWa1_l, 800,
        nullptr, ba1_h, nullptr, 400, MM, 400, 400, CA, nullptr, nullptr);
    // a2 + score fused: tanh(a1 @ Wa2^T + ba2) · Wa3 -> spart  (nsplit=1)
    gemm_mma<5, 0, 1><<<mgrid(MM, 200), 256>>>(ba1_h, ba1_h, 400, bWa2_h, bWa2_l, 400,
        spart, nullptr, nullptr, 200, MM, 200, 400, ba2, Wa3, nullptr);

    // (11) softmax + weighted sum
    softmax_u_kernel<<<LL, 128>>>(spart, bhall_h, bhall_l, u);
}

// round 17
// speedup vs baseline: 2.4295x; 1.0657x over previous
#include <cuda_runtime.h>
#include <cuda_bf16.h>
#include <math.h>
#include <stdint.h>

// Problem constants
#define DD    400
#define BB    64
#define NC_   10
#define NH_   50
#define NHEAD 20
#define DH    20
#define LL    640      // BB*NC_
#define MM    32000    // BB*NC_*NH_
#define BNH   3200     // BB*NH_

typedef __nv_bfloat16 bf16;

// ---------------- fp32 device scratch ----------------
__device__ float g_Hq3 [BNH * 1200];
__device__ float g_Cq3 [LL * 1200];
__device__ float g_T1  [BNH * 400];
__device__ float g_T2  [LL * 400];
__device__ float g_tc  [400];
__device__ float g_CA  [LL * 400];
__device__ float g_spart[2 * MM];

// ---------------- bf16 split scratch (hi/lo pairs) ----------------
__device__ __align__(16) bf16 g_bHcat_h[BNH * 1200], g_bHcat_l[BNH * 1200];
__device__ __align__(16) bf16 g_bh_h  [BNH * 400],  g_bh_l  [BNH * 400];
__device__ __align__(16) bf16 g_bHs_h [BNH * 400],  g_bHs_l [BNH * 400];
__device__ __align__(16) bf16 g_bHp1_h[BNH * 400],  g_bHp1_l[BNH * 400];
__device__ __align__(16) bf16 g_bc_h  [LL * 400],   g_bc_l  [LL * 400];
__device__ __align__(16) bf16 g_bCc_h [LL * 400],   g_bCc_l [LL * 400];
__device__ __align__(16) bf16 g_bCs_h [LL * 400],   g_bCs_l [LL * 400];
__device__ __align__(16) bf16 g_bXo_h [MM * 400];
__device__ __align__(16) bf16 g_bhall_h[MM * 400],  g_bhall_l[MM * 400];
__device__ __align__(16) bf16 g_ba1_h [MM * 400];
__device__ __align__(16) bf16 g_bW1_h [400 * 1600], g_bW1_l [400 * 1600];
__device__ __align__(16) bf16 g_bW2_h [400 * 800],  g_bW2_l [400 * 800];
__device__ __align__(16) bf16 g_bWqkv_h[1200 * 400],g_bWqkv_l[1200 * 400];
__device__ __align__(16) bf16 g_bW3_h [400 * 800],  g_bW3_l [400 * 800];
__device__ __align__(16) bf16 g_bWa1_h[400 * 800],  g_bWa1_l[400 * 800];
__device__ __align__(16) bf16 g_bWa2_h[200 * 400],  g_bWa2_l[200 * 400];
__device__ __align__(16) bf16 g_bWoT_h[400 * 400],  g_bWoT_l[400 * 400];
__device__ __align__(16) bf16 g_bWm_h [400 * 400],  g_bWm_l [400 * 400];

// attention pre-rounded K/V (pure bf16)
// K: [n][h][m(640)][32] = [Kh(20) | 0(12)]    V: [n][h][d(20)][m(640)]
__device__ __align__(16) bf16 g_Kg [50 * 20 * 640 * 32];
__device__ __align__(16) bf16 g_VHg[50 * 20 * 20 * 640];

// ---------------- helpers ----------------
__device__ __forceinline__ uint32_t s2u(const void* p) {
    return (uint32_t)__cvta_generic_to_shared(p);
}
__device__ __forceinline__ void ldm4(uint32_t& r0, uint32_t& r1, uint32_t& r2, uint32_t& r3,
                                     uint32_t addr) {
    asm volatile("ldmatrix.sync.aligned.m8n8.x4.shared.b16 {%0,%1,%2,%3}, [%4];"
                 : "=r"(r0), "=r"(r1), "=r"(r2), "=r"(r3) : "r"(addr));
}
__device__ __forceinline__ void ldm2(uint32_t& r0, uint32_t& r1, uint32_t addr) {
    asm volatile("ldmatrix.sync.aligned.m8n8.x2.shared.b16 {%0,%1}, [%2];"
                 : "=r"(r0), "=r"(r1) : "r"(addr));
}
__device__ __forceinline__ void mma16816(float* d, const uint32_t* a, uint32_t b0, uint32_t b1) {
    asm volatile("mma.sync.aligned.m16n8k16.row.col.f32.bf16.bf16.f32 "
                 "{%0,%1,%2,%3}, {%4,%5,%6,%7}, {%8,%9}, {%0,%1,%2,%3};"
                 : "+f"(d[0]), "+f"(d[1]), "+f"(d[2]), "+f"(d[3])
                 : "r"(a[0]), "r"(a[1]), "r"(a[2]), "r"(a[3]), "r"(b0), "r"(b1));
}
__device__ __forceinline__ uint32_t pkbf(float a, float b) {
    __nv_bfloat162 t = __floats2bfloat162_rn(a, b);
    return *reinterpret_cast<uint32_t*>(&t);
}
__device__ __forceinline__ uint32_t pk2h(bf16 a, bf16 b) {
    __nv_bfloat162 t; t.x = a; t.y = b;
    return *reinterpret_cast<uint32_t*>(&t);
}
// cp.async 16B with src-size (0 => zero-fill)
__device__ __forceinline__ void cpa16(uint32_t saddr, const void* gptr, uint32_t bytes) {
    asm volatile("cp.async.cg.shared.global [%0], [%1], 16, %2;"
                 :: "r"(saddr), "l"(gptr), "r"(bytes));
}
#define CPA_COMMIT() asm volatile("cp.async.commit_group;" ::: "memory")
#define CPA_WAIT0()  asm volatile("cp.async.wait_group 0;" ::: "memory")

// ---------------- merged convert: 8 segments in one launch ----------------
struct ConvParams {
    const float* src[8];
    bf16* hi[8];
    bf16* lo[8];
    int cum[9];
};
__global__ void conv_all_kernel(ConvParams P) {
    int i = blockIdx.x * blockDim.x + threadIdx.x;
    if (i >= P.cum[8]) return;
    int g = 0;
    #pragma unroll
    for (int s = 1; s < 8; s++) if (i >= P.cum[s]) g = s;
    int local = i - P.cum[g];
    float v = P.src[g][local];
    bf16 hh = __float2bfloat16_rn(v);
    P.hi[g][local] = hh;
    P.lo[g][local] = __float2bfloat16_rn(v - __bfloat162float(hh));
}

// ---------------- prep2: Hcat gather (bf16 pairs) + Wo transpose-split ----------------
#define HC_PAIRS (BNH * 600)
#define HC_BLOCKS ((HC_PAIRS + 255) / 256)
#define TR_BLOCKS ((400 * 400 + 255) / 256)
__global__ void prep2_kernel(const bf16* __restrict__ hh, const bf16* __restrict__ hl,
                             bf16* __restrict__ oh, bf16* __restrict__ ol,
                             const float* __restrict__ Wo,
                             bf16* __restrict__ th, bf16* __restrict__ tl) {
    if ((int)blockIdx.x < HC_BLOCKS) {
        int idx = blockIdx.x * blockDim.x + threadIdx.x;   // pairs
        if (idx >= HC_PAIRS) return;
        int row = idx / 600, pr = idx % 600;
        int col = pr * 2;
        int b = row / NH_, j = row % NH_;
        int part = col / 400, d = col % 400;
        int jj = (part == 0) ? (j + NH_ - 1) % NH_ : ((part == 1) ? j : (j + 1) % NH_);
        int s = (b * NH_ + jj) * 400 + d;
        reinterpret_cast<uint32_t*>(oh)[idx] = *reinterpret_cast<const uint32_t*>(&hh[s]);
        reinterpret_cast<uint32_t*>(ol)[idx] = *reinterpret_cast<const uint32_t*>(&hl[s]);
    } else {
        int idx = (blockIdx.x - HC_BLOCKS) * blockDim.x + threadIdx.x;
        if (idx >= 400 * 400) return;
        int n = idx / 400, k = idx % 400;
        float v = Wo[k * 400 + n];
        bf16 hv = __float2bfloat16_rn(v);
        th[idx] = hv;
        tl[idx] = __float2bfloat16_rn(v - __bfloat162float(hv));
    }
}

// ---------------- tc: warp-per-row reduction ----------------
__global__ void tc_kernel(const float* __restrict__ b1, const float* __restrict__ bo,
                          const float* __restrict__ b3, const float* __restrict__ W3,
                          float* __restrict__ tc) {
    int w = threadIdx.x >> 5, lane = threadIdx.x & 31;
    int r = blockIdx.x * 8 + w;
    if (r >= 400) return;
    const float* row = W3 + (size_t)r * 800;
    float acc = 0.f;
    for (int d = lane; d < 400; d += 32)
        acc += b1[d] * row[d] + bo[d] * row[400 + d];
    #pragma unroll
    for (int o = 16; o > 0; o >>= 1) acc += __shfl_xor_sync(0xffffffffu, acc, o);
    if (lane == 0) tc[r] = acc + b3[r];
}

// ---------------- shared tensor-core GEMM core (bf16 split, cp.async) ----------------
// nsplit==3: AhBh+AhBl+AlBh ; nsplit==2: (Ah+Al)·Bh ; nsplit==1: Ah·Bh only
// mode 0: none | 1: +aux0[col] | 2: tanh(x+aux0[col]) | 3: biases | 4: tanh(x+aux0 row-bias)
// mode 5: tanh(x+aux0[col]) then fused dot with aux1 -> C = spart
// out bit0: fp32 C ; bit1: bf16 split Ch/Cl ; bit2: bf16 hi-only Ch
#define TBM 128
#define TBN 128
#define TBK 16
#define SSTR 24

__device__ __forceinline__ void gemm_core(
    const bf16* __restrict__ Ah, const bf16* __restrict__ Al, int lda,
    const bf16* __restrict__ Bh, const bf16* __restrict__ Bl, int ldb,
    float* __restrict__ C, bf16* __restrict__ Ch, bf16* __restrict__ Cl,
    int ldc, int M, int N, int K,
    const float* __restrict__ aux0, const float* __restrict__ aux1,
    const float* __restrict__ aux2,
    int row0, int col0, int mode, int out, int nsplit)
{
    __shared__ __align__(16) bf16 sAh[2][TBM * SSTR];
    __shared__ __align__(16) bf16 sAl[2][TBM * SSTR];
    __shared__ __align__(16) bf16 sBh[2][TBM * SSTR];
    __shared__ __align__(16) bf16 sBl[2][TBM * SSTR];

    const int tid = threadIdx.x;
    const int lrow = tid >> 1, lhalf = tid & 1;

    const bool aok = (row0 + lrow) < M;
    const bool bok = (col0 + lrow) < N;
    const uint32_t abytes = aok ? 16u : 0u;
    const uint32_t bbytes = bok ? 16u : 0u;
    const int arow = aok ? (row0 + lrow) : 0;
    const int brow = bok ? (col0 + lrow) : 0;
    const bf16* Aph = Ah + (size_t)arow * lda + lhalf * 8;
    const bf16* Apl = Al + (size_t)arow * lda + lhalf * 8;
    const bf16* Bph = Bh + (size_t)brow * ldb + lhalf * 8;
    const bf16* Bpl = Bl + (size_t)brow * ldb + lhalf * 8;
    const uint32_t sboff = (uint32_t)((lrow * SSTR + lhalf * 8) * 2);

    const int w = tid >> 5, lane = tid & 31;
    const int wm = w >> 2, wn = w & 3;
    const int mrow = ((lane >> 3) & 1) * 8 + (lane & 7);
    const int koff = (lane >> 4) * 8;

    uint32_t aoff[4], boff[2];
    #pragma unroll
    for (int fm = 0; fm < 4; fm++)
        aoff[fm] = (uint32_t)(((wm * 64 + fm * 16 + mrow) * SSTR + koff) * 2);
    #pragma unroll
    for (int f = 0; f < 2; f++)
        boff[f] = (uint32_t)(((wn * 32 + f * 16 + mrow) * SSTR + koff) * 2);

    const uint32_t bAh = s2u(sAh), bAl = s2u(sAl), bBh = s2u(sBh), bBl = s2u(sBl);
    const uint32_t STB = TBM * SSTR * 2;

    float acc[4][4][4];
    #pragma unroll
    for (int i = 0; i < 4; i++)
        #pragma unroll
        for (int j = 0; j < 4; j++)
            #pragma unroll
            for (int e = 0; e < 4; e++) acc[i][j][e] = 0.f;

    // stage-0 async copy
    {
        cpa16(bAh + sboff, Aph, abytes);
        if (nsplit >= 2) cpa16(bAl + sboff, Apl, abytes);
        cpa16(bBh + sboff, Bph, bbytes);
        if (nsplit == 3) cpa16(bBl + sboff, Bpl, bbytes);
        CPA_COMMIT();
    }
    CPA_WAIT0();
    __syncthreads();

    const int nk = K / TBK;
    for (int t = 0; t < nk; t++) {
        const int st = t & 1;
        if (t + 1 < nk) {
            const int k = (t + 1) * TBK;
            const uint32_t nso = (uint32_t)(st ^ 1) * STB + sboff;
            cpa16(bAh + nso, Aph + k, abytes);
            if (nsplit >= 2) cpa16(bAl + nso, Apl + k, abytes);
            cpa16(bBh + nso, Bph + k, bbytes);
            if (nsplit == 3) cpa16(bBl + nso, Bpl + k, bbytes);
            CPA_COMMIT();
        }

        uint32_t ah[4][4], al[4][4], bh[2][4], bl[2][4];
        #pragma unroll
        for (int fm = 0; fm < 4; fm++) {
            ldm4(ah[fm][0], ah[fm][1], ah[fm][2], ah[fm][3], bAh + st * STB + aoff[fm]);
            if (nsplit >= 2)
                ldm4(al[fm][0], al[fm][1], al[fm][2], al[fm][3], bAl + st * STB + aoff[fm]);
        }
        #pragma unroll
        for (int f = 0; f < 2; f++) {
            ldm4(bh[f][0], bh[f][1], bh[f][2], bh[f][3], bBh + st * STB + boff[f]);
            if (nsplit == 3)
                ldm4(bl[f][0], bl[f][1], bl[f][2], bl[f][3], bBl + st * STB + boff[f]);
        }

        #pragma unroll
        for (int fm = 0; fm < 4; fm++) {
            #pragma unroll
            for (int f = 0; f < 2; f++) {
                mma16816(acc[fm][f * 2 + 0], ah[fm], bh[f][0], bh[f][2]);
                if (nsplit >= 2)
                    mma16816(acc[fm][f * 2 + 0], al[fm], bh[f][0], bh[f][2]);
                if (nsplit == 3)
                    mma16816(acc[fm][f * 2 + 0], ah[fm], bl[f][0], bl[f][2]);
                mma16816(acc[fm][f * 2 + 1], ah[fm], bh[f][1], bh[f][3]);
                if (nsplit >= 2)
                    mma16816(acc[fm][f * 2 + 1], al[fm], bh[f][1], bh[f][3]);
                if (nsplit == 3)
                    mma16816(acc[fm][f * 2 + 1], ah[fm], bl[f][1], bl[f][3]);
            }
        }

        if (t + 1 < nk) {
            CPA_WAIT0();
            __syncthreads();
        }
    }

    float sacc[4][2];
    #pragma unroll
    for (int i = 0; i < 4; i++) { sacc[i][0] = 0.f; sacc[i][1] = 0.f; }

    // epilogue (pairwise: cols cc, cc+1)
    #pragma unroll
    for (int fm = 0; fm < 4; fm++) {
        #pragma unroll
        for (int half = 0; half < 2; half++) {
            const int r = row0 + wm * 64 + fm * 16 + (lane >> 2) + half * 8;
            if (r >= M) continue;
            int bb = 0, ii = 0, jj = 0;
            if (mode == 3 || mode == 4) { bb = r / 500; ii = (r / 50) % 10; jj = r % 50; }
            #pragma unroll
            for (int fn = 0; fn < 4; fn++) {
                const int cc = col0 + wn * 32 + fn * 8 + (lane & 3) * 2;
                if (cc >= N) continue;
                float v0 = acc[fm][fn][half * 2], v1 = acc[fm][fn][half * 2 + 1];
                if (mode == 1) { v0 += aux0[cc]; v1 += aux0[cc + 1]; }
                if (mode == 2 || mode == 5) {
                    v0 = tanhf(v0 + aux0[cc]); v1 = tanhf(v1 + aux0[cc + 1]);
                }
                if (mode == 3) {
                    const float* p0 = aux0 + (size_t)(bb * 50 + jj) * N;
                    const float* p1 = aux1 + (size_t)(bb * 10 + ii) * N;
                    v0 += p0[cc] + p1[cc] + aux2[cc];
                    v1 += p0[cc + 1] + p1[cc + 1] + aux2[cc + 1];
                }
                if (mode == 4) {
                    const float* p0 = aux0 + (size_t)(bb * 10 + ii) * N;
                    v0 = tanhf(v0 + p0[cc]); v1 = tanhf(v1 + p0[cc + 1]);
                }
                if (mode == 5)
                    sacc[fm][half] += v0 * aux1[cc] + v1 * aux1[cc + 1];
                if (out & 1)
                    *reinterpret_cast<float2*>(&C[(size_t)r * ldc + cc]) = make_float2(v0, v1);
                if (out & 2) {
                    bf16 h0 = __float2bfloat16_rn(v0), h1 = __float2bfloat16_rn(v1);
                    *reinterpret_cast<uint32_t*>(&Ch[(size_t)r * ldc + cc]) = pk2h(h0, h1);
                    *reinterpret_cast<uint32_t*>(&Cl[(size_t)r * ldc + cc]) =
                        pkbf(v0 - __bfloat162float(h0), v1 - __bfloat162float(h1));
                }
                if (out & 4)
                    *reinterpret_cast<uint32_t*>(&Ch[(size_t)r * ldc + cc]) = pkbf(v0, v1);
            }
        }
    }

    // mode 5: deterministic cross-warp score reduction -> C[part*M + r]
    if (mode == 5) {
        __syncthreads();
        float* red = reinterpret_cast<float*>(sAh);
        #pragma unroll
        for (int fm = 0; fm < 4; fm++) {
            #pragma unroll
            for (int half = 0; half < 2; half++) {
                float v = sacc[fm][half];
                v += __shfl_xor_sync(0xffffffffu, v, 1);
                v += __shfl_xor_sync(0xffffffffu, v, 2);
                if ((lane & 3) == 0)
                    red[(wm * 64 + fm * 16 + (lane >> 2) + half * 8) * 4 + wn] = v;
            }
        }
        __syncthreads();
        if (tid < 128) {
            int r = row0 + tid;
            if (r < M)
                C[(size_t)(col0 >> 7) * M + r] =
                    red[tid * 4] + red[tid * 4 + 1] + red[tid * 4 + 2] + red[tid * 4 + 3];
        }
    }
}

// template wrapper (big GEMMs)
template <int MODE, int OUT, int NSPLIT>
__global__ __launch_bounds__(256, 2) void gemm_mma(
    const bf16* __restrict__ Ah, const bf16* __restrict__ Al, int lda,
    const bf16* __restrict__ Bh, const bf16* __restrict__ Bl, int ldb,
    float* __restrict__ C, bf16* __restrict__ Ch, bf16* __restrict__ Cl,
    int ldc, int M, int N, int K,
    const float* __restrict__ aux0, const float* __restrict__ aux1,
    const float* __restrict__ aux2)
{
    gemm_core(Ah, Al, lda, Bh, Bl, ldb, C, Ch, Cl, ldc, M, N, K,
              aux0, aux1, aux2, blockIdx.y * TBM, blockIdx.x * TBN, MODE, OUT, NSPLIT);
}

// grouped wrapper (small GEMMs, modes 0/1, nsplit=3: exact split)
struct GDesc {
    const bf16 *Ah, *Al, *Bh, *Bl;
    float* C; bf16 *Ch; bf16 *Cl;
    const float* aux0;
    int lda, ldb, ldc, M, N, K, mode, out, bx;
};
struct GParams { GDesc d[6]; int cum[7]; int nd; };

__global__ __launch_bounds__(256, 2) void gemm_group(GParams P) {
    int g = 0;
    while (g + 1 < P.nd && (int)blockIdx.x >= P.cum[g + 1]) g++;
    const GDesc& D = P.d[g];
    int local = blockIdx.x - P.cum[g];
    int bxi = local % D.bx, byi = local / D.bx;
    gemm_core(D.Ah, D.Al, D.lda, D.Bh, D.Bl, D.ldb, D.C, D.Ch, D.Cl, D.ldc,
              D.M, D.N, D.K, D.aux0, nullptr, nullptr,
              byi * TBM, bxi * TBN, D.mode, D.out, 3);
}

// ---------------- attention K/V prep (pure bf16) ----------------
__global__ void attn_prep(const float* __restrict__ Cq3, const float* __restrict__ Hq3,
                          bf16* __restrict__ Kg, bf16* __restrict__ VHg)
{
    const int n = blockIdx.x, b = blockIdx.y;
    const float* Hrow = Hq3 + (size_t)(b * NH_ + n) * 1200;
    const bf16 zb = __float2bfloat16_rn(0.f);

    for (int idx = threadIdx.x; idx < 20 * 10 * 32; idx += 256) {
        int h = idx / 320, rem = idx % 320, mm = rem >> 5, d = rem & 31;
        int m = b * 10 + mm;
        bf16 outv = zb;
        if (d < 20)
            outv = __float2bfloat16_rn(Cq3[m * 1200 + 400 + h * 20 + d]
                                       + Hrow[400 + h * 20 + d]);
        Kg[((size_t)(n * 20 + h) * 640 + m) * 32 + d] = outv;
    }
    for (int idx = threadIdx.x; idx < 4000; idx += 256) {
        int h = idx / 200, d = (idx / 10) % 20, mm = idx % 10;
        int m = b * 10 + mm;
        VHg[((size_t)(n * 20 + h) * 20 + d) * 640 + m] =
            __float2bfloat16_rn(Cq3[m * 1200 + 800 + h * 20 + d] + Hrow[800 + h * 20 + d]);
    }
}

// ---------------- tensor-core flash attention (pure bf16, hi-only Xo out) ----------------
__global__ __launch_bounds__(256, 2) void attn_mma(
    const float* __restrict__ Cq3, const float* __restrict__ Hq3,
    const bf16* __restrict__ Kg, const bf16* __restrict__ VHg,
    bf16* __restrict__ Xoh)
{
    __shared__ __align__(16) bf16 sm[11264];   // 22.5KB

    const int qt = blockIdx.x, n = blockIdx.y, h = blockIdx.z;
    const int tid = threadIdx.x, w = tid >> 5, lane = tid & 31;
    const float scale = 0.22360679774997896f;  // 1/sqrt(20)
    const bf16 zb = __float2bfloat16_rn(0.f);

    const bf16* Kb  = Kg  + (size_t)(n * 20 + h) * 640 * 32;
    const bf16* Vbh = VHg + (size_t)(n * 20 + h) * 20 * 640;

    const uint32_t smb = s2u(sm);

    for (int idx = tid; idx < 128 * 32; idx += 256) {
        int r = idx >> 5, d = idx & 31;
        bf16 outv = zb;
        if (d < 20) {
            int l = qt * 128 + r;
            int qr = (l / NC_) * NH_ + n;
            outv = __float2bfloat16_rn(
                (Cq3[l * 1200 + h * 20 + d] + Hq3[qr * 1200 + h * 20 + d]) * scale);
        }
        int e = ((d >> 3) ^ (r & 7)) * 8 + (d & 7);
        sm[r * 64 + e] = outv;
    }
    __syncthreads();

    const int mrow = ((lane >> 3) & 1) * 8 + (lane & 7);
    const uint32_t lk16 = (uint32_t)((lane >> 4) << 4);

    uint32_t qf[2][4];
    #pragma unroll
    for (int kc = 0; kc < 2; kc++) {
        int row = w * 16 + mrow;
        uint32_t cb = (uint32_t)(kc * 32) + lk16;
        ldm4(qf[kc][0], qf[kc][1], qf[kc][2], qf[kc][3],
             smb + row * 128 + (cb ^ (uint32_t)((row & 7) << 4)));
    }
    // zero V pad rows 20-23 of both buffers
    for (int idx = tid; idx < 512; idx += 256) {
        int b2 = idx >> 8, e = idx & 255;
        sm[9472 + b2 * 1536 + e] = zb;
    }
    __syncthreads();

    auto copy_tile = [&](int kt2, int bufi) {
        const uint32_t kdst = smb + bufi * 8192;
        {
            int kk = tid >> 2, seg = tid & 3;
            cpa16(kdst + kk * 128 + (uint32_t)((seg * 16) ^ ((kk & 7) << 4)),
                  Kb + (size_t)(kt2 * 64 + kk) * 32 + seg * 8, 16);
        }
        if (tid < 160) {
            int d = tid >> 3, seg = tid & 7;
            uint32_t so = (uint32_t)((seg * 16) ^ ((d & 7) << 4));
            cpa16(smb + 16384 + bufi * 3072 + d * 128 + so,
                  Vbh + (size_t)d * 640 + kt2 * 64 + seg * 8, 16);
        }
    };

    copy_tile(0, 0);
    CPA_COMMIT();

    float O0[3][4];
    #pragma unroll
    for (int f = 0; f < 3; f++)
        #pragma unroll
        for (int e = 0; e < 4; e++) O0[f][e] = 0.f;
    float zl = 0.f, zh2 = 0.f;

    for (int kt = 0; kt < 10; kt++) {
        const int bufi = kt & 1;
        CPA_WAIT0();
        __syncthreads();
        if (kt + 1 < 10) { copy_tile(kt + 1, bufi ^ 1); CPA_COMMIT(); }

        const uint32_t kbase = smb + bufi * 8192;
        union { float f[8][4]; uint32_t u[8][4]; } SP;
        #pragma unroll
        for (int f = 0; f < 8; f++)
            #pragma unroll
            for (int e = 0; e < 4; e++) SP.f[f][e] = 0.f;

        #pragma unroll
        for (int g = 0; g < 4; g++) {
            uint32_t kf[2][4];
            int row = g * 16 + mrow;
            #pragma unroll
            for (int kc = 0; kc < 2; kc++) {
                uint32_t cb = (uint32_t)(kc * 32) + lk16;
                ldm4(kf[kc][0], kf[kc][1], kf[kc][2], kf[kc][3],
                     kbase + row * 128 + (cb ^ (uint32_t)((row & 7) << 4)));
            }
            #pragma unroll
            for (int kc = 0; kc < 2; kc++) {
                mma16816(SP.f[2 * g + 0], qf[kc], kf[kc][0], kf[kc][2]);
                mma16816(SP.f[2 * g + 1], qf[kc], kf[kc][1], kf[kc][3]);
            }
        }

        #pragma unroll
        for (int f = 0; f < 8; f++) {
            float e0 = __expf(SP.f[f][0]), e1 = __expf(SP.f[f][1]);
            float e2 = __expf(SP.f[f][2]), e3 = __expf(SP.f[f][3]);
            zl += e0 + e1; zh2 += e2 + e3;
            SP.u[f][0] = pkbf(e0, e1);
            SP.u[f][1] = pkbf(e2, e3);
        }

        const uint32_t vhbase = smb + 16384 + bufi * 3072;
        #pragma unroll
        for (int kc2 = 0; kc2 < 4; kc2++) {
            uint32_t ah[4] = { SP.u[2 * kc2][0], SP.u[2 * kc2][1],
                               SP.u[2 * kc2 + 1][0], SP.u[2 * kc2 + 1][1] };
            uint32_t vh4[4], vh2[2];
            uint32_t cb4 = (uint32_t)(kc2 * 32) + lk16;
            uint32_t a4 = mrow * 128 + (cb4 ^ (uint32_t)((mrow & 7) << 4));
            int d2 = 16 + (lane & 7);
            uint32_t cb2 = (uint32_t)(kc2 * 32) + (uint32_t)(((lane >> 3) & 1) << 4);
            uint32_t a2 = d2 * 128 + (cb2 ^ (uint32_t)((d2 & 7) << 4));
            ldm4(vh4[0], vh4[1], vh4[2], vh4[3], vhbase + a4);
            ldm2(vh2[0], vh2[1], vhbase + a2);
            mma16816(O0[0], ah, vh4[0], vh4[2]);
            mma16816(O0[1], ah, vh4[1], vh4[3]);
            mma16816(O0[2], ah, vh2[0], vh2[1]);
        }
    }

    zl  += __shfl_xor_sync(0xffffffffu, zl, 1);
    zl  += __shfl_xor_sync(0xffffffffu, zl, 2);
    zh2 += __shfl_xor_sync(0xffffffffu, zh2, 1);
    zh2 += __shfl_xor_sync(0xffffffffu, zh2, 2);
    float izl = 1.f / zl, izh = 1.f / zh2;

    const int rowq = lane >> 2;
    #pragma unroll
    for (int f = 0; f < 3; f++) {
        int d0 = f * 8 + (lane & 3) * 2;
        if (d0 >= 20) continue;
        #pragma unroll
        for (int half = 0; half < 2; half++) {
            int lq = qt * 128 + w * 16 + rowq + half * 8;
            float v0 = O0[f][half * 2]     * (half ? izh : izl);
            float v1 = O0[f][half * 2 + 1] * (half ? izh : izl);
            size_t o = (size_t)(lq * NH_ + n) * 400 + h * 20 + d0;
            *reinterpret_cast<uint32_t*>(&Xoh[o]) = pkbf(v0, v1);
        }
    }
}

// ---------------- softmax over j + weighted sum ----------------
__global__ void softmax_u_kernel(const float* __restrict__ spart,
                                 const bf16* __restrict__ hallh,
                                 const bf16* __restrict__ halll,
                                 float* __restrict__ u)
{
    __shared__ float a[NH_];
    int bi = blockIdx.x;
    if (threadIdx.x == 0) {
        float sv[NH_];
        float mx = -1e30f;
        for (int j = 0; j < NH_; j++) {
            int r = bi * NH_ + j;
            sv[j] = spart[r] + spart[MM + r];
            mx = fmaxf(mx, sv[j]);
        }
        float Z = 0.f;
        for (int j = 0; j < NH_; j++) { float e = __expf(sv[j] - mx); a[j] = e; Z += e; }
        float iz = 1.f / Z;
        for (int j = 0; j < NH_; j++) a[j] *= iz;
    }
    __syncthreads();
    for (int d = threadIdx.x; d < 400; d += blockDim.x) {
        float acc = 0.f;
        for (int j = 0; j < NH_; j++) {
            size_t o = ((size_t)bi * NH_ + j) * 400 + d;
            acc += a[j] * (__bfloat162float(hallh[o]) + __bfloat162float(halll[o]));
        }
        u[(size_t)bi * 400 + d] = acc;
    }
}

// ---------------- launch ----------------
static inline dim3 mgrid(int M, int N) { return dim3((N + TBN - 1) / TBN, (M + TBM - 1) / TBM); }

extern "C" void kernel_launch(void* const* d_in, const int* in_sizes, int n_in,
                              void* d_out, int out_size)
{
    const float* h    = (const float*)d_in[0];
    const float* c    = (const float*)d_in[2];
    const float* W1   = (const float*)d_in[4];
    const float* b1   = (const float*)d_in[5];
    const float* W2   = (const float*)d_in[6];
    const float* b2   = (const float*)d_in[7];
    const float* W3   = (const float*)d_in[8];
    const float* b3   = (const float*)d_in[9];
    const float* Wa1  = (const float*)d_in[10];
    const float* ba1  = (const float*)d_in[11];
    const float* Wa2  = (const float*)d_in[12];
    const float* ba2  = (const float*)d_in[13];
    const float* Wa3  = (const float*)d_in[14];
    const float* Wqkv = (const float*)d_in[16];
    const float* bqkv = (const float*)d_in[17];
    const float* Wo   = (const float*)d_in[18];
    const float* bo   = (const float*)d_in[19];
    float* u = (float*)d_out;

    float *Hq3, *Cq3, *T1, *T2, *tc, *CA, *spart;
    cudaGetSymbolAddress((void**)&Hq3,  g_Hq3);
    cudaGetSymbolAddress((void**)&Cq3,  g_Cq3);
    cudaGetSymbolAddress((void**)&T1,   g_T1);
    cudaGetSymbolAddress((void**)&T2,   g_T2);
    cudaGetSymbolAddress((void**)&tc,   g_tc);
    cudaGetSymbolAddress((void**)&CA,   g_CA);
    cudaGetSymbolAddress((void**)&spart, g_spart);

    bf16 *bHcat_h, *bHcat_l, *bh_h, *bh_l, *bHs_h, *bHs_l, *bHp1_h, *bHp1_l;
    bf16 *bc_h, *bc_l, *bCc_h, *bCc_l, *bCs_h, *bCs_l;
    bf16 *bXo_h, *bhall_h, *bhall_l, *ba1_h;
    bf16 *bW1_h, *bW1_l, *bW2_h, *bW2_l, *bWqkv_h, *bWqkv_l, *bW3_h, *bW3_l;
    bf16 *bWa1_h, *bWa1_l, *bWa2_h, *bWa2_l, *bWoT_h, *bWoT_l, *bWm_h, *bWm_l;
    bf16 *Kg, *VHg;
    cudaGetSymbolAddress((void**)&bHcat_h, g_bHcat_h);  cudaGetSymbolAddress((void**)&bHcat_l, g_bHcat_l);
    cudaGetSymbolAddress((void**)&bh_h,    g_bh_h);     cudaGetSymbolAddress((void**)&bh_l,    g_bh_l);
    cudaGetSymbolAddress((void**)&bHs_h,   g_bHs_h);    cudaGetSymbolAddress((void**)&bHs_l,   g_bHs_l);
    cudaGetSymbolAddress((void**)&bHp1_h,  g_bHp1_h);   cudaGetSymbolAddress((void**)&bHp1_l,  g_bHp1_l);
    cudaGetSymbolAddress((void**)&bc_h,    g_bc_h);     cudaGetSymbolAddress((void**)&bc_l,    g_bc_l);
    cudaGetSymbolAddress((void**)&bCc_h,   g_bCc_h);    cudaGetSymbolAddress((void**)&bCc_l,   g_bCc_l);
    cudaGetSymbolAddress((void**)&bCs_h,   g_bCs_h);    cudaGetSymbolAddress((void**)&bCs_l,   g_bCs_l);
    cudaGetSymbolAddress((void**)&bXo_h,   g_bXo_h);
    cudaGetSymbolAddress((void**)&bhall_h, g_bhall_h);  cudaGetSymbolAddress((void**)&bhall_l, g_bhall_l);
    cudaGetSymbolAddress((void**)&ba1_h,   g_ba1_h);
    cudaGetSymbolAddress((void**)&bW1_h,   g_bW1_h);    cudaGetSymbolAddress((void**)&bW1_l,   g_bW1_l);
    cudaGetSymbolAddress((void**)&bW2_h,   g_bW2_h);    cudaGetSymbolAddress((void**)&bW2_l,   g_bW2_l);
    cudaGetSymbolAddress((void**)&bWqkv_h, g_bWqkv_h);  cudaGetSymbolAddress((void**)&bWqkv_l, g_bWqkv_l);
    cudaGetSymbolAddress((void**)&bW3_h,   g_bW3_h);    cudaGetSymbolAddress((void**)&bW3_l,   g_bW3_l);
    cudaGetSymbolAddress((void**)&bWa1_h,  g_bWa1_h);   cudaGetSymbolAddress((void**)&bWa1_l,  g_bWa1_l);
    cudaGetSymbolAddress((void**)&bWa2_h,  g_bWa2_h);   cudaGetSymbolAddress((void**)&bWa2_l,  g_bWa2_l);
    cudaGetSymbolAddress((void**)&bWoT_h,  g_bWoT_h);   cudaGetSymbolAddress((void**)&bWoT_l,  g_bWoT_l);
    cudaGetSymbolAddress((void**)&bWm_h,   g_bWm_h);    cudaGetSymbolAddress((void**)&bWm_l,   g_bWm_l);
    cudaGetSymbolAddress((void**)&Kg,  g_Kg);
    cudaGetSymbolAddress((void**)&VHg, g_VHg);

    // (1) merged conversions
    ConvParams CP;
    const float* srcs[8] = { h, c, W1, W2, Wqkv, W3, Wa1, Wa2 };
    bf16* his[8] = { bh_h, bc_h, bW1_h, bW2_h, bWqkv_h, bW3_h, bWa1_h, bWa2_h };
    bf16* los[8] = { bh_l, bc_l, bW1_l, bW2_l, bWqkv_l, bW3_l, bWa1_l, bWa2_l };
    int ns[8] = { BNH * 400, LL * 400, 400 * 1600, 400 * 800, 1200 * 400,
                  400 * 800, 400 * 800, 200 * 400 };
    int cum = 0;
    for (int i = 0; i < 8; i++) { CP.src[i] = srcs[i]; CP.hi[i] = his[i]; CP.lo[i] = los[i];
                                  CP.cum[i] = cum; cum += ns[i]; }
    CP.cum[8] = cum;
    conv_all_kernel<<<(cum + 255) / 256, 256>>>(CP);

    // (2) Hcat gather + Wo transpose-split
    prep2_kernel<<<HC_BLOCKS + TR_BLOCKS, 256>>>(bh_h, bh_l, bHcat_h, bHcat_l,
                                                 Wo, bWoT_h, bWoT_l);

    // (3) grouped GEMM launch 1 (exact nsplit=3)
    {
        GParams G; int cumb = 0; int gi = 0;
        auto add = [&](const bf16* Ah, const bf16* Al, int lda,
                       const bf16* Bh, const bf16* Bl, int ldb,
                       float* C, bf16* Ch, bf16* Cl, int ldc,
                       int M, int N, int K, int mode, int out, const float* aux0) {
            GDesc& D = G.d[gi];
            D.Ah = Ah; D.Al = Al; D.Bh = Bh; D.Bl = Bl;
            D.C = C; D.Ch = Ch; D.Cl = Cl; D.aux0 = aux0;
            D.lda = lda; D.ldb = ldb; D.ldc = ldc; D.M = M; D.N = N; D.K = K;
            D.mode = mode; D.out = out;
            D.bx = (N + TBN - 1) / TBN;
            int by = (M + TBM - 1) / TBM;
            G.cum[gi] = cumb; cumb += D.bx * by; gi++;
        };
        add(bHcat_h, bHcat_l, 1200, bW1_h, bW1_l, 1600, nullptr, bHp1_h, bHp1_l, 400,
            BNH, 400, 1200, 0, 2, nullptr);                                   // Hp1
        add(bh_h, bh_l, 400, bW2_h + 400, bW2_l + 400, 800, nullptr, bHs_h, bHs_l, 400,
            BNH, 400, 400, 0, 2, nullptr);                                    // Hs
        add(bc_h, bc_l, 400, bW1_h + 1200, bW1_l + 1200, 1600, nullptr, bCc_h, bCc_l, 400,
            LL, 400, 400, 0, 2, nullptr);                                     // Cc
        add(bc_h, bc_l, 400, bW2_h, bW2_l, 800, nullptr, bCs_h, bCs_l, 400,
            LL, 400, 400, 1, 2, b2);                                          // Cs
        add(bc_h, bc_l, 400, bWa1_h + 400, bWa1_l + 400, 800, CA, nullptr, nullptr, 400,
            LL, 400, 400, 1, 1, ba1);                                         // CA
        add(bW3_h + 400, bW3_l + 400, 800, bWoT_h, bWoT_l, 400, nullptr, bWm_h, bWm_l, 400,
            400, 400, 400, 0, 2, nullptr);                                    // Wm
        G.cum[gi] = cumb; G.nd = gi;
        gemm_group<<<cumb, 256>>>(G);
    }

    // (4) grouped GEMM launch 2 (exact nsplit=3)
    {
        GParams G; int cumb = 0; int gi = 0;
        auto add = [&](const bf16* Ah, const bf16* Al, int lda,
                       const bf16* Bh, const bf16* Bl, int ldb,
                       float* C, int ldc, int M, int N, int K, int mode, const float* aux0) {
            GDesc& D = G.d[gi];
            D.Ah = Ah; D.Al = Al; D.Bh = Bh; D.Bl = Bl;
            D.C = C; D.Ch = nullptr; D.Cl = nullptr; D.aux0 = aux0;
            D.lda = lda; D.ldb = ldb; D.ldc = ldc; D.M = M; D.N = N; D.K = K;
            D.mode = mode; D.out = 1;
            D.bx = (N + TBN - 1) / TBN;
            int by = (M + TBM - 1) / TBM;
            G.cum[gi] = cumb; cumb += D.bx * by; gi++;
        };
        add(bHp1_h, bHp1_l, 400, bW3_h, bW3_l, 800, T1, 400, BNH, 400, 400, 0, nullptr);      // T1
        add(bHs_h, bHs_l, 400, bWqkv_h, bWqkv_l, 400, Hq3, 1200, BNH, 1200, 400, 0, nullptr); // Hq3
        add(bCs_h, bCs_l, 400, bWqkv_h, bWqkv_l, 400, Cq3, 1200, LL, 1200, 400, 1, bqkv);     // Cq3
        add(bCc_h, bCc_l, 400, bW3_h, bW3_l, 800, T2, 400, LL, 400, 400, 0, nullptr);         // T2
        G.cum[gi] = cumb; G.nd = gi;
        gemm_group<<<cumb, 256>>>(G);
    }

    // (5) attention K/V prep (pure bf16)
    attn_prep<<<dim3(NH_, BB), 256>>>(Cq3, Hq3, Kg, VHg);

    // (6) tensor-core flash attention (pure bf16; hi-only Xo out)
    attn_mma<<<dim3(5, NH_, NHEAD), 256>>>(Cq3, Hq3, Kg, VHg, bXo_h);

    // (7) tc
    tc_kernel<<<50, 256>>>(b1, bo, b3, W3, tc);

    // (8-10) big GEMMs
    // hall = Xo_h @ Wm_h^T + T1 + T2 + tc  (split out; nsplit=1)
    gemm_mma<3, 2, 1><<<mgrid(MM, 400), 256>>>(bXo_h, bXo_h, 400, bWm_h, bWm_l, 400,
        nullptr, bhall_h, bhall_l, 400, MM, 400, 400, T1, T2, tc);
    // a1 = tanh(bf16(hall) @ Wa1a^T + CA)  (hi-only out; nsplit=1)
    gemm_mma<4, 4, 1><<<mgrid(MM, 400), 256>>>(bhall_h, bhall_h, 400, bWa1_h, bWa1_l, 800,
        nullptr, ba1_h, nullptr, 400, MM, 400, 400, CA, nullptr, nullptr);
    // a2 + score fused: tanh(a1 @ Wa2^T + ba2) · Wa3 -> spart  (nsplit=1)
    gemm_mma<5, 0, 1><<<mgrid(MM, 200), 256>>>(ba1_h, ba1_h, 400, bWa2_h, bWa2_l, 400,
        spart, nullptr, nullptr, 200, MM, 200, 400, ba2, Wa3, nullptr);

    // (11) softmax + weighted sum
    softmax_u_kernel<<<LL, 128>>>(spart, bhall_h, bhall_l, u);
}